// round 7
// baseline (speedup 1.0000x reference)
#include <cuda_runtime.h>

#define BB 128
#define NN 100
#define EE 3200
#define K1T 512
#define K3T 768

struct Args {
    const float* nodes;
    const int*   ei;
    const float* ea;
    const int*   agent;
    const float* emb;
    const float *W1,*b1,*W2,*b2,*W3,*b3,*lng,*lnb;
    const float *g1Wq,*g1bq,*g1Wk,*g1bk,*g1Wv,*g1bv,*g1We,*g1Ws,*g1bs;
    const float *g2Wq,*g2bq,*g2Wk,*g2bk,*g2Wv,*g2bv,*g2We,*g2Ws,*g2bs;
    float* out;
};

// stream-ordered global intermediates
__device__ int   g_csr[BB * EE];           // (src<<16)|e, grouped by dst
__device__ int   g_rowptr[BB * (NN + 1)];
__device__ float g_hbuf[(size_t)BB * EE * 16];
__device__ float g_q[BB * NN * 64], g_k[BB * NN * 64], g_v[BB * NN * 64];
__device__ float g_root[BB * NN * 16];
__device__ float g_expl[BB * EE * 4];
__device__ float g_a[BB * NN * 16];

// e^x via FMA-pipe polynomial (avoids MUFU throughput floor)
__device__ __forceinline__ float fexp(float x) {
    float t = x * 1.4426950408889634f;
    float n = rintf(t);
    float f = t - n;
    float p = 1.3333558e-3f;
    p = p * f + 9.6181291e-3f;
    p = p * f + 5.5504109e-2f;
    p = p * f + 2.4022651e-1f;
    p = p * f + 6.9314718e-1f;
    p = p * f + 1.0f;
    int ni = (int)n;
    ni = max(-126, min(127, ni));
    return p * __int_as_float((ni + 127) << 23);
}

__device__ __forceinline__ void ln16(float* h, const float* g, const float* bb) {
    float m = 0.f;
#pragma unroll
    for (int i = 0; i < 16; i++) m += h[i];
    m *= (1.f / 16.f);
    float var = 0.f;
#pragma unroll
    for (int i = 0; i < 16; i++) { float d = h[i] - m; var += d * d; }
    var *= (1.f / 16.f);
    float inv = rsqrtf(var + 1e-5f);
#pragma unroll
    for (int i = 0; i < 16; i++) h[i] = (h[i] - m) * inv * g[i] + bb[i];
}

// ================= K0: per-batch CSR build =================
__global__ void __launch_bounds__(256) csr_kernel(Args A) {
    __shared__ int deg[NN], rp[NN + 1], cur[NN];
    const int b = blockIdx.x, tid = threadIdx.x;
    const int* ei = A.ei + b * 2 * EE;
    for (int i = tid; i < NN; i += 256) deg[i] = 0;
    __syncthreads();
    for (int e = tid; e < EE; e += 256) atomicAdd(&deg[ei[EE + e]], 1);
    __syncthreads();
    if (tid < 32) {
        int d0[4]; int t = 0;
#pragma unroll
        for (int u = 0; u < 4; u++) {
            const int n = tid * 4 + u;
            d0[u] = (n < NN) ? deg[n] : 0;
            t += d0[u];
        }
        int incl = t;
#pragma unroll
        for (int o = 1; o < 32; o <<= 1) {
            const int vv = __shfl_up_sync(0xFFFFFFFFu, incl, o);
            if (tid >= o) incl += vv;
        }
        int run = incl - t;
#pragma unroll
        for (int u = 0; u < 4; u++) {
            const int n = tid * 4 + u;
            if (n < NN) { rp[n] = run; run += d0[u]; }
        }
        if (tid == 31) rp[NN] = incl;
    }
    __syncthreads();
    for (int n = tid; n < NN; n += 256) cur[n] = rp[n];
    for (int n = tid; n <= NN; n += 256) g_rowptr[b * (NN + 1) + n] = rp[n];
    __syncthreads();
    for (int e = tid; e < EE; e += 256) {
        const int src = ei[e], dst = ei[EE + e];
        const int pos = atomicAdd(&cur[dst], 1);
        g_csr[b * EE + pos] = (src << 16) | e;
    }
}

// ================= K1: flat per-edge MLP =================
__global__ void __launch_bounds__(K1T, 2) mlp_kernel(Args A) {
    __shared__ float4 W1v[48];
    __shared__ float4 W2v[64];
    __shared__ float4 W3v[64];
    __shared__ float  b1s[16], b2s[16], b3s[16], lngs[16], lnbs[16];
    __shared__ float4 embv[5];

    const int tid = threadIdx.x;
    if (tid < 192) ((float*)W1v)[tid] = A.W1[tid];
    if (tid >= 192 && tid < 448) ((float*)W2v)[tid - 192] = A.W2[tid - 192];
    if (tid < 256) ((float*)W3v)[tid] = A.W3[tid];
    if (tid < 16) {
        b1s[tid] = A.b1[tid]; b2s[tid] = A.b2[tid]; b3s[tid] = A.b3[tid];
        lngs[tid] = A.lng[tid]; lnbs[tid] = A.lnb[tid];
    }
    if (tid < 20) ((float*)embv)[tid] = A.emb[tid];
    __syncthreads();

    const int b = blockIdx.y;
    const int e = blockIdx.x * K1T + tid;
    if (e >= EE) return;

    const int src = A.ei[b * 2 * EE + e];
    const int t = (int)A.nodes[b * NN + src];
    const float* eag = A.ea + (size_t)b * EE * 8;

    const float4 xA = embv[t];
    const float4 xB = *(const float4*)(eag + (size_t)e * 8);
    const float4 xC = *(const float4*)(eag + (size_t)e * 8 + 4);

    float h[16], h2[16];
#pragma unroll
    for (int o = 0; o < 16; o++) {
        const float4 w0 = W1v[o * 3], w1 = W1v[o * 3 + 1], w2 = W1v[o * 3 + 2];
        float acc = b1s[o]
            + w0.x * xA.x + w0.y * xA.y + w0.z * xA.z + w0.w * xA.w
            + w1.x * xB.x + w1.y * xB.y + w1.z * xB.z + w1.w * xB.w
            + w2.x * xC.x + w2.y * xC.y + w2.z * xC.z + w2.w * xC.w;
        h[o] = fmaxf(acc, 0.f);
    }
    ln16(h, lngs, lnbs);
#pragma unroll
    for (int o = 0; o < 16; o++) {
        float acc = b2s[o];
#pragma unroll
        for (int jq = 0; jq < 4; jq++) {
            const float4 w = W2v[o * 4 + jq];
            acc += w.x * h[jq * 4] + w.y * h[jq * 4 + 1] + w.z * h[jq * 4 + 2] + w.w * h[jq * 4 + 3];
        }
        h2[o] = fmaxf(acc, 0.f);
    }
    ln16(h2, lngs, lnbs);
#pragma unroll
    for (int o = 0; o < 16; o++) {
        float acc = b3s[o];
#pragma unroll
        for (int jq = 0; jq < 4; jq++) {
            const float4 w = W3v[o * 4 + jq];
            acc += w.x * h2[jq * 4] + w.y * h2[jq * 4 + 1] + w.z * h2[jq * 4 + 2] + w.w * h2[jq * 4 + 3];
        }
        h[o] = fmaxf(acc, 0.f);
    }
    ln16(h, lngs, lnbs);

    float4* hp = (float4*)&g_hbuf[((size_t)b * EE + e) * 16];
    hp[0] = make_float4(h[0], h[1], h[2], h[3]);
    hp[1] = make_float4(h[4], h[5], h[6], h[7]);
    hp[2] = make_float4(h[8], h[9], h[10], h[11]);
    hp[3] = make_float4(h[12], h[13], h[14], h[15]);
}

// ================= K2: warp-per-node z gather + qkv + root =================
__global__ void __launch_bounds__(256) node_kernel(Args A) {
    __shared__ float wqs[16 * 64], wks[16 * 64], wvs[16 * 64];   // [j][u]
    __shared__ float wss[16 * 16];                               // [j][o]
    __shared__ float bqs[64], bks[64], bvs[64], bss[16];
    __shared__ float zsh[8][16];

    const int tid = threadIdx.x;
    for (int i = tid; i < 1024; i += 256) {
        const int u = i >> 4, j = i & 15;
        wqs[j * 64 + u] = A.g1Wq[i];
        wks[j * 64 + u] = A.g1Wk[i];
        wvs[j * 64 + u] = A.g1Wv[i];
    }
    for (int i = tid; i < 256; i += 256) {
        const int o = i >> 4, j = i & 15;
        wss[j * 16 + o] = A.g1Ws[i];
    }
    if (tid < 64) { bqs[tid] = A.g1bq[tid]; bks[tid] = A.g1bk[tid]; bvs[tid] = A.g1bv[tid]; }
    if (tid < 16) bss[tid] = A.g1bs[tid];
    __syncthreads();

    const int gw = blockIdx.x * 8 + (tid >> 5);
    const int l = tid & 31;
    const int wid = tid >> 5;
    if (gw >= BB * NN) return;
    const int b = gw / NN, n = gw % NN;
    const int p0 = g_rowptr[b * (NN + 1) + n], p1 = g_rowptr[b * (NN + 1) + n + 1];

    // z gather: lanes = 8 positions x 4 channel-groups
    const int pp = l >> 2, g = l & 3;
    float4 acc = make_float4(0.f, 0.f, 0.f, 0.f);
    for (int p = p0 + pp; p < p1; p += 8) {
        const int e = g_csr[b * EE + p] & 0xFFFF;
        const float4 hv = *(const float4*)&g_hbuf[((size_t)b * EE + e) * 16 + g * 4];
        acc.x += hv.x; acc.y += hv.y; acc.z += hv.z; acc.w += hv.w;
    }
#pragma unroll
    for (int off = 16; off >= 4; off >>= 1) {
        acc.x += __shfl_down_sync(0xFFFFFFFFu, acc.x, off);
        acc.y += __shfl_down_sync(0xFFFFFFFFu, acc.y, off);
        acc.z += __shfl_down_sync(0xFFFFFFFFu, acc.z, off);
        acc.w += __shfl_down_sync(0xFFFFFFFFu, acc.w, off);
    }
    if (l < 4) *(float4*)&zsh[wid][l * 4] = acc;
    __syncwarp();

    // qkv: lane handles u=l and u=l+32
    const int u0 = l, u1 = l + 32;
    float aq0 = bqs[u0], aq1 = bqs[u1];
    float ak0 = bks[u0], ak1 = bks[u1];
    float av0 = bvs[u0], av1 = bvs[u1];
#pragma unroll
    for (int j = 0; j < 16; j++) {
        const float zj = zsh[wid][j];
        aq0 += wqs[j * 64 + u0] * zj;  aq1 += wqs[j * 64 + u1] * zj;
        ak0 += wks[j * 64 + u0] * zj;  ak1 += wks[j * 64 + u1] * zj;
        av0 += wvs[j * 64 + u0] * zj;  av1 += wvs[j * 64 + u1] * zj;
    }
    const int nb = (b * NN + n) * 64;
    g_q[nb + u0] = aq0; g_q[nb + u1] = aq1;
    g_k[nb + u0] = ak0; g_k[nb + u1] = ak1;
    g_v[nb + u0] = av0; g_v[nb + u1] = av1;

    if (l < 16) {
        float ro = bss[l];
#pragma unroll
        for (int j = 0; j < 16; j++) ro += wss[j * 16 + l] * zsh[wid][j];
        g_root[(b * NN + n) * 16 + l] = ro;
    }
}

// ================= K3: per-batch edge logits =================
struct SM3 {
    float qs[NN * 68];
    float ks[NN * 68];
    float qwes[NN * 36];
    float wev[512];
};

__global__ void __launch_bounds__(K3T, 1) logits_kernel(Args A) {
    extern __shared__ unsigned char smraw[];
    SM3* s = reinterpret_cast<SM3*>(smraw);
    const int b = blockIdx.x, tid = threadIdx.x;
    const int* ei = A.ei + b * 2 * EE;
    const float* eag = A.ea + (size_t)b * EE * 8;

    for (int i = tid; i < 512; i += K3T) s->wev[i] = A.g1We[i];
    for (int i = tid; i < NN * 64; i += K3T) {
        const int n = i >> 6, u = i & 63;
        s->qs[n * 68 + u] = g_q[b * NN * 64 + i];
        s->ks[n * 68 + u] = g_k[b * NN * 64 + i];
    }
    __syncthreads();

    // qwe[n,h,j]
    for (int idx = tid; idx < NN * 32; idx += K3T) {
        const int n = idx >> 5, r = idx & 31;
        const int hh = r >> 3, j = r & 7;
        const float* qr = &s->qs[n * 68 + hh * 16];
        float acc = 0.f;
#pragma unroll
        for (int c = 0; c < 16; c++) acc += qr[c] * s->wev[(hh * 16 + c) * 8 + j];
        s->qwes[n * 36 + r] = acc;
    }
    __syncthreads();

    for (int e = tid; e < EE; e += K3T) {
        const int src = ei[e], dst = ei[EE + e];
        const float4 eA = *(const float4*)(eag + (size_t)e * 8);
        const float4 eB = *(const float4*)(eag + (size_t)e * 8 + 4);
        const float* qd = &s->qs[dst * 68];
        const float* ks = &s->ks[src * 68];
        const float* qw = &s->qwes[dst * 36];
        float4 exv;
#pragma unroll
        for (int hh = 0; hh < 4; hh++) {
            float lg = 0.f;
#pragma unroll
            for (int g = 0; g < 4; g++) {
                const int u0 = hh * 16 + g * 4;
                const float4 q4 = *(const float4*)(qd + u0);
                const float4 k4 = *(const float4*)(ks + u0);
                lg += q4.x * k4.x + q4.y * k4.y + q4.z * k4.z + q4.w * k4.w;
            }
            const float4 wa = *(const float4*)(qw + hh * 8);
            const float4 wb = *(const float4*)(qw + hh * 8 + 4);
            lg += wa.x * eA.x + wa.y * eA.y + wa.z * eA.z + wa.w * eA.w
                + wb.x * eB.x + wb.y * eB.y + wb.z * eB.z + wb.w * eB.w;
            (&exv.x)[hh] = fexp(lg * 0.25f);
        }
        *(float4*)&g_expl[(b * EE + e) * 4] = exv;
    }
}

// ================= K4: warp-per-node message aggregate + finalize =================
__global__ void __launch_bounds__(256) aggr_kernel(Args A) {
    __shared__ float wes[128 * 9];   // We padded stride 9 (conflict-free)

    const int tid = threadIdx.x;
    for (int i = tid; i < 1024; i += 256) {
        const int u = i >> 3, j = i & 7;
        wes[u * 9 + j] = A.g1We[i];
    }
    __syncthreads();

    const int gw = blockIdx.x * 8 + (tid >> 5);
    const int l = tid & 31;
    if (gw >= BB * NN) return;
    const int b = gw / NN, n = gw % NN;
    const int p0 = g_rowptr[b * (NN + 1) + n], p1 = g_rowptr[b * (NN + 1) + n + 1];

    const int u0 = l, u1 = l + 32;
    const int h0 = l >> 4;            // head of u0 (0/1)
    const int h1 = 2 + (l >> 4);      // head of u1 (2/3)
    const int hw = l >> 3, jw = l & 7; // wea mapping

    float a0 = 0.f, a1 = 0.f, w = 0.f, d = 0.f;
    for (int p = p0; p < p1; p++) {
        const int pk = g_csr[b * EE + p];
        const int e = pk & 0xFFFF, src = pk >> 16;
        const float* ex4 = &g_expl[(b * EE + e) * 4];
        const float e0 = ex4[h0], e1 = ex4[h1], ew = ex4[hw];
        const int vb = (b * NN + src) * 64;
        a0 += e0 * g_v[vb + u0];
        a1 += e1 * g_v[vb + u1];
        const float eaj = A.ea[((size_t)b * EE + e) * 8 + jw];
        w += ew * eaj;
        if (jw == 0) d += ew;
    }

    float t0 = 0.f, t1 = 0.f;
#pragma unroll
    for (int j = 0; j < 8; j++) {
        const float w0 = __shfl_sync(0xFFFFFFFFu, w, h0 * 8 + j);
        const float w1 = __shfl_sync(0xFFFFFFFFu, w, h1 * 8 + j);
        t0 += wes[u0 * 9 + j] * w0;
        t1 += wes[u1 * 9 + j] * w1;
    }
    const float d0 = __shfl_sync(0xFFFFFFFFu, d, h0 * 8);
    const float d1 = __shfl_sync(0xFFFFFFFFu, d, h1 * 8);
    const float v0 = (a0 + t0) / (d0 + 1e-16f);
    const float v1 = (a1 + t1) / (d1 + 1e-16f);
    float s1 = v0 + v1;
    s1 += __shfl_xor_sync(0xFFFFFFFFu, s1, 16);
    if (l < 16)
        g_a[(b * NN + n) * 16 + l] = 0.25f * s1 + g_root[(b * NN + n) * 16 + l];
}

// ================= K5: per-batch g2 epilogue =================
__global__ void __launch_bounds__(256) g2_kernel(Args A) {
    __shared__ float wq2[2048], wk2[2048], wv2[2048], we2[1024], ws2[512];
    __shared__ float qa[128], roota[32], denom2[4], acc2[128];
    __shared__ float aga[16];
    __shared__ int agsh;

    const int b = blockIdx.x, tid = threadIdx.x;
    for (int i = tid; i < 2048; i += 256) { wq2[i] = A.g2Wq[i]; wk2[i] = A.g2Wk[i]; wv2[i] = A.g2Wv[i]; }
    for (int i = tid; i < 1024; i += 256) we2[i] = A.g2We[i];
    for (int i = tid; i < 512; i += 256) ws2[i] = A.g2Ws[i];
    if (tid < 4) denom2[tid] = 0.f;
    if (tid < 128) acc2[tid] = 0.f;
    if (tid == 0) agsh = A.agent[b];
    __syncthreads();
    const int ag = agsh;
    if (tid < 16) aga[tid] = g_a[(b * NN + ag) * 16 + tid];
    __syncthreads();

    if (tid < 128) {
        float ac = A.g2bq[tid];
#pragma unroll
        for (int j = 0; j < 16; j++) ac += wq2[tid * 16 + j] * aga[j];
        qa[tid] = ac;
    }
    if (tid >= 128 && tid < 160) {
        const int c = tid - 128;
        float ac = A.g2bs[c];
#pragma unroll
        for (int j = 0; j < 16; j++) ac += ws2[c * 16 + j] * aga[j];
        roota[c] = ac;
    }
    __syncthreads();

    const int p0 = g_rowptr[b * (NN + 1) + ag];
    const int m = g_rowptr[b * (NN + 1) + ag + 1] - p0;
    const float* eag = A.ea + (size_t)b * EE * 8;
    for (int wk = tid; wk < m * 4; wk += 256) {
        const int pe = wk >> 2, hh = wk & 3;
        const int pk = g_csr[b * EE + p0 + pe];
        const int e = pk & 0xFFFF, src = pk >> 16;
        float ear[8];
        {
            const float4 eA = *(const float4*)(eag + (size_t)e * 8);
            const float4 eB = *(const float4*)(eag + (size_t)e * 8 + 4);
            ear[0] = eA.x; ear[1] = eA.y; ear[2] = eA.z; ear[3] = eA.w;
            ear[4] = eB.x; ear[5] = eB.y; ear[6] = eB.z; ear[7] = eB.w;
        }
        float ar[16];
        {
            const float4* ap = (const float4*)&g_a[(b * NN + src) * 16];
            const float4 a0 = ap[0], A1 = ap[1], a2 = ap[2], a3 = ap[3];
            ar[0]=a0.x; ar[1]=a0.y; ar[2]=a0.z; ar[3]=a0.w;
            ar[4]=A1.x; ar[5]=A1.y; ar[6]=A1.z; ar[7]=A1.w;
            ar[8]=a2.x; ar[9]=a2.y; ar[10]=a2.z; ar[11]=a2.w;
            ar[12]=a3.x; ar[13]=a3.y; ar[14]=a3.z; ar[15]=a3.w;
        }
        float ev[32];
        float lg = 0.f;
#pragma unroll
        for (int c = 0; c < 32; c++) {
            const int u = hh * 32 + c;
            float evv = 0.f;
#pragma unroll
            for (int j = 0; j < 8; j++) evv += we2[u * 8 + j] * ear[j];
            ev[c] = evv;
            float kk = A.g2bk[u];
#pragma unroll
            for (int j = 0; j < 16; j++) kk += wk2[u * 16 + j] * ar[j];
            lg += qa[u] * (kk + evv);
        }
        const float ex = __expf(lg * 0.17677669529663689f);
        atomicAdd(&denom2[hh], ex);
#pragma unroll
        for (int c = 0; c < 32; c++) {
            const int u = hh * 32 + c;
            float vv = A.g2bv[u];
#pragma unroll
            for (int j = 0; j < 16; j++) vv += wv2[u * 16 + j] * ar[j];
            atomicAdd(&acc2[u], ex * (vv + ev[c]));
        }
    }
    __syncthreads();

    if (tid < 32) {
        float sum = 0.f;
#pragma unroll
        for (int hh = 0; hh < 4; hh++)
            sum += acc2[hh * 32 + tid] / (denom2[hh] + 1e-16f);
        A.out[b * 32 + tid] = fmaxf(0.25f * sum + roota[tid], 0.f);
    }
}

extern "C" void kernel_launch(void* const* d_in, const int* in_sizes, int n_in,
                              void* d_out, int out_size) {
    Args A;
    A.nodes = (const float*)d_in[0];
    A.ei    = (const int*)  d_in[1];
    A.ea    = (const float*)d_in[2];
    A.agent = (const int*)  d_in[3];
    A.emb   = (const float*)d_in[4];
    A.W1 = (const float*)d_in[5];  A.b1 = (const float*)d_in[6];
    A.W2 = (const float*)d_in[7];  A.b2 = (const float*)d_in[8];
    A.W3 = (const float*)d_in[9];  A.b3 = (const float*)d_in[10];
    A.lng = (const float*)d_in[11]; A.lnb = (const float*)d_in[12];
    A.g1Wq = (const float*)d_in[13]; A.g1bq = (const float*)d_in[14];
    A.g1Wk = (const float*)d_in[15]; A.g1bk = (const float*)d_in[16];
    A.g1Wv = (const float*)d_in[17]; A.g1bv = (const float*)d_in[18];
    A.g1We = (const float*)d_in[19];
    A.g1Ws = (const float*)d_in[20]; A.g1bs = (const float*)d_in[21];
    A.g2Wq = (const float*)d_in[22]; A.g2bq = (const float*)d_in[23];
    A.g2Wk = (const float*)d_in[24]; A.g2bk = (const float*)d_in[25];
    A.g2Wv = (const float*)d_in[26]; A.g2bv = (const float*)d_in[27];
    A.g2We = (const float*)d_in[28];
    A.g2Ws = (const float*)d_in[29]; A.g2bs = (const float*)d_in[30];
    A.out = (float*)d_out;

    csr_kernel<<<BB, 256>>>(A);

    dim3 gmlp((EE + K1T - 1) / K1T, BB);
    mlp_kernel<<<gmlp, K1T>>>(A);

    node_kernel<<<(BB * NN) / 8, 256>>>(A);

    cudaFuncSetAttribute(logits_kernel, cudaFuncAttributeMaxDynamicSharedMemorySize,
                         (int)sizeof(SM3));
    logits_kernel<<<BB, K3T, sizeof(SM3)>>>(A);

    aggr_kernel<<<(BB * NN) / 8, 256>>>(A);

    g2_kernel<<<BB, 256>>>(A);
}

// round 8
// speedup vs baseline: 1.0299x; 1.0299x over previous
#include <cuda_runtime.h>

#define BB 128
#define NN 100
#define EE 3200
#define NT 1024

struct Args {
    const float* nodes;
    const int*   ei;
    const float* ea;
    const int*   agent;
    const float* emb;
    const float *W1,*b1,*W2,*b2,*W3,*b3,*lng,*lnb;
    const float *g1Wq,*g1bq,*g1Wk,*g1bk,*g1Wv,*g1bv,*g1We,*g1Ws,*g1bs;
    const float *g2Wq,*g2bq,*g2Wk,*g2bk,*g2Wv,*g2bv,*g2We,*g2Ws,*g2bs;
    float* out;
};

// block-private global scratch (written+read within one CTA across __syncthreads)
__device__ float g_hbuf[(size_t)BB * EE * 16];   // per-edge MLP outputs, by edge id e

// e^x via FMA-pipe polynomial (avoids the MUFU throughput floor)
__device__ __forceinline__ float fexp(float x) {
    float t = x * 1.4426950408889634f;
    float n = rintf(t);
    float f = t - n;
    float p = 1.3333558e-3f;
    p = p * f + 9.6181291e-3f;
    p = p * f + 5.5504109e-2f;
    p = p * f + 2.4022651e-1f;
    p = p * f + 6.9314718e-1f;
    p = p * f + 1.0f;
    int ni = (int)n;
    ni = max(-126, min(127, ni));
    return p * __int_as_float((ni + 127) << 23);
}

struct SM {
    float z[NN * 16];
    float q[NN * 68], k[NN * 68], v[NN * 68];
    float root1[NN * 16];
    float acc1[NN * 64];
    float denom1[NN * 4];
    float expl[EE * 4];        // [alias] a[NN*17] lives here after S3b (expl dead)
    float qwe[NN * 32];        // qWe in S2b..S3a; wea after (disjoint lifetimes)
    // MLP weights (vectorized rows)
    float4 W1v[48];  float b1[16];
    float4 W2v[64];  float b2[16];
    float4 W3v[64];  float b3[16];
    float lng[16], lnb[16], emb[20];
    // g1 attention weights: transposed [j][u], stride 65 (conflict-free)
    float WqT[16 * 65], WkT[16 * 65], WvT[16 * 65];
    float g1bq[64], g1bk[64], g1bv[64];
    float4 Wev[128];           // We rows as 2x float4 (row-major [u][j])
    float WsT[256];            // Ws transposed [j][o]
    float g1bs[16];
    // g2 agent-only state
    float qa[128], roota[32], denom2[4], acc2[128];
    // CSR by dst
    int csr[EE];               // (src<<16)|e
    int rowptr[NN + 1];
    int cursor[NN], deg[NN], etype[NN];
    int agent;
};
static_assert(sizeof(SM) <= 232448, "smem over limit");

__device__ __forceinline__ void cpf(float* d, const float* s, int n, int tid) {
    for (int i = tid; i < n; i += NT) d[i] = s[i];
}

__device__ __forceinline__ void ln16(float* h, const float* g, const float* bb) {
    float m = 0.f;
#pragma unroll
    for (int i = 0; i < 16; i++) m += h[i];
    m *= (1.f / 16.f);
    float var = 0.f;
#pragma unroll
    for (int i = 0; i < 16; i++) { float d = h[i] - m; var += d * d; }
    var *= (1.f / 16.f);
    float inv = rsqrtf(var + 1e-5f);
#pragma unroll
    for (int i = 0; i < 16; i++) h[i] = (h[i] - m) * inv * g[i] + bb[i];
}

__global__ void __launch_bounds__(NT, 1) gnn_kernel(Args A) {
    extern __shared__ unsigned char smraw[];
    SM* s = reinterpret_cast<SM*>(smraw);
    const int b = blockIdx.x;
    const int tid = threadIdx.x;
    const int* ei = A.ei + b * 2 * EE;
    const float* eag = A.ea + (size_t)b * EE * 8;
    const float* wef = (const float*)s->Wev;
    float* aarr = s->expl;   // alias: a[n*17+c], valid after S3b

    // ---- S0: weights -> smem, init ----
    cpf((float*)s->W1v, A.W1, 192, tid);  cpf(s->b1, A.b1, 16, tid);
    cpf((float*)s->W2v, A.W2, 256, tid);  cpf(s->b2, A.b2, 16, tid);
    cpf((float*)s->W3v, A.W3, 256, tid);  cpf(s->b3, A.b3, 16, tid);
    cpf(s->lng, A.lng, 16, tid); cpf(s->lnb, A.lnb, 16, tid);
    cpf(s->emb, A.emb, 20, tid);
    cpf((float*)s->Wev, A.g1We, 512, tid);
    cpf(s->g1bq, A.g1bq, 64, tid); cpf(s->g1bk, A.g1bk, 64, tid);
    cpf(s->g1bv, A.g1bv, 64, tid); cpf(s->g1bs, A.g1bs, 16, tid);
    for (int i = tid; i < 1024; i += NT) {
        const int u = i >> 4, j = i & 15;
        s->WqT[j * 65 + u] = A.g1Wq[i];
        s->WkT[j * 65 + u] = A.g1Wk[i];
        s->WvT[j * 65 + u] = A.g1Wv[i];
    }
    for (int i = tid; i < 256; i += NT) {
        const int o = i >> 4, j = i & 15;
        s->WsT[j * 16 + o] = A.g1Ws[i];
    }
    for (int i = tid; i < NN; i += NT) {
        s->etype[i] = (int)A.nodes[b * NN + i];
        s->deg[i] = 0;
    }
    for (int i = tid; i < 4; i += NT) s->denom2[i] = 0.f;
    for (int i = tid; i < 128; i += NT) s->acc2[i] = 0.f;
    if (tid == 0) s->agent = A.agent[b];
    __syncthreads();

    // ---- S0b: degree histogram ----
    for (int e = tid; e < EE; e += NT) atomicAdd(&s->deg[ei[EE + e]], 1);
    __syncthreads();

    // ---- S0c: warp-parallel prefix sum (warp 0) ----
    if (tid < 32) {
        int d0[4]; int t = 0;
#pragma unroll
        for (int u = 0; u < 4; u++) {
            const int n = tid * 4 + u;
            d0[u] = (n < NN) ? s->deg[n] : 0;
            t += d0[u];
        }
        int incl = t;
#pragma unroll
        for (int o = 1; o < 32; o <<= 1) {
            const int vv = __shfl_up_sync(0xFFFFFFFFu, incl, o);
            if (tid >= o) incl += vv;
        }
        int run = incl - t;
#pragma unroll
        for (int u = 0; u < 4; u++) {
            const int n = tid * 4 + u;
            if (n < NN) { s->rowptr[n] = run; run += d0[u]; }
        }
        if (tid == 31) s->rowptr[NN] = incl;
    }
    __syncthreads();
    for (int n = tid; n < NN; n += NT) s->cursor[n] = s->rowptr[n];
    __syncthreads();

    // ---- S1a: CSR scatter + per-edge MLP -> g_hbuf ----
    for (int e = tid; e < EE; e += NT) {
        const int src = ei[e], dst = ei[EE + e];
        const int pos = atomicAdd(&s->cursor[dst], 1);
        s->csr[pos] = (src << 16) | e;

        const int t = s->etype[src];
        const float4 xA = *(const float4*)&s->emb[t * 4];
        const float4 xB = *(const float4*)(eag + (size_t)e * 8);
        const float4 xC = *(const float4*)(eag + (size_t)e * 8 + 4);

        float h[16], h2[16];
#pragma unroll
        for (int o = 0; o < 16; o++) {
            const float4 w0 = s->W1v[o * 3], w1 = s->W1v[o * 3 + 1], w2 = s->W1v[o * 3 + 2];
            float acc = s->b1[o]
                + w0.x * xA.x + w0.y * xA.y + w0.z * xA.z + w0.w * xA.w
                + w1.x * xB.x + w1.y * xB.y + w1.z * xB.z + w1.w * xB.w
                + w2.x * xC.x + w2.y * xC.y + w2.z * xC.z + w2.w * xC.w;
            h[o] = fmaxf(acc, 0.f);
        }
        ln16(h, s->lng, s->lnb);
#pragma unroll
        for (int o = 0; o < 16; o++) {
            float acc = s->b2[o];
#pragma unroll
            for (int jq = 0; jq < 4; jq++) {
                const float4 w = s->W2v[o * 4 + jq];
                acc += w.x * h[jq * 4] + w.y * h[jq * 4 + 1] + w.z * h[jq * 4 + 2] + w.w * h[jq * 4 + 3];
            }
            h2[o] = fmaxf(acc, 0.f);
        }
        ln16(h2, s->lng, s->lnb);
#pragma unroll
        for (int o = 0; o < 16; o++) {
            float acc = s->b3[o];
#pragma unroll
            for (int jq = 0; jq < 4; jq++) {
                const float4 w = s->W3v[o * 4 + jq];
                acc += w.x * h2[jq * 4] + w.y * h2[jq * 4 + 1] + w.z * h2[jq * 4 + 2] + w.w * h2[jq * 4 + 3];
            }
            h[o] = fmaxf(acc, 0.f);
        }
        ln16(h, s->lng, s->lnb);

        float4* hp = (float4*)&g_hbuf[((size_t)b * EE + e) * 16];
        hp[0] = make_float4(h[0], h[1], h[2], h[3]);
        hp[1] = make_float4(h[4], h[5], h[6], h[7]);
        hp[2] = make_float4(h[8], h[9], h[10], h[11]);
        hp[3] = make_float4(h[12], h[13], h[14], h[15]);
    }
    __syncthreads();

    // ---- S1b: z = segment_sum(h, dst) via CSR gather (float4) ----
    for (int idx = tid; idx < NN * 4; idx += NT) {
        const int n = idx >> 2, g = idx & 3;
        const int p0 = s->rowptr[n], p1 = s->rowptr[n + 1];
        float4 acc = make_float4(0.f, 0.f, 0.f, 0.f);
        for (int p = p0; p < p1; p++) {
            const int e = s->csr[p] & 0xFFFF;
            const float4 hv = *(const float4*)&g_hbuf[((size_t)b * EE + e) * 16 + g * 4];
            acc.x += hv.x; acc.y += hv.y; acc.z += hv.z; acc.w += hv.w;
        }
        *(float4*)&s->z[n * 16 + g * 4] = acc;
    }
    __syncthreads();

    // ---- S2: q,k,v and root for ALL nodes (transposed weights) ----
    for (int idx = tid; idx < NN * 64; idx += NT) {
        const int n = idx >> 6, u = idx & 63;
        const float* zr = &s->z[n * 16];
        float aq = s->g1bq[u], ak = s->g1bk[u], av = s->g1bv[u];
#pragma unroll
        for (int j = 0; j < 16; j++) {
            const float zj = zr[j];
            aq += s->WqT[j * 65 + u] * zj;
            ak += s->WkT[j * 65 + u] * zj;
            av += s->WvT[j * 65 + u] * zj;
        }
        s->q[n * 68 + u] = aq; s->k[n * 68 + u] = ak; s->v[n * 68 + u] = av;
    }
    for (int idx = tid; idx < NN * 16; idx += NT) {
        const int n = idx >> 4, o = idx & 15;
        float ac = s->g1bs[o];
#pragma unroll
        for (int j = 0; j < 16; j++) ac += s->WsT[j * 16 + o] * s->z[n * 16 + j];
        s->root1[idx] = ac;
    }
    __syncthreads();

    // ---- S2b: qWe[n,h,j] = sum_c q[n,h*16+c] * We[h*16+c, j] ----
    for (int idx = tid; idx < NN * 32; idx += NT) {
        const int n = idx >> 5, r = idx & 31;
        const int hh = r >> 3, j = r & 7;
        const float* qr = &s->q[n * 68 + hh * 16];
        float acc = 0.f;
#pragma unroll
        for (int c = 0; c < 16; c++) acc += qr[c] * wef[(hh * 16 + c) * 8 + j];
        s->qwe[idx] = acc;
    }
    __syncthreads();

    // ---- S3a: per-edge logits: lg = q.k + qWe[dst].ea ----
    for (int e = tid; e < EE; e += NT) {
        const int src = ei[e], dst = ei[EE + e];
        const float4 eA = *(const float4*)(eag + (size_t)e * 8);
        const float4 eB = *(const float4*)(eag + (size_t)e * 8 + 4);
        const float* qd = &s->q[dst * 68];
        const float* ks = &s->k[src * 68];
        const float* qw = &s->qwe[dst * 32];
#pragma unroll
        for (int hh = 0; hh < 4; hh++) {
            float lg = 0.f;
#pragma unroll
            for (int g = 0; g < 4; g++) {
                const int u0 = hh * 16 + g * 4;
                const float4 q4 = *(const float4*)(qd + u0);
                const float4 k4 = *(const float4*)(ks + u0);
                lg += q4.x * k4.x + q4.y * k4.y + q4.z * k4.z + q4.w * k4.w;
            }
            const float4 wa = *(const float4*)(qw + hh * 8);
            const float4 wb = *(const float4*)(qw + hh * 8 + 4);
            lg += wa.x * eA.x + wa.y * eA.y + wa.z * eA.z + wa.w * eA.w
                + wb.x * eB.x + wb.y * eB.y + wb.z * eB.z + wb.w * eB.w;
            s->expl[e * 4 + hh] = fexp(lg * 0.25f);
        }
    }
    __syncthreads();

    // ---- S3b-1: wea[n,h,j] = sum_e expl[e,h] * ea[e,j]  (overwrites qwe) ----
    for (int idx = tid; idx < NN * 8; idx += NT) {
        const int n = idx >> 3, r = idx & 7;
        const int hh = r >> 1, half = r & 1;
        const int p0 = s->rowptr[n], p1 = s->rowptr[n + 1];
        float4 acc = make_float4(0.f, 0.f, 0.f, 0.f);
        for (int p = p0; p < p1; p++) {
            const int e = s->csr[p] & 0xFFFF;
            const float ex = s->expl[e * 4 + hh];
            const float4 ea4 = *(const float4*)(eag + (size_t)e * 8 + half * 4);
            acc.x += ex * ea4.x; acc.y += ex * ea4.y; acc.z += ex * ea4.z; acc.w += ex * ea4.w;
        }
        *(float4*)&s->qwe[n * 32 + hh * 8 + half * 4] = acc;
    }
    // ---- S3b-2: denominators ----
    for (int idx = tid; idx < NN * 4; idx += NT) {
        const int n = idx >> 2, hh = idx & 3;
        const int p0 = s->rowptr[n], p1 = s->rowptr[n + 1];
        float d = 0.f;
        for (int p = p0; p < p1; p++) d += s->expl[(s->csr[p] & 0xFFFF) * 4 + hh];
        s->denom1[idx] = d;
    }
    __syncthreads();

    // ---- S3b-3: acc1[n,u] = sum_e expl*v[src,u]  +  We[u,:].wea[n,h,:] ----
    for (int idx = tid; idx < NN * 16; idx += NT) {
        const int n = idx >> 4, g = idx & 15;
        const int u0 = g * 4, hh = g >> 2;
        const int p0 = s->rowptr[n], p1 = s->rowptr[n + 1];
        float4 acc = make_float4(0.f, 0.f, 0.f, 0.f);
        for (int p = p0; p < p1; p++) {
            const int pk = s->csr[p];
            const int e = pk & 0xFFFF, src = pk >> 16;
            const float ex = s->expl[e * 4 + hh];
            const float4 v4 = *(const float4*)&s->v[src * 68 + u0];
            acc.x += ex * v4.x; acc.y += ex * v4.y; acc.z += ex * v4.z; acc.w += ex * v4.w;
        }
        const float* we_n = &s->qwe[n * 32 + hh * 8];
        float add[4];
#pragma unroll
        for (int t = 0; t < 4; t++) {
            const int u = u0 + t;
            float a2 = 0.f;
#pragma unroll
            for (int j = 0; j < 8; j++) a2 += wef[u * 8 + j] * we_n[j];
            add[t] = a2;
        }
        acc.x += add[0]; acc.y += add[1]; acc.z += add[2]; acc.w += add[3];
        *(float4*)&s->acc1[n * 64 + u0] = acc;
    }
    __syncthreads();

    // ---- S4: a = mean_h(acc/denom) + root (a aliases expl region) ----
    for (int idx = tid; idx < NN * 16; idx += NT) {
        const int n = idx >> 4, c = idx & 15;
        float sum = 0.f;
#pragma unroll
        for (int hh = 0; hh < 4; hh++)
            sum += s->acc1[n * 64 + hh * 16 + c] / (s->denom1[n * 4 + hh] + 1e-16f);
        aarr[n * 17 + c] = 0.25f * sum + s->root1[idx];
    }
    __syncthreads();

    const int ag = s->agent;

    // ---- S5: g2 agent q and root ----
    {
        const float* ar = &aarr[ag * 17];
        for (int u = tid; u < 128; u += NT) {
            float ac = A.g2bq[u];
#pragma unroll
            for (int j = 0; j < 16; j++) ac += A.g2Wq[u * 16 + j] * ar[j];
            s->qa[u] = ac;
        }
        for (int c = tid; c < 32; c += NT) {
            float ac = A.g2bs[c];
#pragma unroll
            for (int j = 0; j < 16; j++) ac += A.g2Ws[c * 16 + j] * ar[j];
            s->roota[c] = ac;
        }
    }
    __syncthreads();

    // ---- S6: g2 edges with dst == agent ----
    {
        const int p0 = s->rowptr[ag];
        const int m = s->rowptr[ag + 1] - p0;
        for (int w = tid; w < m * 4; w += NT) {
            const int pe = w >> 2, hh = w & 3;
            const int pk = s->csr[p0 + pe];
            const int e = pk & 0xFFFF, src = pk >> 16;
            const float* eap = eag + (size_t)e * 8;
            float ear[8];
#pragma unroll
            for (int j = 0; j < 8; j++) ear[j] = eap[j];
            const float* ar = &aarr[src * 17];
            float ev[32];
            float lg = 0.f;
#pragma unroll
            for (int c = 0; c < 32; c++) {
                const int u = hh * 32 + c;
                float evv = 0.f;
#pragma unroll
                for (int j = 0; j < 8; j++) evv += A.g2We[u * 8 + j] * ear[j];
                ev[c] = evv;
                float kk = A.g2bk[u];
#pragma unroll
                for (int j = 0; j < 16; j++) kk += A.g2Wk[u * 16 + j] * ar[j];
                lg += s->qa[u] * (kk + evv);
            }
            const float ex = fexp(lg * 0.17677669529663689f);
            atomicAdd(&s->denom2[hh], ex);
#pragma unroll
            for (int c = 0; c < 32; c++) {
                const int u = hh * 32 + c;
                float vv = A.g2bv[u];
#pragma unroll
                for (int j = 0; j < 16; j++) vv += A.g2Wv[u * 16 + j] * ar[j];
                atomicAdd(&s->acc2[u], ex * (vv + ev[c]));
            }
        }
    }
    __syncthreads();

    // ---- S7: output at agent node ----
    for (int c = tid; c < 32; c += NT) {
        float sum = 0.f;
#pragma unroll
        for (int hh = 0; hh < 4; hh++)
            sum += s->acc2[hh * 32 + c] / (s->denom2[hh] + 1e-16f);
        A.out[b * 32 + c] = fmaxf(0.25f * sum + s->roota[c], 0.f);
    }
}

extern "C" void kernel_launch(void* const* d_in, const int* in_sizes, int n_in,
                              void* d_out, int out_size) {
    Args A;
    A.nodes = (const float*)d_in[0];
    A.ei    = (const int*)  d_in[1];
    A.ea    = (const float*)d_in[2];
    A.agent = (const int*)  d_in[3];
    A.emb   = (const float*)d_in[4];
    A.W1 = (const float*)d_in[5];  A.b1 = (const float*)d_in[6];
    A.W2 = (const float*)d_in[7];  A.b2 = (const float*)d_in[8];
    A.W3 = (const float*)d_in[9];  A.b3 = (const float*)d_in[10];
    A.lng = (const float*)d_in[11]; A.lnb = (const float*)d_in[12];
    A.g1Wq = (const float*)d_in[13]; A.g1bq = (const float*)d_in[14];
    A.g1Wk = (const float*)d_in[15]; A.g1bk = (const float*)d_in[16];
    A.g1Wv = (const float*)d_in[17]; A.g1bv = (const float*)d_in[18];
    A.g1We = (const float*)d_in[19];
    A.g1Ws = (const float*)d_in[20]; A.g1bs = (const float*)d_in[21];
    A.g2Wq = (const float*)d_in[22]; A.g2bq = (const float*)d_in[23];
    A.g2Wk = (const float*)d_in[24]; A.g2bk = (const float*)d_in[25];
    A.g2Wv = (const float*)d_in[26]; A.g2bv = (const float*)d_in[27];
    A.g2We = (const float*)d_in[28];
    A.g2Ws = (const float*)d_in[29]; A.g2bs = (const float*)d_in[30];
    A.out = (float*)d_out;

    cudaFuncSetAttribute(gnn_kernel, cudaFuncAttributeMaxDynamicSharedMemorySize,
                         (int)sizeof(SM));
    gnn_kernel<<<BB, NT, sizeof(SM)>>>(A);
}

// round 9
// speedup vs baseline: 1.1034x; 1.0714x over previous
#include <cuda_runtime.h>

#define BB 128
#define NN 100
#define EE 3200
#define NT 768

struct Args {
    const float* nodes;
    const int*   ei;
    const float* ea;
    const int*   agent;
    const float* emb;
    const float *W1,*b1,*W2,*b2,*W3,*b3,*lng,*lnb;
    const float *g1Wq,*g1bq,*g1Wk,*g1bk,*g1Wv,*g1bv,*g1We,*g1Ws,*g1bs;
    const float *g2Wq,*g2bq,*g2Wk,*g2bk,*g2Wv,*g2bv,*g2We,*g2Ws,*g2bs;
    float* out;
};

// block-private global scratch (written+read within one CTA across __syncthreads)
__device__ float g_hbuf[(size_t)BB * EE * 16];   // per-edge MLP outputs, by edge id e

// e^x via FMA-pipe polynomial (avoids the MUFU throughput floor)
__device__ __forceinline__ float fexp(float x) {
    float t = x * 1.4426950408889634f;
    float n = rintf(t);
    float f = t - n;
    float p = 1.3333558e-3f;
    p = p * f + 9.6181291e-3f;
    p = p * f + 5.5504109e-2f;
    p = p * f + 2.4022651e-1f;
    p = p * f + 6.9314718e-1f;
    p = p * f + 1.0f;
    int ni = (int)n;
    ni = max(-126, min(127, ni));
    return p * __int_as_float((ni + 127) << 23);
}

struct SM {
    float z[NN * 16];
    float q[NN * 68], k[NN * 68], v[NN * 68];
    float root1[NN * 16];
    float acc1[NN * 64];
    float denom1[NN * 4];
    float expl[EE * 4];        // [alias] a[NN*17] lives here after S3b (expl dead)
    float qwe[NN * 32];        // qWe in S2b..S3a; wea after (disjoint lifetimes)
    // MLP weights (vectorized rows)
    float4 W1v[48];  float b1[16];
    float4 W2v[64];  float b2[16];
    float4 W3v[64];  float b3[16];
    float lng[16], lnb[16], emb[20];
    // g1 attention weights: transposed [j][u], stride 65 (conflict-free)
    float WqT[16 * 65], WkT[16 * 65], WvT[16 * 65];
    float g1bq[64], g1bk[64], g1bv[64];
    float4 Wev[128];           // We rows as 2x float4 (row-major [u][j])
    float WsT[256];            // Ws transposed [j][o]
    float g1bs[16];
    // g2 agent-only state
    float qa[128], roota[32], denom2[4], acc2[128];
    // CSR by dst
    int csr[EE];               // (src<<16)|e
    int rowptr[NN + 1];
    int cursor[NN], deg[NN], etype[NN];
    int agent;
};
static_assert(sizeof(SM) <= 232448, "smem over limit");

__device__ __forceinline__ void cpf(float* d, const float* s, int n, int tid) {
    for (int i = tid; i < n; i += NT) d[i] = s[i];
}

__device__ __forceinline__ void ln16(float* h, const float* g, const float* bb) {
    float m = 0.f;
#pragma unroll
    for (int i = 0; i < 16; i++) m += h[i];
    m *= (1.f / 16.f);
    float var = 0.f;
#pragma unroll
    for (int i = 0; i < 16; i++) { float d = h[i] - m; var += d * d; }
    var *= (1.f / 16.f);
    float inv = rsqrtf(var + 1e-5f);
#pragma unroll
    for (int i = 0; i < 16; i++) h[i] = (h[i] - m) * inv * g[i] + bb[i];
}

__global__ void __launch_bounds__(NT, 1) gnn_kernel(Args A) {
    extern __shared__ unsigned char smraw[];
    SM* s = reinterpret_cast<SM*>(smraw);
    const int b = blockIdx.x;
    const int tid = threadIdx.x;
    const int* ei = A.ei + b * 2 * EE;
    const float* eag = A.ea + (size_t)b * EE * 8;
    const float* wef = (const float*)s->Wev;
    float* aarr = s->expl;   // alias: a[n*17+c], valid after S3b

    // ---- S0: weights -> smem, init ----
    cpf((float*)s->W1v, A.W1, 192, tid);  cpf(s->b1, A.b1, 16, tid);
    cpf((float*)s->W2v, A.W2, 256, tid);  cpf(s->b2, A.b2, 16, tid);
    cpf((float*)s->W3v, A.W3, 256, tid);  cpf(s->b3, A.b3, 16, tid);
    cpf(s->lng, A.lng, 16, tid); cpf(s->lnb, A.lnb, 16, tid);
    cpf(s->emb, A.emb, 20, tid);
    cpf((float*)s->Wev, A.g1We, 512, tid);
    cpf(s->g1bq, A.g1bq, 64, tid); cpf(s->g1bk, A.g1bk, 64, tid);
    cpf(s->g1bv, A.g1bv, 64, tid); cpf(s->g1bs, A.g1bs, 16, tid);
    for (int i = tid; i < 1024; i += NT) {
        const int u = i >> 4, j = i & 15;
        s->WqT[j * 65 + u] = A.g1Wq[i];
        s->WkT[j * 65 + u] = A.g1Wk[i];
        s->WvT[j * 65 + u] = A.g1Wv[i];
    }
    for (int i = tid; i < 256; i += NT) {
        const int o = i >> 4, j = i & 15;
        s->WsT[j * 16 + o] = A.g1Ws[i];
    }
    for (int i = tid; i < NN; i += NT) {
        s->etype[i] = (int)A.nodes[b * NN + i];
        s->deg[i] = 0;
    }
    for (int i = tid; i < 4; i += NT) s->denom2[i] = 0.f;
    for (int i = tid; i < 128; i += NT) s->acc2[i] = 0.f;
    if (tid == 0) s->agent = A.agent[b];
    __syncthreads();

    // ---- S0b: degree histogram ----
    for (int e = tid; e < EE; e += NT) atomicAdd(&s->deg[ei[EE + e]], 1);
    __syncthreads();

    // ---- S0c: warp-parallel prefix sum (warp 0) ----
    if (tid < 32) {
        int d0[4]; int t = 0;
#pragma unroll
        for (int u = 0; u < 4; u++) {
            const int n = tid * 4 + u;
            d0[u] = (n < NN) ? s->deg[n] : 0;
            t += d0[u];
        }
        int incl = t;
#pragma unroll
        for (int o = 1; o < 32; o <<= 1) {
            const int vv = __shfl_up_sync(0xFFFFFFFFu, incl, o);
            if (tid >= o) incl += vv;
        }
        int run = incl - t;
#pragma unroll
        for (int u = 0; u < 4; u++) {
            const int n = tid * 4 + u;
            if (n < NN) { s->rowptr[n] = run; run += d0[u]; }
        }
        if (tid == 31) s->rowptr[NN] = incl;
    }
    __syncthreads();
    for (int n = tid; n < NN; n += NT) s->cursor[n] = s->rowptr[n];
    __syncthreads();

    // ---- S1a: CSR scatter + per-edge MLP -> g_hbuf ----
    for (int e = tid; e < EE; e += NT) {
        const int src = ei[e], dst = ei[EE + e];
        const int pos = atomicAdd(&s->cursor[dst], 1);
        s->csr[pos] = (src << 16) | e;

        const int t = s->etype[src];
        const float4 xA = *(const float4*)&s->emb[t * 4];
        const float4 xB = *(const float4*)(eag + (size_t)e * 8);
        const float4 xC = *(const float4*)(eag + (size_t)e * 8 + 4);

        float h[16], h2[16];
#pragma unroll
        for (int o = 0; o < 16; o++) {
            const float4 w0 = s->W1v[o * 3], w1 = s->W1v[o * 3 + 1], w2 = s->W1v[o * 3 + 2];
            float acc = s->b1[o]
                + w0.x * xA.x + w0.y * xA.y + w0.z * xA.z + w0.w * xA.w
                + w1.x * xB.x + w1.y * xB.y + w1.z * xB.z + w1.w * xB.w
                + w2.x * xC.x + w2.y * xC.y + w2.z * xC.z + w2.w * xC.w;
            h[o] = fmaxf(acc, 0.f);
        }
        ln16(h, s->lng, s->lnb);
#pragma unroll
        for (int o = 0; o < 16; o++) {
            float acc = s->b2[o];
#pragma unroll
            for (int jq = 0; jq < 4; jq++) {
                const float4 w = s->W2v[o * 4 + jq];
                acc += w.x * h[jq * 4] + w.y * h[jq * 4 + 1] + w.z * h[jq * 4 + 2] + w.w * h[jq * 4 + 3];
            }
            h2[o] = fmaxf(acc, 0.f);
        }
        ln16(h2, s->lng, s->lnb);
#pragma unroll
        for (int o = 0; o < 16; o++) {
            float acc = s->b3[o];
#pragma unroll
            for (int jq = 0; jq < 4; jq++) {
                const float4 w = s->W3v[o * 4 + jq];
                acc += w.x * h2[jq * 4] + w.y * h2[jq * 4 + 1] + w.z * h2[jq * 4 + 2] + w.w * h2[jq * 4 + 3];
            }
            h[o] = fmaxf(acc, 0.f);
        }
        ln16(h, s->lng, s->lnb);

        float4* hp = (float4*)&g_hbuf[((size_t)b * EE + e) * 16];
        hp[0] = make_float4(h[0], h[1], h[2], h[3]);
        hp[1] = make_float4(h[4], h[5], h[6], h[7]);
        hp[2] = make_float4(h[8], h[9], h[10], h[11]);
        hp[3] = make_float4(h[12], h[13], h[14], h[15]);
    }
    __syncthreads();

    // ---- S1b: z = segment_sum(h, dst) via CSR gather (float4) ----
    for (int idx = tid; idx < NN * 4; idx += NT) {
        const int n = idx >> 2, g = idx & 3;
        const int p0 = s->rowptr[n], p1 = s->rowptr[n + 1];
        float4 acc = make_float4(0.f, 0.f, 0.f, 0.f);
        for (int p = p0; p < p1; p++) {
            const int e = s->csr[p] & 0xFFFF;
            const float4 hv = *(const float4*)&g_hbuf[((size_t)b * EE + e) * 16 + g * 4];
            acc.x += hv.x; acc.y += hv.y; acc.z += hv.z; acc.w += hv.w;
        }
        *(float4*)&s->z[n * 16 + g * 4] = acc;
    }
    __syncthreads();

    // ---- S2: q,k,v and root for ALL nodes (transposed weights) ----
    for (int idx = tid; idx < NN * 64; idx += NT) {
        const int n = idx >> 6, u = idx & 63;
        const float* zr = &s->z[n * 16];
        float aq = s->g1bq[u], ak = s->g1bk[u], av = s->g1bv[u];
#pragma unroll
        for (int j = 0; j < 16; j++) {
            const float zj = zr[j];
            aq += s->WqT[j * 65 + u] * zj;
            ak += s->WkT[j * 65 + u] * zj;
            av += s->WvT[j * 65 + u] * zj;
        }
        s->q[n * 68 + u] = aq; s->k[n * 68 + u] = ak; s->v[n * 68 + u] = av;
    }
    for (int idx = tid; idx < NN * 16; idx += NT) {
        const int n = idx >> 4, o = idx & 15;
        float ac = s->g1bs[o];
#pragma unroll
        for (int j = 0; j < 16; j++) ac += s->WsT[j * 16 + o] * s->z[n * 16 + j];
        s->root1[idx] = ac;
    }
    __syncthreads();

    // ---- S2b: qWe[n,h,j] = sum_c q[n,h*16+c] * We[h*16+c, j] ----
    for (int idx = tid; idx < NN * 32; idx += NT) {
        const int n = idx >> 5, r = idx & 31;
        const int hh = r >> 3, j = r & 7;
        const float* qr = &s->q[n * 68 + hh * 16];
        float acc = 0.f;
#pragma unroll
        for (int c = 0; c < 16; c++) acc += qr[c] * wef[(hh * 16 + c) * 8 + j];
        s->qwe[idx] = acc;
    }
    __syncthreads();

    // ---- S3a: per-edge logits: lg = q.k + qWe[dst].ea ----
    for (int e = tid; e < EE; e += NT) {
        const int src = ei[e], dst = ei[EE + e];
        const float4 eA = *(const float4*)(eag + (size_t)e * 8);
        const float4 eB = *(const float4*)(eag + (size_t)e * 8 + 4);
        const float* qd = &s->q[dst * 68];
        const float* ks = &s->k[src * 68];
        const float* qw = &s->qwe[dst * 32];
#pragma unroll
        for (int hh = 0; hh < 4; hh++) {
            float lg = 0.f;
#pragma unroll
            for (int g = 0; g < 4; g++) {
                const int u0 = hh * 16 + g * 4;
                const float4 q4 = *(const float4*)(qd + u0);
                const float4 k4 = *(const float4*)(ks + u0);
                lg += q4.x * k4.x + q4.y * k4.y + q4.z * k4.z + q4.w * k4.w;
            }
            const float4 wa = *(const float4*)(qw + hh * 8);
            const float4 wb = *(const float4*)(qw + hh * 8 + 4);
            lg += wa.x * eA.x + wa.y * eA.y + wa.z * eA.z + wa.w * eA.w
                + wb.x * eB.x + wb.y * eB.y + wb.z * eB.z + wb.w * eB.w;
            s->expl[e * 4 + hh] = fexp(lg * 0.25f);
        }
    }
    __syncthreads();

    // ---- S3b-1: wea[n,h,j] = sum_e expl[e,h] * ea[e,j]  (overwrites qwe) ----
    for (int idx = tid; idx < NN * 8; idx += NT) {
        const int n = idx >> 3, r = idx & 7;
        const int hh = r >> 1, half = r & 1;
        const int p0 = s->rowptr[n], p1 = s->rowptr[n + 1];
        float4 acc = make_float4(0.f, 0.f, 0.f, 0.f);
        for (int p = p0; p < p1; p++) {
            const int e = s->csr[p] & 0xFFFF;
            const float ex = s->expl[e * 4 + hh];
            const float4 ea4 = *(const float4*)(eag + (size_t)e * 8 + half * 4);
            acc.x += ex * ea4.x; acc.y += ex * ea4.y; acc.z += ex * ea4.z; acc.w += ex * ea4.w;
        }
        *(float4*)&s->qwe[n * 32 + hh * 8 + half * 4] = acc;
    }
    // ---- S3b-2: denominators ----
    for (int idx = tid; idx < NN * 4; idx += NT) {
        const int n = idx >> 2, hh = idx & 3;
        const int p0 = s->rowptr[n], p1 = s->rowptr[n + 1];
        float d = 0.f;
        for (int p = p0; p < p1; p++) d += s->expl[(s->csr[p] & 0xFFFF) * 4 + hh];
        s->denom1[idx] = d;
    }
    __syncthreads();

    // ---- S3b-3: acc1[n,u] = sum_e expl*v[src,u]  +  We[u,:].wea[n,h,:] ----
    for (int idx = tid; idx < NN * 16; idx += NT) {
        const int n = idx >> 4, g = idx & 15;
        const int u0 = g * 4, hh = g >> 2;
        const int p0 = s->rowptr[n], p1 = s->rowptr[n + 1];
        float4 acc = make_float4(0.f, 0.f, 0.f, 0.f);
        for (int p = p0; p < p1; p++) {
            const int pk = s->csr[p];
            const int e = pk & 0xFFFF, src = pk >> 16;
            const float ex = s->expl[e * 4 + hh];
            const float4 v4 = *(const float4*)&s->v[src * 68 + u0];
            acc.x += ex * v4.x; acc.y += ex * v4.y; acc.z += ex * v4.z; acc.w += ex * v4.w;
        }
        const float* we_n = &s->qwe[n * 32 + hh * 8];
        float add[4];
#pragma unroll
        for (int t = 0; t < 4; t++) {
            const int u = u0 + t;
            float a2 = 0.f;
#pragma unroll
            for (int j = 0; j < 8; j++) a2 += wef[u * 8 + j] * we_n[j];
            add[t] = a2;
        }
        acc.x += add[0]; acc.y += add[1]; acc.z += add[2]; acc.w += add[3];
        *(float4*)&s->acc1[n * 64 + u0] = acc;
    }
    __syncthreads();

    // ---- S4: a = mean_h(acc/denom) + root (a aliases expl region) ----
    for (int idx = tid; idx < NN * 16; idx += NT) {
        const int n = idx >> 4, c = idx & 15;
        float sum = 0.f;
#pragma unroll
        for (int hh = 0; hh < 4; hh++)
            sum += s->acc1[n * 64 + hh * 16 + c] / (s->denom1[n * 4 + hh] + 1e-16f);
        aarr[n * 17 + c] = 0.25f * sum + s->root1[idx];
    }
    __syncthreads();

    const int ag = s->agent;

    // ---- S5: g2 agent q and root ----
    {
        const float* ar = &aarr[ag * 17];
        for (int u = tid; u < 128; u += NT) {
            float ac = A.g2bq[u];
#pragma unroll
            for (int j = 0; j < 16; j++) ac += A.g2Wq[u * 16 + j] * ar[j];
            s->qa[u] = ac;
        }
        for (int c = tid; c < 32; c += NT) {
            float ac = A.g2bs[c];
#pragma unroll
            for (int j = 0; j < 16; j++) ac += A.g2Ws[c * 16 + j] * ar[j];
            s->roota[c] = ac;
        }
    }
    __syncthreads();

    // ---- S6: g2 edges with dst == agent ----
    {
        const int p0 = s->rowptr[ag];
        const int m = s->rowptr[ag + 1] - p0;
        for (int w = tid; w < m * 4; w += NT) {
            const int pe = w >> 2, hh = w & 3;
            const int pk = s->csr[p0 + pe];
            const int e = pk & 0xFFFF, src = pk >> 16;
            const float* eap = eag + (size_t)e * 8;
            float ear[8];
#pragma unroll
            for (int j = 0; j < 8; j++) ear[j] = eap[j];
            const float* ar = &aarr[src * 17];
            float ev[32];
            float lg = 0.f;
#pragma unroll
            for (int c = 0; c < 32; c++) {
                const int u = hh * 32 + c;
                float evv = 0.f;
#pragma unroll
                for (int j = 0; j < 8; j++) evv += A.g2We[u * 8 + j] * ear[j];
                ev[c] = evv;
                float kk = A.g2bk[u];
#pragma unroll
                for (int j = 0; j < 16; j++) kk += A.g2Wk[u * 16 + j] * ar[j];
                lg += s->qa[u] * (kk + evv);
            }
            const float ex = fexp(lg * 0.17677669529663689f);
            atomicAdd(&s->denom2[hh], ex);
#pragma unroll
            for (int c = 0; c < 32; c++) {
                const int u = hh * 32 + c;
                float vv = A.g2bv[u];
#pragma unroll
                for (int j = 0; j < 16; j++) vv += A.g2Wv[u * 16 + j] * ar[j];
                atomicAdd(&s->acc2[u], ex * (vv + ev[c]));
            }
        }
    }
    __syncthreads();

    // ---- S7: output at agent node ----
    for (int c = tid; c < 32; c += NT) {
        float sum = 0.f;
#pragma unroll
        for (int hh = 0; hh < 4; hh++)
            sum += s->acc2[hh * 32 + c] / (s->denom2[hh] + 1e-16f);
        A.out[b * 32 + c] = fmaxf(0.25f * sum + s->roota[c], 0.f);
    }
}

extern "C" void kernel_launch(void* const* d_in, const int* in_sizes, int n_in,
                              void* d_out, int out_size) {
    Args A;
    A.nodes = (const float*)d_in[0];
    A.ei    = (const int*)  d_in[1];
    A.ea    = (const float*)d_in[2];
    A.agent = (const int*)  d_in[3];
    A.emb   = (const float*)d_in[4];
    A.W1 = (const float*)d_in[5];  A.b1 = (const float*)d_in[6];
    A.W2 = (const float*)d_in[7];  A.b2 = (const float*)d_in[8];
    A.W3 = (const float*)d_in[9];  A.b3 = (const float*)d_in[10];
    A.lng = (const float*)d_in[11]; A.lnb = (const float*)d_in[12];
    A.g1Wq = (const float*)d_in[13]; A.g1bq = (const float*)d_in[14];
    A.g1Wk = (const float*)d_in[15]; A.g1bk = (const float*)d_in[16];
    A.g1Wv = (const float*)d_in[17]; A.g1bv = (const float*)d_in[18];
    A.g1We = (const float*)d_in[19];
    A.g1Ws = (const float*)d_in[20]; A.g1bs = (const float*)d_in[21];
    A.g2Wq = (const float*)d_in[22]; A.g2bq = (const float*)d_in[23];
    A.g2Wk = (const float*)d_in[24]; A.g2bk = (const float*)d_in[25];
    A.g2Wv = (const float*)d_in[26]; A.g2bv = (const float*)d_in[27];
    A.g2We = (const float*)d_in[28];
    A.g2Ws = (const float*)d_in[29]; A.g2bs = (const float*)d_in[30];
    A.out = (float*)d_out;

    cudaFuncSetAttribute(gnn_kernel, cudaFuncAttributeMaxDynamicSharedMemorySize,
                         (int)sizeof(SM));
    gnn_kernel<<<BB, NT, sizeof(SM)>>>(A);
}

// round 10
// speedup vs baseline: 1.1063x; 1.0026x over previous
#include <cuda_runtime.h>

#define BB 128
#define NN 100
#define EE 3200
#define NT 768

typedef unsigned long long u64;

struct Args {
    const float* nodes;
    const int*   ei;
    const float* ea;
    const int*   agent;
    const float* emb;
    const float *W1,*b1,*W2,*b2,*W3,*b3,*lng,*lnb;
    const float *g1Wq,*g1bq,*g1Wk,*g1bk,*g1Wv,*g1bv,*g1We,*g1Ws,*g1bs;
    const float *g2Wq,*g2bq,*g2Wk,*g2bk,*g2Wv,*g2bv,*g2We,*g2Ws,*g2bs;
    float* out;
};

// block-private global scratch (written+read within one CTA across __syncthreads)
__device__ float g_hbuf[(size_t)BB * EE * 16];   // per-edge MLP outputs, by edge id e

// packed f32x2 helpers (FFMA2 path; PTX-only per sm_103a SASS quickref)
__device__ __forceinline__ u64 fma2(u64 a, u64 b, u64 c) {
    u64 d; asm("fma.rn.f32x2 %0,%1,%2,%3;" : "=l"(d) : "l"(a), "l"(b), "l"(c)); return d;
}
__device__ __forceinline__ u64 pk2(float lo, float hi) {
    u64 r; asm("mov.b64 %0,{%1,%2};" : "=l"(r) : "f"(lo), "f"(hi)); return r;
}
__device__ __forceinline__ float hadd2(u64 v) {
    float lo, hi; asm("mov.b64 {%0,%1},%2;" : "=f"(lo), "=f"(hi) : "l"(v)); return lo + hi;
}

// e^x via FMA-pipe polynomial
__device__ __forceinline__ float fexp(float x) {
    float t = x * 1.4426950408889634f;
    float n = rintf(t);
    float f = t - n;
    float p = 1.3333558e-3f;
    p = p * f + 9.6181291e-3f;
    p = p * f + 5.5504109e-2f;
    p = p * f + 2.4022651e-1f;
    p = p * f + 6.9314718e-1f;
    p = p * f + 1.0f;
    int ni = (int)n;
    ni = max(-126, min(127, ni));
    return p * __int_as_float((ni + 127) << 23);
}

struct SM {
    float z[NN * 16];
    float q[NN * 68], k[NN * 68], v[NN * 68];
    float root1[NN * 16];
    float acc1[NN * 64];
    float denom1[NN * 4];
    float expl[EE * 4];        // [alias] a[NN*18] lives here after S3b (expl dead)
    float qwe[NN * 32];        // qWe in S2b..S3a; wea after (disjoint lifetimes)
    // MLP weights (vectorized rows)
    float4 W1v[48];  float b1[16];
    float4 W2v[64];  float b2[16];
    float4 W3v[64];  float b3[16];
    float lng[16], lnb[16], emb[20];
    // g1 attention weights: transposed [j][u], stride 66 (8B-aligned pairs, conflict-free)
    float WqT[16 * 66], WkT[16 * 66], WvT[16 * 66];
    float g1bq[64], g1bk[64], g1bv[64];
    float4 Wev[128];           // We rows as 2x float4 (row-major [u][j])
    float WsT[256];            // Ws transposed [j][o]
    float g1bs[16];
    // g2 agent-only state
    float qa[128], roota[32], denom2[4], acc2[128];
    // CSR by dst
    int csr[EE];               // (src<<16)|e
    int rowptr[NN + 1];
    int cursor[NN], deg[NN], etype[NN];
    int agent;
};
static_assert(sizeof(SM) <= 232448, "smem over limit");

__device__ __forceinline__ void cpf(float* d, const float* s, int n, int tid) {
    for (int i = tid; i < n; i += NT) d[i] = s[i];
}

__device__ __forceinline__ void ln16(float* h, const float* g, const float* bb) {
    float m = 0.f;
#pragma unroll
    for (int i = 0; i < 16; i++) m += h[i];
    m *= (1.f / 16.f);
    float var = 0.f;
#pragma unroll
    for (int i = 0; i < 16; i++) { float d = h[i] - m; var += d * d; }
    var *= (1.f / 16.f);
    float inv = rsqrtf(var + 1e-5f);
#pragma unroll
    for (int i = 0; i < 16; i++) h[i] = (h[i] - m) * inv * g[i] + bb[i];
}

__global__ void __launch_bounds__(NT, 1) gnn_kernel(Args A) {
    extern __shared__ unsigned char smraw[];
    SM* s = reinterpret_cast<SM*>(smraw);
    const int b = blockIdx.x;
    const int tid = threadIdx.x;
    const int* ei = A.ei + b * 2 * EE;
    const float* eag = A.ea + (size_t)b * EE * 8;
    const float* wef = (const float*)s->Wev;
    float* aarr = s->expl;   // alias: a[n*18+c], valid after S3b

    // ---- S0: weights -> smem, init ----
    cpf((float*)s->W1v, A.W1, 192, tid);  cpf(s->b1, A.b1, 16, tid);
    cpf((float*)s->W2v, A.W2, 256, tid);  cpf(s->b2, A.b2, 16, tid);
    cpf((float*)s->W3v, A.W3, 256, tid);  cpf(s->b3, A.b3, 16, tid);
    cpf(s->lng, A.lng, 16, tid); cpf(s->lnb, A.lnb, 16, tid);
    cpf(s->emb, A.emb, 20, tid);
    cpf((float*)s->Wev, A.g1We, 512, tid);
    cpf(s->g1bq, A.g1bq, 64, tid); cpf(s->g1bk, A.g1bk, 64, tid);
    cpf(s->g1bv, A.g1bv, 64, tid); cpf(s->g1bs, A.g1bs, 16, tid);
    for (int i = tid; i < 1024; i += NT) {
        const int u = i >> 4, j = i & 15;
        s->WqT[j * 66 + u] = A.g1Wq[i];
        s->WkT[j * 66 + u] = A.g1Wk[i];
        s->WvT[j * 66 + u] = A.g1Wv[i];
    }
    for (int i = tid; i < 256; i += NT) {
        const int o = i >> 4, j = i & 15;
        s->WsT[j * 16 + o] = A.g1Ws[i];
    }
    for (int i = tid; i < NN; i += NT) {
        s->etype[i] = (int)A.nodes[b * NN + i];
        s->deg[i] = 0;
    }
    for (int i = tid; i < 4; i += NT) s->denom2[i] = 0.f;
    for (int i = tid; i < 128; i += NT) s->acc2[i] = 0.f;
    if (tid == 0) s->agent = A.agent[b];
    __syncthreads();

    // ---- S0b: degree histogram ----
    for (int e = tid; e < EE; e += NT) atomicAdd(&s->deg[ei[EE + e]], 1);
    __syncthreads();

    // ---- S0c: warp-parallel prefix sum (warp 0) ----
    if (tid < 32) {
        int d0[4]; int t = 0;
#pragma unroll
        for (int u = 0; u < 4; u++) {
            const int n = tid * 4 + u;
            d0[u] = (n < NN) ? s->deg[n] : 0;
            t += d0[u];
        }
        int incl = t;
#pragma unroll
        for (int o = 1; o < 32; o <<= 1) {
            const int vv = __shfl_up_sync(0xFFFFFFFFu, incl, o);
            if (tid >= o) incl += vv;
        }
        int run = incl - t;
#pragma unroll
        for (int u = 0; u < 4; u++) {
            const int n = tid * 4 + u;
            if (n < NN) { s->rowptr[n] = run; run += d0[u]; }
        }
        if (tid == 31) s->rowptr[NN] = incl;
    }
    __syncthreads();
    for (int n = tid; n < NN; n += NT) s->cursor[n] = s->rowptr[n];
    __syncthreads();

    // ---- S1a: CSR scatter + per-edge MLP (packed f32x2) -> g_hbuf ----
    for (int e = tid; e < EE; e += NT) {
        const int src = ei[e], dst = ei[EE + e];
        const int pos = atomicAdd(&s->cursor[dst], 1);
        s->csr[pos] = (src << 16) | e;

        const int t = s->etype[src];
        const float4 xA = *(const float4*)&s->emb[t * 4];
        const float4 xB = *(const float4*)(eag + (size_t)e * 8);
        const float4 xC = *(const float4*)(eag + (size_t)e * 8 + 4);

        u64 xp[6];
        xp[0] = pk2(xA.x, xA.y); xp[1] = pk2(xA.z, xA.w);
        xp[2] = pk2(xB.x, xB.y); xp[3] = pk2(xB.z, xB.w);
        xp[4] = pk2(xC.x, xC.y); xp[5] = pk2(xC.z, xC.w);

        float h[16], h2[16];
#pragma unroll
        for (int o = 0; o < 16; o++) {
            const ulonglong2* wr = reinterpret_cast<const ulonglong2*>(&s->W1v[o * 3]);
            const ulonglong2 wa = wr[0], wb = wr[1], wc = wr[2];
            u64 acc = pk2(s->b1[o], 0.f);
            acc = fma2(wa.x, xp[0], acc); acc = fma2(wa.y, xp[1], acc);
            acc = fma2(wb.x, xp[2], acc); acc = fma2(wb.y, xp[3], acc);
            acc = fma2(wc.x, xp[4], acc); acc = fma2(wc.y, xp[5], acc);
            h[o] = fmaxf(hadd2(acc), 0.f);
        }
        ln16(h, s->lng, s->lnb);
        u64 hp2[8];
#pragma unroll
        for (int i = 0; i < 8; i++) hp2[i] = pk2(h[i * 2], h[i * 2 + 1]);
#pragma unroll
        for (int o = 0; o < 16; o++) {
            const ulonglong2* wr = reinterpret_cast<const ulonglong2*>(&s->W2v[o * 4]);
            const ulonglong2 w0 = wr[0], w1 = wr[1], w2 = wr[2], w3 = wr[3];
            u64 acc = pk2(s->b2[o], 0.f);
            acc = fma2(w0.x, hp2[0], acc); acc = fma2(w0.y, hp2[1], acc);
            acc = fma2(w1.x, hp2[2], acc); acc = fma2(w1.y, hp2[3], acc);
            acc = fma2(w2.x, hp2[4], acc); acc = fma2(w2.y, hp2[5], acc);
            acc = fma2(w3.x, hp2[6], acc); acc = fma2(w3.y, hp2[7], acc);
            h2[o] = fmaxf(hadd2(acc), 0.f);
        }
        ln16(h2, s->lng, s->lnb);
#pragma unroll
        for (int i = 0; i < 8; i++) hp2[i] = pk2(h2[i * 2], h2[i * 2 + 1]);
#pragma unroll
        for (int o = 0; o < 16; o++) {
            const ulonglong2* wr = reinterpret_cast<const ulonglong2*>(&s->W3v[o * 4]);
            const ulonglong2 w0 = wr[0], w1 = wr[1], w2 = wr[2], w3 = wr[3];
            u64 acc = pk2(s->b3[o], 0.f);
            acc = fma2(w0.x, hp2[0], acc); acc = fma2(w0.y, hp2[1], acc);
            acc = fma2(w1.x, hp2[2], acc); acc = fma2(w1.y, hp2[3], acc);
            acc = fma2(w2.x, hp2[4], acc); acc = fma2(w2.y, hp2[5], acc);
            acc = fma2(w3.x, hp2[6], acc); acc = fma2(w3.y, hp2[7], acc);
            h[o] = fmaxf(hadd2(acc), 0.f);
        }
        ln16(h, s->lng, s->lnb);

        float4* hp = (float4*)&g_hbuf[((size_t)b * EE + e) * 16];
        hp[0] = make_float4(h[0], h[1], h[2], h[3]);
        hp[1] = make_float4(h[4], h[5], h[6], h[7]);
        hp[2] = make_float4(h[8], h[9], h[10], h[11]);
        hp[3] = make_float4(h[12], h[13], h[14], h[15]);
    }
    __syncthreads();

    // ---- S1b: z = segment_sum(h, dst) via CSR gather (float4) ----
    for (int idx = tid; idx < NN * 4; idx += NT) {
        const int n = idx >> 2, g = idx & 3;
        const int p0 = s->rowptr[n], p1 = s->rowptr[n + 1];
        float4 acc = make_float4(0.f, 0.f, 0.f, 0.f);
#pragma unroll 4
        for (int p = p0; p < p1; p++) {
            const int e = s->csr[p] & 0xFFFF;
            const float4 hv = *(const float4*)&g_hbuf[((size_t)b * EE + e) * 16 + g * 4];
            acc.x += hv.x; acc.y += hv.y; acc.z += hv.z; acc.w += hv.w;
        }
        *(float4*)&s->z[n * 16 + g * 4] = acc;
    }
    __syncthreads();

    // ---- S2: q,k,v packed over u-pairs; root for all nodes ----
    for (int idx = tid; idx < NN * 32; idx += NT) {
        const int n = idx >> 5, up = idx & 31;
        const int u = up * 2;
        const float* zr = &s->z[n * 16];
        u64 aq = *(const u64*)&s->g1bq[u];
        u64 ak = *(const u64*)&s->g1bk[u];
        u64 av = *(const u64*)&s->g1bv[u];
#pragma unroll
        for (int j = 0; j < 16; j++) {
            const u64 zj = pk2(zr[j], zr[j]);
            aq = fma2(*(const u64*)&s->WqT[j * 66 + u], zj, aq);
            ak = fma2(*(const u64*)&s->WkT[j * 66 + u], zj, ak);
            av = fma2(*(const u64*)&s->WvT[j * 66 + u], zj, av);
        }
        *(u64*)&s->q[n * 68 + u] = aq;
        *(u64*)&s->k[n * 68 + u] = ak;
        *(u64*)&s->v[n * 68 + u] = av;
    }
    for (int idx = tid; idx < NN * 16; idx += NT) {
        const int n = idx >> 4, o = idx & 15;
        float ac = s->g1bs[o];
#pragma unroll
        for (int j = 0; j < 16; j++) ac += s->WsT[j * 16 + o] * s->z[n * 16 + j];
        s->root1[idx] = ac;
    }
    __syncthreads();

    // ---- S2b: qWe[n,h,j] = sum_c q[n,h*16+c] * We[h*16+c, j] ----
    for (int idx = tid; idx < NN * 32; idx += NT) {
        const int n = idx >> 5, r = idx & 31;
        const int hh = r >> 3, j = r & 7;
        const float* qr = &s->q[n * 68 + hh * 16];
        float acc = 0.f;
#pragma unroll
        for (int c = 0; c < 16; c++) acc += qr[c] * wef[(hh * 16 + c) * 8 + j];
        s->qwe[idx] = acc;
    }
    __syncthreads();

    // ---- S3a: per-edge logits (packed): lg = q.k + qWe[dst].ea ----
    for (int e = tid; e < EE; e += NT) {
        const int src = ei[e], dst = ei[EE + e];
        const float4 eA = *(const float4*)(eag + (size_t)e * 8);
        const float4 eB = *(const float4*)(eag + (size_t)e * 8 + 4);
        u64 eap[4];
        eap[0] = pk2(eA.x, eA.y); eap[1] = pk2(eA.z, eA.w);
        eap[2] = pk2(eB.x, eB.y); eap[3] = pk2(eB.z, eB.w);
        const ulonglong2* qd2 = (const ulonglong2*)&s->q[dst * 68];
        const ulonglong2* ks2 = (const ulonglong2*)&s->k[src * 68];
        const ulonglong2* qw2 = (const ulonglong2*)&s->qwe[dst * 32];
#pragma unroll
        for (int hh = 0; hh < 4; hh++) {
            u64 acc = 0ull;
#pragma unroll
            for (int t = 0; t < 4; t++) {
                const ulonglong2 q2 = qd2[hh * 4 + t];
                const ulonglong2 k2 = ks2[hh * 4 + t];
                acc = fma2(q2.x, k2.x, acc);
                acc = fma2(q2.y, k2.y, acc);
            }
            const ulonglong2 wa = qw2[hh * 2], wb = qw2[hh * 2 + 1];
            acc = fma2(wa.x, eap[0], acc);
            acc = fma2(wa.y, eap[1], acc);
            acc = fma2(wb.x, eap[2], acc);
            acc = fma2(wb.y, eap[3], acc);
            s->expl[e * 4 + hh] = fexp(hadd2(acc) * 0.25f);
        }
    }
    __syncthreads();

    // ---- S3b-1: wea[n,h,j] = sum_e expl[e,h]*ea[e,j] + denominators fused ----
    for (int idx = tid; idx < NN * 8; idx += NT) {
        const int n = idx >> 3, r = idx & 7;
        const int hh = r >> 1, half = r & 1;
        const int p0 = s->rowptr[n], p1 = s->rowptr[n + 1];
        float4 acc = make_float4(0.f, 0.f, 0.f, 0.f);
        float d = 0.f;
#pragma unroll 4
        for (int p = p0; p < p1; p++) {
            const int e = s->csr[p] & 0xFFFF;
            const float ex = s->expl[e * 4 + hh];
            const float4 ea4 = *(const float4*)(eag + (size_t)e * 8 + half * 4);
            acc.x += ex * ea4.x; acc.y += ex * ea4.y; acc.z += ex * ea4.z; acc.w += ex * ea4.w;
            d += ex;
        }
        *(float4*)&s->qwe[n * 32 + hh * 8 + half * 4] = acc;
        if (half == 0) s->denom1[n * 4 + hh] = d;
    }
    __syncthreads();

    // ---- S3b-3: acc1[n,u] = sum_e expl*v[src,u]  +  We[u,:].wea[n,h,:] ----
    for (int idx = tid; idx < NN * 16; idx += NT) {
        const int n = idx >> 4, g = idx & 15;
        const int u0 = g * 4, hh = g >> 2;
        const int p0 = s->rowptr[n], p1 = s->rowptr[n + 1];
        float4 acc = make_float4(0.f, 0.f, 0.f, 0.f);
#pragma unroll 4
        for (int p = p0; p < p1; p++) {
            const int pk = s->csr[p];
            const int e = pk & 0xFFFF, src = pk >> 16;
            const float ex = s->expl[e * 4 + hh];
            const float4 v4 = *(const float4*)&s->v[src * 68 + u0];
            acc.x += ex * v4.x; acc.y += ex * v4.y; acc.z += ex * v4.z; acc.w += ex * v4.w;
        }
        const float* we_n = &s->qwe[n * 32 + hh * 8];
        float add[4];
#pragma unroll
        for (int t = 0; t < 4; t++) {
            const int u = u0 + t;
            float a2 = 0.f;
#pragma unroll
            for (int j = 0; j < 8; j++) a2 += wef[u * 8 + j] * we_n[j];
            add[t] = a2;
        }
        acc.x += add[0]; acc.y += add[1]; acc.z += add[2]; acc.w += add[3];
        *(float4*)&s->acc1[n * 64 + u0] = acc;
    }
    __syncthreads();

    // ---- S4: a = mean_h(acc/denom) + root (a aliases expl region, stride 18) ----
    for (int idx = tid; idx < NN * 16; idx += NT) {
        const int n = idx >> 4, c = idx & 15;
        float sum = 0.f;
#pragma unroll
        for (int hh = 0; hh < 4; hh++)
            sum += s->acc1[n * 64 + hh * 16 + c] / (s->denom1[n * 4 + hh] + 1e-16f);
        aarr[n * 18 + c] = 0.25f * sum + s->root1[idx];
    }
    __syncthreads();

    const int ag = s->agent;

    // ---- S5: g2 agent q and root ----
    {
        const float* ar = &aarr[ag * 18];
        for (int u = tid; u < 128; u += NT) {
            float ac = A.g2bq[u];
#pragma unroll
            for (int j = 0; j < 16; j++) ac += A.g2Wq[u * 16 + j] * ar[j];
            s->qa[u] = ac;
        }
        for (int c = tid; c < 32; c += NT) {
            float ac = A.g2bs[c];
#pragma unroll
            for (int j = 0; j < 16; j++) ac += A.g2Ws[c * 16 + j] * ar[j];
            s->roota[c] = ac;
        }
    }
    __syncthreads();

    // ---- S6: g2 edges with dst == agent ----
    {
        const int p0 = s->rowptr[ag];
        const int m = s->rowptr[ag + 1] - p0;
        for (int w = tid; w < m * 4; w += NT) {
            const int pe = w >> 2, hh = w & 3;
            const int pk = s->csr[p0 + pe];
            const int e = pk & 0xFFFF, src = pk >> 16;
            const float* eap = eag + (size_t)e * 8;
            float ear[8];
#pragma unroll
            for (int j = 0; j < 8; j++) ear[j] = eap[j];
            const float* ar = &aarr[src * 18];
            float ev[32];
            float lg = 0.f;
#pragma unroll
            for (int c = 0; c < 32; c++) {
                const int u = hh * 32 + c;
                float evv = 0.f;
#pragma unroll
                for (int j = 0; j < 8; j++) evv += A.g2We[u * 8 + j] * ear[j];
                ev[c] = evv;
                float kk = A.g2bk[u];
#pragma unroll
                for (int j = 0; j < 16; j++) kk += A.g2Wk[u * 16 + j] * ar[j];
                lg += s->qa[u] * (kk + evv);
            }
            const float ex = fexp(lg * 0.17677669529663689f);
            atomicAdd(&s->denom2[hh], ex);
#pragma unroll
            for (int c = 0; c < 32; c++) {
                const int u = hh * 32 + c;
                float vv = A.g2bv[u];
#pragma unroll
                for (int j = 0; j < 16; j++) vv += A.g2Wv[u * 16 + j] * ar[j];
                atomicAdd(&s->acc2[u], ex * (vv + ev[c]));
            }
        }
    }
    __syncthreads();

    // ---- S7: output at agent node ----
    for (int c = tid; c < 32; c += NT) {
        float sum = 0.f;
#pragma unroll
        for (int hh = 0; hh < 4; hh++)
            sum += s->acc2[hh * 32 + c] / (s->denom2[hh] + 1e-16f);
        A.out[b * 32 + c] = fmaxf(0.25f * sum + s->roota[c], 0.f);
    }
}

extern "C" void kernel_launch(void* const* d_in, const int* in_sizes, int n_in,
                              void* d_out, int out_size) {
    Args A;
    A.nodes = (const float*)d_in[0];
    A.ei    = (const int*)  d_in[1];
    A.ea    = (const float*)d_in[2];
    A.agent = (const int*)  d_in[3];
    A.emb   = (const float*)d_in[4];
    A.W1 = (const float*)d_in[5];  A.b1 = (const float*)d_in[6];
    A.W2 = (const float*)d_in[7];  A.b2 = (const float*)d_in[8];
    A.W3 = (const float*)d_in[9];  A.b3 = (const float*)d_in[10];
    A.lng = (const float*)d_in[11]; A.lnb = (const float*)d_in[12];
    A.g1Wq = (const float*)d_in[13]; A.g1bq = (const float*)d_in[14];
    A.g1Wk = (const float*)d_in[15]; A.g1bk = (const float*)d_in[16];
    A.g1Wv = (const float*)d_in[17]; A.g1bv = (const float*)d_in[18];
    A.g1We = (const float*)d_in[19];
    A.g1Ws = (const float*)d_in[20]; A.g1bs = (const float*)d_in[21];
    A.g2Wq = (const float*)d_in[22]; A.g2bq = (const float*)d_in[23];
    A.g2Wk = (const float*)d_in[24]; A.g2bk = (const float*)d_in[25];
    A.g2Wv = (const float*)d_in[26]; A.g2bv = (const float*)d_in[27];
    A.g2We = (const float*)d_in[28];
    A.g2Ws = (const float*)d_in[29]; A.g2bs = (const float*)d_in[30];
    A.out = (float*)d_out;

    cudaFuncSetAttribute(gnn_kernel, cudaFuncAttributeMaxDynamicSharedMemorySize,
                         (int)sizeof(SM));
    gnn_kernel<<<BB, NT, sizeof(SM)>>>(A);
}

// round 11
// speedup vs baseline: 1.1894x; 1.0751x over previous
#include <cuda_runtime.h>

#define BB 128
#define NN 100
#define EE 3200
#define NT 768

typedef unsigned long long u64;

struct Args {
    const float* nodes;
    const int*   ei;
    const float* ea;
    const int*   agent;
    const float* emb;
    const float *W1,*b1,*W2,*b2,*W3,*b3,*lng,*lnb;
    const float *g1Wq,*g1bq,*g1Wk,*g1bk,*g1Wv,*g1bv,*g1We,*g1Ws,*g1bs;
    const float *g2Wq,*g2bq,*g2Wk,*g2bk,*g2Wv,*g2bv,*g2We,*g2Ws,*g2bs;
    float* out;
};

__device__ float g_hbuf[(size_t)BB * EE * 16];   // per-edge MLP outputs, by edge id e

__device__ __forceinline__ u64 fma2(u64 a, u64 b, u64 c) {
    u64 d; asm("fma.rn.f32x2 %0,%1,%2,%3;" : "=l"(d) : "l"(a), "l"(b), "l"(c)); return d;
}
__device__ __forceinline__ u64 pk2(float lo, float hi) {
    u64 r; asm("mov.b64 %0,{%1,%2};" : "=l"(r) : "f"(lo), "f"(hi)); return r;
}
__device__ __forceinline__ float hadd2(u64 v) {
    float lo, hi; asm("mov.b64 {%0,%1},%2;" : "=f"(lo), "=f"(hi) : "l"(v)); return lo + hi;
}
__device__ __forceinline__ void unpk2(u64 v, float& lo, float& hi) {
    asm("mov.b64 {%0,%1},%2;" : "=f"(lo), "=f"(hi) : "l"(v));
}

__device__ __forceinline__ float fexp(float x) {
    float t = x * 1.4426950408889634f;
    float n = rintf(t);
    float f = t - n;
    float p = 1.3333558e-3f;
    p = p * f + 9.6181291e-3f;
    p = p * f + 5.5504109e-2f;
    p = p * f + 2.4022651e-1f;
    p = p * f + 6.9314718e-1f;
    p = p * f + 1.0f;
    int ni = (int)n;
    ni = max(-126, min(127, ni));
    return p * __int_as_float((ni + 127) << 23);
}

struct SM {
    float z[NN * 16];
    float q[NN * 66], k[NN * 66], v[NN * 66];   // stride 66: 16 bank residues, 8B aligned
    float root1[NN * 16];
    float acc1[NN * 64];
    float denom1[NN * 4];
    float expl[EE * 4];        // indexed by CSR position p; [alias] a[NN*18] after S3b
    float qwe[NN * 32];        // qWe in S2b..S3a; wea after (disjoint lifetimes)
    float4 W1v[48];  float b1[16];
    float4 W2v[64];  float b2[16];
    float4 W3v[64];  float b3[16];
    float lng[16], lnb[16], emb[20];
    float WqT[16 * 66], WkT[16 * 66], WvT[16 * 66];
    float g1bq[64], g1bk[64], g1bv[64];
    float4 Wev[128];
    float WsT[256];
    float g1bs[16];
    float qa[128], roota[32], denom2[4], acc2[128];
    int csr[EE];               // (dst<<19)|(src<<12)|e
    int rowptr[NN + 1];
    int cursor[NN], deg[NN], etype[NN];
    int agent;
};
static_assert(sizeof(SM) <= 232448, "smem over limit");

__device__ __forceinline__ void cpf(float* d, const float* s, int n, int tid) {
    for (int i = tid; i < n; i += NT) d[i] = s[i];
}

__device__ __forceinline__ void ln16(float* h, const float* g, const float* bb) {
    float m = 0.f;
#pragma unroll
    for (int i = 0; i < 16; i++) m += h[i];
    m *= (1.f / 16.f);
    float var = 0.f;
#pragma unroll
    for (int i = 0; i < 16; i++) { float d = h[i] - m; var += d * d; }
    var *= (1.f / 16.f);
    float inv = rsqrtf(var + 1e-5f);
#pragma unroll
    for (int i = 0; i < 16; i++) h[i] = (h[i] - m) * inv * g[i] + bb[i];
}

__global__ void __launch_bounds__(NT, 1) gnn_kernel(Args A) {
    extern __shared__ unsigned char smraw[];
    SM* s = reinterpret_cast<SM*>(smraw);
    const int b = blockIdx.x;
    const int tid = threadIdx.x;
    const int* ei = A.ei + b * 2 * EE;
    const float* eag = A.ea + (size_t)b * EE * 8;
    const float* wef = (const float*)s->Wev;
    float* aarr = s->expl;   // alias: a[n*18+c], valid after S3b

    // ---- S0 ----
    cpf((float*)s->W1v, A.W1, 192, tid);  cpf(s->b1, A.b1, 16, tid);
    cpf((float*)s->W2v, A.W2, 256, tid);  cpf(s->b2, A.b2, 16, tid);
    cpf((float*)s->W3v, A.W3, 256, tid);  cpf(s->b3, A.b3, 16, tid);
    cpf(s->lng, A.lng, 16, tid); cpf(s->lnb, A.lnb, 16, tid);
    cpf(s->emb, A.emb, 20, tid);
    cpf((float*)s->Wev, A.g1We, 512, tid);
    cpf(s->g1bq, A.g1bq, 64, tid); cpf(s->g1bk, A.g1bk, 64, tid);
    cpf(s->g1bv, A.g1bv, 64, tid); cpf(s->g1bs, A.g1bs, 16, tid);
    for (int i = tid; i < 1024; i += NT) {
        const int u = i >> 4, j = i & 15;
        s->WqT[j * 66 + u] = A.g1Wq[i];
        s->WkT[j * 66 + u] = A.g1Wk[i];
        s->WvT[j * 66 + u] = A.g1Wv[i];
    }
    for (int i = tid; i < 256; i += NT) {
        const int o = i >> 4, j = i & 15;
        s->WsT[j * 16 + o] = A.g1Ws[i];
    }
    for (int i = tid; i < NN; i += NT) {
        s->etype[i] = (int)A.nodes[b * NN + i];
        s->deg[i] = 0;
    }
    for (int i = tid; i < 4; i += NT) s->denom2[i] = 0.f;
    for (int i = tid; i < 128; i += NT) s->acc2[i] = 0.f;
    if (tid == 0) s->agent = A.agent[b];
    __syncthreads();

    // ---- S0b: degree histogram ----
    for (int e = tid; e < EE; e += NT) atomicAdd(&s->deg[ei[EE + e]], 1);
    __syncthreads();

    // ---- S0c: warp-parallel prefix sum ----
    if (tid < 32) {
        int d0[4]; int t = 0;
#pragma unroll
        for (int u = 0; u < 4; u++) {
            const int n = tid * 4 + u;
            d0[u] = (n < NN) ? s->deg[n] : 0;
            t += d0[u];
        }
        int incl = t;
#pragma unroll
        for (int o = 1; o < 32; o <<= 1) {
            const int vv = __shfl_up_sync(0xFFFFFFFFu, incl, o);
            if (tid >= o) incl += vv;
        }
        int run = incl - t;
#pragma unroll
        for (int u = 0; u < 4; u++) {
            const int n = tid * 4 + u;
            if (n < NN) { s->rowptr[n] = run; run += d0[u]; }
        }
        if (tid == 31) s->rowptr[NN] = incl;
    }
    __syncthreads();
    for (int n = tid; n < NN; n += NT) s->cursor[n] = s->rowptr[n];
    __syncthreads();

    // ---- S1a: CSR scatter ((dst<<19)|(src<<12)|e) + per-edge MLP ----
    for (int e = tid; e < EE; e += NT) {
        const int src = ei[e], dst = ei[EE + e];
        const int pos = atomicAdd(&s->cursor[dst], 1);
        s->csr[pos] = (dst << 19) | (src << 12) | e;

        const int t = s->etype[src];
        const float4 xA = *(const float4*)&s->emb[t * 4];
        const float4 xB = *(const float4*)(eag + (size_t)e * 8);
        const float4 xC = *(const float4*)(eag + (size_t)e * 8 + 4);

        u64 xp[6];
        xp[0] = pk2(xA.x, xA.y); xp[1] = pk2(xA.z, xA.w);
        xp[2] = pk2(xB.x, xB.y); xp[3] = pk2(xB.z, xB.w);
        xp[4] = pk2(xC.x, xC.y); xp[5] = pk2(xC.z, xC.w);

        float h[16], h2[16];
#pragma unroll
        for (int o = 0; o < 16; o++) {
            const ulonglong2* wr = reinterpret_cast<const ulonglong2*>(&s->W1v[o * 3]);
            const ulonglong2 wa = wr[0], wb = wr[1], wc = wr[2];
            u64 acc = pk2(s->b1[o], 0.f);
            acc = fma2(wa.x, xp[0], acc); acc = fma2(wa.y, xp[1], acc);
            acc = fma2(wb.x, xp[2], acc); acc = fma2(wb.y, xp[3], acc);
            acc = fma2(wc.x, xp[4], acc); acc = fma2(wc.y, xp[5], acc);
            h[o] = fmaxf(hadd2(acc), 0.f);
        }
        ln16(h, s->lng, s->lnb);
        u64 hp2[8];
#pragma unroll
        for (int i = 0; i < 8; i++) hp2[i] = pk2(h[i * 2], h[i * 2 + 1]);
#pragma unroll
        for (int o = 0; o < 16; o++) {
            const ulonglong2* wr = reinterpret_cast<const ulonglong2*>(&s->W2v[o * 4]);
            const ulonglong2 w0 = wr[0], w1 = wr[1], w2 = wr[2], w3 = wr[3];
            u64 acc = pk2(s->b2[o], 0.f);
            acc = fma2(w0.x, hp2[0], acc); acc = fma2(w0.y, hp2[1], acc);
            acc = fma2(w1.x, hp2[2], acc); acc = fma2(w1.y, hp2[3], acc);
            acc = fma2(w2.x, hp2[4], acc); acc = fma2(w2.y, hp2[5], acc);
            acc = fma2(w3.x, hp2[6], acc); acc = fma2(w3.y, hp2[7], acc);
            h2[o] = fmaxf(hadd2(acc), 0.f);
        }
        ln16(h2, s->lng, s->lnb);
#pragma unroll
        for (int i = 0; i < 8; i++) hp2[i] = pk2(h2[i * 2], h2[i * 2 + 1]);
#pragma unroll
        for (int o = 0; o < 16; o++) {
            const ulonglong2* wr = reinterpret_cast<const ulonglong2*>(&s->W3v[o * 4]);
            const ulonglong2 w0 = wr[0], w1 = wr[1], w2 = wr[2], w3 = wr[3];
            u64 acc = pk2(s->b3[o], 0.f);
            acc = fma2(w0.x, hp2[0], acc); acc = fma2(w0.y, hp2[1], acc);
            acc = fma2(w1.x, hp2[2], acc); acc = fma2(w1.y, hp2[3], acc);
            acc = fma2(w2.x, hp2[4], acc); acc = fma2(w2.y, hp2[5], acc);
            acc = fma2(w3.x, hp2[6], acc); acc = fma2(w3.y, hp2[7], acc);
            h[o] = fmaxf(hadd2(acc), 0.f);
        }
        ln16(h, s->lng, s->lnb);

        float4* hp = (float4*)&g_hbuf[((size_t)b * EE + e) * 16];
        hp[0] = make_float4(h[0], h[1], h[2], h[3]);
        hp[1] = make_float4(h[4], h[5], h[6], h[7]);
        hp[2] = make_float4(h[8], h[9], h[10], h[11]);
        hp[3] = make_float4(h[12], h[13], h[14], h[15]);
    }
    __syncthreads();

    // ---- S1b: z = segment_sum(h, dst) ----
    for (int idx = tid; idx < NN * 4; idx += NT) {
        const int n = idx >> 2, g = idx & 3;
        const int p0 = s->rowptr[n], p1 = s->rowptr[n + 1];
        float4 acc = make_float4(0.f, 0.f, 0.f, 0.f);
#pragma unroll 4
        for (int p = p0; p < p1; p++) {
            const int e = s->csr[p] & 0xFFF;
            const float4 hv = *(const float4*)&g_hbuf[((size_t)b * EE + e) * 16 + g * 4];
            acc.x += hv.x; acc.y += hv.y; acc.z += hv.z; acc.w += hv.w;
        }
        *(float4*)&s->z[n * 16 + g * 4] = acc;
    }
    __syncthreads();

    // ---- S2: q,k,v (stride 66, packed pairs); root ----
    for (int idx = tid; idx < NN * 32; idx += NT) {
        const int n = idx >> 5, up = idx & 31;
        const int u = up * 2;
        const float* zr = &s->z[n * 16];
        u64 aq = *(const u64*)&s->g1bq[u];
        u64 ak = *(const u64*)&s->g1bk[u];
        u64 av = *(const u64*)&s->g1bv[u];
#pragma unroll
        for (int j = 0; j < 16; j++) {
            const u64 zj = pk2(zr[j], zr[j]);
            aq = fma2(*(const u64*)&s->WqT[j * 66 + u], zj, aq);
            ak = fma2(*(const u64*)&s->WkT[j * 66 + u], zj, ak);
            av = fma2(*(const u64*)&s->WvT[j * 66 + u], zj, av);
        }
        *(u64*)&s->q[n * 66 + u] = aq;
        *(u64*)&s->k[n * 66 + u] = ak;
        *(u64*)&s->v[n * 66 + u] = av;
    }
    for (int idx = tid; idx < NN * 16; idx += NT) {
        const int n = idx >> 4, o = idx & 15;
        float ac = s->g1bs[o];
#pragma unroll
        for (int j = 0; j < 16; j++) ac += s->WsT[j * 16 + o] * s->z[n * 16 + j];
        s->root1[idx] = ac;
    }
    __syncthreads();

    // ---- S2b: qWe[n,h,j] ----
    for (int idx = tid; idx < NN * 32; idx += NT) {
        const int n = idx >> 5, r = idx & 31;
        const int hh = r >> 3, j = r & 7;
        const float* qr = &s->q[n * 66 + hh * 16];
        float acc = 0.f;
#pragma unroll
        for (int c = 0; c < 16; c++) acc += qr[c] * wef[(hh * 16 + c) * 8 + j];
        s->qwe[idx] = acc;
    }
    __syncthreads();

    // ---- S3a: per-position logits (CSR order; dst broadcast across lanes) ----
    for (int p = tid; p < EE; p += NT) {
        const int pk = s->csr[p];
        const int dst = pk >> 19, src = (pk >> 12) & 0x7F, e = pk & 0xFFF;
        const float4 eA = *(const float4*)(eag + (size_t)e * 8);
        const float4 eB = *(const float4*)(eag + (size_t)e * 8 + 4);
        u64 eap[4];
        eap[0] = pk2(eA.x, eA.y); eap[1] = pk2(eA.z, eA.w);
        eap[2] = pk2(eB.x, eB.y); eap[3] = pk2(eB.z, eB.w);
        const u64* qd2 = (const u64*)&s->q[dst * 66];
        const u64* ks2 = (const u64*)&s->k[src * 66];
        const u64* qw2 = (const u64*)&s->qwe[dst * 32];
#pragma unroll
        for (int hh = 0; hh < 4; hh++) {
            u64 acc = 0ull;
#pragma unroll
            for (int t = 0; t < 8; t++)
                acc = fma2(qd2[hh * 8 + t], ks2[hh * 8 + t], acc);
            acc = fma2(qw2[hh * 4 + 0], eap[0], acc);
            acc = fma2(qw2[hh * 4 + 1], eap[1], acc);
            acc = fma2(qw2[hh * 4 + 2], eap[2], acc);
            acc = fma2(qw2[hh * 4 + 3], eap[3], acc);
            s->expl[p * 4 + hh] = fexp(hadd2(acc) * 0.25f);
        }
    }
    __syncthreads();

    // ---- S3b-1: wea + denominators (expl sequential by p) ----
    for (int idx = tid; idx < NN * 8; idx += NT) {
        const int n = idx >> 3, r = idx & 7;
        const int hh = r >> 1, half = r & 1;
        const int p0 = s->rowptr[n], p1 = s->rowptr[n + 1];
        float4 acc = make_float4(0.f, 0.f, 0.f, 0.f);
        float d = 0.f;
#pragma unroll 4
        for (int p = p0; p < p1; p++) {
            const int e = s->csr[p] & 0xFFF;
            const float ex = s->expl[p * 4 + hh];
            const float4 ea4 = *(const float4*)(eag + (size_t)e * 8 + half * 4);
            acc.x += ex * ea4.x; acc.y += ex * ea4.y; acc.z += ex * ea4.z; acc.w += ex * ea4.w;
            d += ex;
        }
        *(float4*)&s->qwe[n * 32 + hh * 8 + half * 4] = acc;
        if (half == 0) s->denom1[n * 4 + hh] = d;
    }
    __syncthreads();

    // ---- S3b-3: acc1[n,u] = sum_p expl*v[src,u] + We.wea ----
    for (int idx = tid; idx < NN * 16; idx += NT) {
        const int n = idx >> 4, g = idx & 15;
        const int u0 = g * 4, hh = g >> 2;
        const int p0 = s->rowptr[n], p1 = s->rowptr[n + 1];
        u64 acc01 = 0ull, acc23 = 0ull;
#pragma unroll 4
        for (int p = p0; p < p1; p++) {
            const int pk = s->csr[p];
            const int src = (pk >> 12) & 0x7F;
            const float ex = s->expl[p * 4 + hh];
            const u64 ex2 = pk2(ex, ex);
            acc01 = fma2(*(const u64*)&s->v[src * 66 + u0], ex2, acc01);
            acc23 = fma2(*(const u64*)&s->v[src * 66 + u0 + 2], ex2, acc23);
        }
        float a0, a1, a2, a3;
        unpk2(acc01, a0, a1);
        unpk2(acc23, a2, a3);
        const float* we_n = &s->qwe[n * 32 + hh * 8];
        float add[4];
#pragma unroll
        for (int t = 0; t < 4; t++) {
            const int u = u0 + t;
            float w = 0.f;
#pragma unroll
            for (int j = 0; j < 8; j++) w += wef[u * 8 + j] * we_n[j];
            add[t] = w;
        }
        float4 outv = make_float4(a0 + add[0], a1 + add[1], a2 + add[2], a3 + add[3]);
        *(float4*)&s->acc1[n * 64 + u0] = outv;
    }
    __syncthreads();

    // ---- S4: a = mean_h(acc/denom) + root (alias over expl, stride 18) ----
    for (int idx = tid; idx < NN * 16; idx += NT) {
        const int n = idx >> 4, c = idx & 15;
        float sum = 0.f;
#pragma unroll
        for (int hh = 0; hh < 4; hh++)
            sum += s->acc1[n * 64 + hh * 16 + c] / (s->denom1[n * 4 + hh] + 1e-16f);
        aarr[n * 18 + c] = 0.25f * sum + s->root1[idx];
    }
    __syncthreads();

    const int ag = s->agent;

    // ---- S5: g2 agent q and root ----
    {
        const float* ar = &aarr[ag * 18];
        for (int u = tid; u < 128; u += NT) {
            float ac = A.g2bq[u];
#pragma unroll
            for (int j = 0; j < 16; j++) ac += A.g2Wq[u * 16 + j] * ar[j];
            s->qa[u] = ac;
        }
        for (int c = tid; c < 32; c += NT) {
            float ac = A.g2bs[c];
#pragma unroll
            for (int j = 0; j < 16; j++) ac += A.g2Ws[c * 16 + j] * ar[j];
            s->roota[c] = ac;
        }
    }
    __syncthreads();

    // ---- S6: g2 edges with dst == agent ----
    {
        const int p0 = s->rowptr[ag];
        const int m = s->rowptr[ag + 1] - p0;
        for (int w = tid; w < m * 4; w += NT) {
            const int pe = w >> 2, hh = w & 3;
            const int pk = s->csr[p0 + pe];
            const int e = pk & 0xFFF, src = (pk >> 12) & 0x7F;
            const float* eap = eag + (size_t)e * 8;
            float ear[8];
#pragma unroll
            for (int j = 0; j < 8; j++) ear[j] = eap[j];
            const float* ar = &aarr[src * 18];
            float ev[32];
            float lg = 0.f;
#pragma unroll
            for (int c = 0; c < 32; c++) {
                const int u = hh * 32 + c;
                float evv = 0.f;
#pragma unroll
                for (int j = 0; j < 8; j++) evv += A.g2We[u * 8 + j] * ear[j];
                ev[c] = evv;
                float kk = A.g2bk[u];
#pragma unroll
                for (int j = 0; j < 16; j++) kk += A.g2Wk[u * 16 + j] * ar[j];
                lg += s->qa[u] * (kk + evv);
            }
            const float ex = fexp(lg * 0.17677669529663689f);
            atomicAdd(&s->denom2[hh], ex);
#pragma unroll
            for (int c = 0; c < 32; c++) {
                const int u = hh * 32 + c;
                float vv = A.g2bv[u];
#pragma unroll
                for (int j = 0; j < 16; j++) vv += A.g2Wv[u * 16 + j] * ar[j];
                atomicAdd(&s->acc2[u], ex * (vv + ev[c]));
            }
        }
    }
    __syncthreads();

    // ---- S7: output at agent node ----
    for (int c = tid; c < 32; c += NT) {
        float sum = 0.f;
#pragma unroll
        for (int hh = 0; hh < 4; hh++)
            sum += s->acc2[hh * 32 + c] / (s->denom2[hh] + 1e-16f);
        A.out[b * 32 + c] = fmaxf(0.25f * sum + s->roota[c], 0.f);
    }
}

extern "C" void kernel_launch(void* const* d_in, const int* in_sizes, int n_in,
                              void* d_out, int out_size) {
    Args A;
    A.nodes = (const float*)d_in[0];
    A.ei    = (const int*)  d_in[1];
    A.ea    = (const float*)d_in[2];
    A.agent = (const int*)  d_in[3];
    A.emb   = (const float*)d_in[4];
    A.W1 = (const float*)d_in[5];  A.b1 = (const float*)d_in[6];
    A.W2 = (const float*)d_in[7];  A.b2 = (const float*)d_in[8];
    A.W3 = (const float*)d_in[9];  A.b3 = (const float*)d_in[10];
    A.lng = (const float*)d_in[11]; A.lnb = (const float*)d_in[12];
    A.g1Wq = (const float*)d_in[13]; A.g1bq = (const float*)d_in[14];
    A.g1Wk = (const float*)d_in[15]; A.g1bk = (const float*)d_in[16];
    A.g1Wv = (const float*)d_in[17]; A.g1bv = (const float*)d_in[18];
    A.g1We = (const float*)d_in[19];
    A.g1Ws = (const float*)d_in[20]; A.g1bs = (const float*)d_in[21];
    A.g2Wq = (const float*)d_in[22]; A.g2bq = (const float*)d_in[23];
    A.g2Wk = (const float*)d_in[24]; A.g2bk = (const float*)d_in[25];
    A.g2Wv = (const float*)d_in[26]; A.g2bv = (const float*)d_in[27];
    A.g2We = (const float*)d_in[28];
    A.g2Ws = (const float*)d_in[29]; A.g2bs = (const float*)d_in[30];
    A.out = (float*)d_out;

    cudaFuncSetAttribute(gnn_kernel, cudaFuncAttributeMaxDynamicSharedMemorySize,
                         (int)sizeof(SM));
    gnn_kernel<<<BB, NT, sizeof(SM)>>>(A);
}

// round 12
// speedup vs baseline: 1.2008x; 1.0097x over previous
#include <cuda_runtime.h>

#define BB 128
#define NN 100
#define EE 3200
#define NT 768

typedef unsigned long long u64;

struct Args {
    const float* nodes;
    const int*   ei;
    const float* ea;
    const int*   agent;
    const float* emb;
    const float *W1,*b1,*W2,*b2,*W3,*b3,*lng,*lnb;
    const float *g1Wq,*g1bq,*g1Wk,*g1bk,*g1Wv,*g1bv,*g1We,*g1Ws,*g1bs;
    const float *g2Wq,*g2bq,*g2Wk,*g2bk,*g2Wv,*g2bv,*g2We,*g2Ws,*g2bs;
    float* out;
};

__device__ float g_hbuf[(size_t)BB * EE * 16];   // per-edge MLP outputs, by edge id e

__device__ __forceinline__ u64 fma2(u64 a, u64 b, u64 c) {
    u64 d; asm("fma.rn.f32x2 %0,%1,%2,%3;" : "=l"(d) : "l"(a), "l"(b), "l"(c)); return d;
}
__device__ __forceinline__ u64 pk2(float lo, float hi) {
    u64 r; asm("mov.b64 %0,{%1,%2};" : "=l"(r) : "f"(lo), "f"(hi)); return r;
}
__device__ __forceinline__ float hadd2(u64 v) {
    float lo, hi; asm("mov.b64 {%0,%1},%2;" : "=f"(lo), "=f"(hi) : "l"(v)); return lo + hi;
}
__device__ __forceinline__ void unpk2(u64 v, float& lo, float& hi) {
    asm("mov.b64 {%0,%1},%2;" : "=f"(lo), "=f"(hi) : "l"(v));
}

__device__ __forceinline__ float fexp(float x) {
    float t = x * 1.4426950408889634f;
    float n = rintf(t);
    float f = t - n;
    float p = 1.3333558e-3f;
    p = p * f + 9.6181291e-3f;
    p = p * f + 5.5504109e-2f;
    p = p * f + 2.4022651e-1f;
    p = p * f + 6.9314718e-1f;
    p = p * f + 1.0f;
    int ni = (int)n;
    ni = max(-126, min(127, ni));
    return p * __int_as_float((ni + 127) << 23);
}

struct SM {
    float z[NN * 16];
    float q[NN * 66], k[NN * 66], v[NN * 66];   // stride 66: 16 bank residues, 8B aligned
    float root1[NN * 16];
    float acc1[NN * 64];
    float denom1[NN * 4];
    float expl[EE * 4];        // indexed by CSR position p; [alias] a[NN*18] after S3b
    float qwe[NN * 32];        // qWe in S2b..S3a; wea after (disjoint lifetimes)
    float4 W1v[48];  float b1[16];
    float4 W2v[64];  float b2[16];
    float4 W3v[64];  float b3[16];
    float lng[16], lnb[16], emb[20];
    float WqT[16 * 66], WkT[16 * 66], WvT[16 * 66];
    float g1bq[64], g1bk[64], g1bv[64];
    float4 Wev[128];
    float WsT[256];
    float g1bs[16];
    float qa[128], roota[32], denom2[4], acc2[128];
    int csr[EE];               // (dst<<19)|(src<<12)|e
    int rowptr[NN + 1];
    int cursor[NN], deg[NN], etype[NN];
    int agent;
};
static_assert(sizeof(SM) <= 232448, "smem over limit");

__device__ __forceinline__ void cpf(float* d, const float* s, int n, int tid) {
    for (int i = tid; i < n; i += NT) d[i] = s[i];
}

__device__ __forceinline__ void ln16(float* h, const float* g, const float* bb) {
    float m = 0.f;
#pragma unroll
    for (int i = 0; i < 16; i++) m += h[i];
    m *= (1.f / 16.f);
    float var = 0.f;
#pragma unroll
    for (int i = 0; i < 16; i++) { float d = h[i] - m; var += d * d; }
    var *= (1.f / 16.f);
    float inv = rsqrtf(var + 1e-5f);
#pragma unroll
    for (int i = 0; i < 16; i++) h[i] = (h[i] - m) * inv * g[i] + bb[i];
}

__global__ void __launch_bounds__(NT, 1) gnn_kernel(Args A) {
    extern __shared__ unsigned char smraw[];
    SM* s = reinterpret_cast<SM*>(smraw);
    const int b = blockIdx.x;
    const int tid = threadIdx.x;
    const int* ei = A.ei + b * 2 * EE;
    const float* eag = A.ea + (size_t)b * EE * 8;
    const float* wef = (const float*)s->Wev;
    float* aarr = s->expl;   // alias: a[n*18+c], valid after S3b

    // ---- S0 ----
    cpf((float*)s->W1v, A.W1, 192, tid);  cpf(s->b1, A.b1, 16, tid);
    cpf((float*)s->W2v, A.W2, 256, tid);  cpf(s->b2, A.b2, 16, tid);
    cpf((float*)s->W3v, A.W3, 256, tid);  cpf(s->b3, A.b3, 16, tid);
    cpf(s->lng, A.lng, 16, tid); cpf(s->lnb, A.lnb, 16, tid);
    cpf(s->emb, A.emb, 20, tid);
    cpf((float*)s->Wev, A.g1We, 512, tid);
    cpf(s->g1bq, A.g1bq, 64, tid); cpf(s->g1bk, A.g1bk, 64, tid);
    cpf(s->g1bv, A.g1bv, 64, tid); cpf(s->g1bs, A.g1bs, 16, tid);
    for (int i = tid; i < 1024; i += NT) {
        const int u = i >> 4, j = i & 15;
        s->WqT[j * 66 + u] = A.g1Wq[i];
        s->WkT[j * 66 + u] = A.g1Wk[i];
        s->WvT[j * 66 + u] = A.g1Wv[i];
    }
    for (int i = tid; i < 256; i += NT) {
        const int o = i >> 4, j = i & 15;
        s->WsT[j * 16 + o] = A.g1Ws[i];
    }
    for (int i = tid; i < NN; i += NT) {
        s->etype[i] = (int)A.nodes[b * NN + i];
        s->deg[i] = 0;
    }
    for (int i = tid; i < 4; i += NT) s->denom2[i] = 0.f;
    for (int i = tid; i < 128; i += NT) s->acc2[i] = 0.f;
    if (tid == 0) s->agent = A.agent[b];
    __syncthreads();

    // ---- S0b: degree histogram ----
    for (int e = tid; e < EE; e += NT) atomicAdd(&s->deg[ei[EE + e]], 1);
    __syncthreads();

    // ---- S0c: warp-parallel prefix sum ----
    if (tid < 32) {
        int d0[4]; int t = 0;
#pragma unroll
        for (int u = 0; u < 4; u++) {
            const int n = tid * 4 + u;
            d0[u] = (n < NN) ? s->deg[n] : 0;
            t += d0[u];
        }
        int incl = t;
#pragma unroll
        for (int o = 1; o < 32; o <<= 1) {
            const int vv = __shfl_up_sync(0xFFFFFFFFu, incl, o);
            if (tid >= o) incl += vv;
        }
        int run = incl - t;
#pragma unroll
        for (int u = 0; u < 4; u++) {
            const int n = tid * 4 + u;
            if (n < NN) { s->rowptr[n] = run; run += d0[u]; }
        }
        if (tid == 31) s->rowptr[NN] = incl;
    }
    __syncthreads();
    for (int n = tid; n < NN; n += NT) s->cursor[n] = s->rowptr[n];
    __syncthreads();

    // ---- S1a: CSR scatter ((dst<<19)|(src<<12)|e) + per-edge MLP ----
    for (int e = tid; e < EE; e += NT) {
        const int src = ei[e], dst = ei[EE + e];
        const int pos = atomicAdd(&s->cursor[dst], 1);
        s->csr[pos] = (dst << 19) | (src << 12) | e;

        const int t = s->etype[src];
        const float4 xA = *(const float4*)&s->emb[t * 4];
        const float4 xB = *(const float4*)(eag + (size_t)e * 8);
        const float4 xC = *(const float4*)(eag + (size_t)e * 8 + 4);

        u64 xp[6];
        xp[0] = pk2(xA.x, xA.y); xp[1] = pk2(xA.z, xA.w);
        xp[2] = pk2(xB.x, xB.y); xp[3] = pk2(xB.z, xB.w);
        xp[4] = pk2(xC.x, xC.y); xp[5] = pk2(xC.z, xC.w);

        float h[16], h2[16];
#pragma unroll
        for (int o = 0; o < 16; o++) {
            const ulonglong2* wr = reinterpret_cast<const ulonglong2*>(&s->W1v[o * 3]);
            const ulonglong2 wa = wr[0], wb = wr[1], wc = wr[2];
            u64 acc = pk2(s->b1[o], 0.f);
            acc = fma2(wa.x, xp[0], acc); acc = fma2(wa.y, xp[1], acc);
            acc = fma2(wb.x, xp[2], acc); acc = fma2(wb.y, xp[3], acc);
            acc = fma2(wc.x, xp[4], acc); acc = fma2(wc.y, xp[5], acc);
            h[o] = fmaxf(hadd2(acc), 0.f);
        }
        ln16(h, s->lng, s->lnb);
        u64 hp2[8];
#pragma unroll
        for (int i = 0; i < 8; i++) hp2[i] = pk2(h[i * 2], h[i * 2 + 1]);
#pragma unroll
        for (int o = 0; o < 16; o++) {
            const ulonglong2* wr = reinterpret_cast<const ulonglong2*>(&s->W2v[o * 4]);
            const ulonglong2 w0 = wr[0], w1 = wr[1], w2 = wr[2], w3 = wr[3];
            u64 acc = pk2(s->b2[o], 0.f);
            acc = fma2(w0.x, hp2[0], acc); acc = fma2(w0.y, hp2[1], acc);
            acc = fma2(w1.x, hp2[2], acc); acc = fma2(w1.y, hp2[3], acc);
            acc = fma2(w2.x, hp2[4], acc); acc = fma2(w2.y, hp2[5], acc);
            acc = fma2(w3.x, hp2[6], acc); acc = fma2(w3.y, hp2[7], acc);
            h2[o] = fmaxf(hadd2(acc), 0.f);
        }
        ln16(h2, s->lng, s->lnb);
#pragma unroll
        for (int i = 0; i < 8; i++) hp2[i] = pk2(h2[i * 2], h2[i * 2 + 1]);
#pragma unroll
        for (int o = 0; o < 16; o++) {
            const ulonglong2* wr = reinterpret_cast<const ulonglong2*>(&s->W3v[o * 4]);
            const ulonglong2 w0 = wr[0], w1 = wr[1], w2 = wr[2], w3 = wr[3];
            u64 acc = pk2(s->b3[o], 0.f);
            acc = fma2(w0.x, hp2[0], acc); acc = fma2(w0.y, hp2[1], acc);
            acc = fma2(w1.x, hp2[2], acc); acc = fma2(w1.y, hp2[3], acc);
            acc = fma2(w2.x, hp2[4], acc); acc = fma2(w2.y, hp2[5], acc);
            acc = fma2(w3.x, hp2[6], acc); acc = fma2(w3.y, hp2[7], acc);
            h[o] = fmaxf(hadd2(acc), 0.f);
        }
        ln16(h, s->lng, s->lnb);

        float4* hp = (float4*)&g_hbuf[((size_t)b * EE + e) * 16];
        hp[0] = make_float4(h[0], h[1], h[2], h[3]);
        hp[1] = make_float4(h[4], h[5], h[6], h[7]);
        hp[2] = make_float4(h[8], h[9], h[10], h[11]);
        hp[3] = make_float4(h[12], h[13], h[14], h[15]);
    }
    __syncthreads();

    // ---- S1b: z = segment_sum(h, dst) — parity-split pairs + shfl combine ----
    for (int idx = tid; idx < NN * 8; idx += NT) {
        const int par = idx & 1, g = (idx >> 1) & 3, n = idx >> 3;
        const int p1 = s->rowptr[n + 1];
        float4 acc = make_float4(0.f, 0.f, 0.f, 0.f);
        for (int p = s->rowptr[n] + par; p < p1; p += 2) {
            const int e = s->csr[p] & 0xFFF;
            const float4 hv = *(const float4*)&g_hbuf[((size_t)b * EE + e) * 16 + g * 4];
            acc.x += hv.x; acc.y += hv.y; acc.z += hv.z; acc.w += hv.w;
        }
        acc.x += __shfl_xor_sync(0xFFFFFFFFu, acc.x, 1);
        acc.y += __shfl_xor_sync(0xFFFFFFFFu, acc.y, 1);
        acc.z += __shfl_xor_sync(0xFFFFFFFFu, acc.z, 1);
        acc.w += __shfl_xor_sync(0xFFFFFFFFu, acc.w, 1);
        if (!par) *(float4*)&s->z[n * 16 + g * 4] = acc;
    }
    __syncthreads();

    // ---- S2: q,k,v (stride 66, packed pairs); root ----
    for (int idx = tid; idx < NN * 32; idx += NT) {
        const int n = idx >> 5, up = idx & 31;
        const int u = up * 2;
        const float* zr = &s->z[n * 16];
        u64 aq = *(const u64*)&s->g1bq[u];
        u64 ak = *(const u64*)&s->g1bk[u];
        u64 av = *(const u64*)&s->g1bv[u];
#pragma unroll
        for (int j = 0; j < 16; j++) {
            const u64 zj = pk2(zr[j], zr[j]);
            aq = fma2(*(const u64*)&s->WqT[j * 66 + u], zj, aq);
            ak = fma2(*(const u64*)&s->WkT[j * 66 + u], zj, ak);
            av = fma2(*(const u64*)&s->WvT[j * 66 + u], zj, av);
        }
        *(u64*)&s->q[n * 66 + u] = aq;
        *(u64*)&s->k[n * 66 + u] = ak;
        *(u64*)&s->v[n * 66 + u] = av;
    }
    for (int idx = tid; idx < NN * 16; idx += NT) {
        const int n = idx >> 4, o = idx & 15;
        float ac = s->g1bs[o];
#pragma unroll
        for (int j = 0; j < 16; j++) ac += s->WsT[j * 16 + o] * s->z[n * 16 + j];
        s->root1[idx] = ac;
    }
    __syncthreads();

    // ---- S2b: qWe[n,h,j] ----
    for (int idx = tid; idx < NN * 32; idx += NT) {
        const int n = idx >> 5, r = idx & 31;
        const int hh = r >> 3, j = r & 7;
        const float* qr = &s->q[n * 66 + hh * 16];
        float acc = 0.f;
#pragma unroll
        for (int c = 0; c < 16; c++) acc += qr[c] * wef[(hh * 16 + c) * 8 + j];
        s->qwe[idx] = acc;
    }
    __syncthreads();

    // ---- S3a: per-position logits (CSR order; dst broadcast across lanes) ----
    for (int p = tid; p < EE; p += NT) {
        const int pk = s->csr[p];
        const int dst = pk >> 19, src = (pk >> 12) & 0x7F, e = pk & 0xFFF;
        const float4 eA = *(const float4*)(eag + (size_t)e * 8);
        const float4 eB = *(const float4*)(eag + (size_t)e * 8 + 4);
        u64 eap[4];
        eap[0] = pk2(eA.x, eA.y); eap[1] = pk2(eA.z, eA.w);
        eap[2] = pk2(eB.x, eB.y); eap[3] = pk2(eB.z, eB.w);
        const u64* qd2 = (const u64*)&s->q[dst * 66];
        const u64* ks2 = (const u64*)&s->k[src * 66];
        const u64* qw2 = (const u64*)&s->qwe[dst * 32];
#pragma unroll
        for (int hh = 0; hh < 4; hh++) {
            u64 acc = 0ull;
#pragma unroll
            for (int t = 0; t < 8; t++)
                acc = fma2(qd2[hh * 8 + t], ks2[hh * 8 + t], acc);
            acc = fma2(qw2[hh * 4 + 0], eap[0], acc);
            acc = fma2(qw2[hh * 4 + 1], eap[1], acc);
            acc = fma2(qw2[hh * 4 + 2], eap[2], acc);
            acc = fma2(qw2[hh * 4 + 3], eap[3], acc);
            s->expl[p * 4 + hh] = fexp(hadd2(acc) * 0.25f);
        }
    }
    __syncthreads();

    // ---- S3b-1: wea + denominators — parity-split + shfl combine ----
    for (int idx = tid; idx < NN * 16; idx += NT) {
        const int par = idx & 1, half = (idx >> 1) & 1, hh = (idx >> 2) & 3, n = idx >> 4;
        const int p1 = s->rowptr[n + 1];
        float4 acc = make_float4(0.f, 0.f, 0.f, 0.f);
        float d = 0.f;
        for (int p = s->rowptr[n] + par; p < p1; p += 2) {
            const int e = s->csr[p] & 0xFFF;
            const float ex = s->expl[p * 4 + hh];
            const float4 ea4 = *(const float4*)(eag + (size_t)e * 8 + half * 4);
            acc.x += ex * ea4.x; acc.y += ex * ea4.y; acc.z += ex * ea4.z; acc.w += ex * ea4.w;
            d += ex;
        }
        acc.x += __shfl_xor_sync(0xFFFFFFFFu, acc.x, 1);
        acc.y += __shfl_xor_sync(0xFFFFFFFFu, acc.y, 1);
        acc.z += __shfl_xor_sync(0xFFFFFFFFu, acc.z, 1);
        acc.w += __shfl_xor_sync(0xFFFFFFFFu, acc.w, 1);
        d += __shfl_xor_sync(0xFFFFFFFFu, d, 1);
        if (!par) {
            *(float4*)&s->qwe[n * 32 + hh * 8 + half * 4] = acc;
            if (half == 0) s->denom1[n * 4 + hh] = d;
        }
    }
    __syncthreads();

    // ---- S3b-3: acc1 — parity-split + shfl combine ----
    for (int idx = tid; idx < NN * 32; idx += NT) {
        const int par = idx & 1, g = (idx >> 1) & 15, n = idx >> 5;
        const int u0 = g * 4, hh = g >> 2;
        const int p1 = s->rowptr[n + 1];
        u64 acc01 = 0ull, acc23 = 0ull;
        for (int p = s->rowptr[n] + par; p < p1; p += 2) {
            const int pk = s->csr[p];
            const int src = (pk >> 12) & 0x7F;
            const float ex = s->expl[p * 4 + hh];
            const u64 ex2 = pk2(ex, ex);
            acc01 = fma2(*(const u64*)&s->v[src * 66 + u0], ex2, acc01);
            acc23 = fma2(*(const u64*)&s->v[src * 66 + u0 + 2], ex2, acc23);
        }
        float a0, a1, a2, a3;
        unpk2(acc01, a0, a1);
        unpk2(acc23, a2, a3);
        a0 += __shfl_xor_sync(0xFFFFFFFFu, a0, 1);
        a1 += __shfl_xor_sync(0xFFFFFFFFu, a1, 1);
        a2 += __shfl_xor_sync(0xFFFFFFFFu, a2, 1);
        a3 += __shfl_xor_sync(0xFFFFFFFFu, a3, 1);
        if (!par) {
            const float* we_n = &s->qwe[n * 32 + hh * 8];
            float add[4];
#pragma unroll
            for (int t = 0; t < 4; t++) {
                const int u = u0 + t;
                float w = 0.f;
#pragma unroll
                for (int j = 0; j < 8; j++) w += wef[u * 8 + j] * we_n[j];
                add[t] = w;
            }
            float4 outv = make_float4(a0 + add[0], a1 + add[1], a2 + add[2], a3 + add[3]);
            *(float4*)&s->acc1[n * 64 + u0] = outv;
        }
    }
    __syncthreads();

    // ---- S4: a = mean_h(acc/denom) + root (alias over expl, stride 18) ----
    for (int idx = tid; idx < NN * 16; idx += NT) {
        const int n = idx >> 4, c = idx & 15;
        float sum = 0.f;
#pragma unroll
        for (int hh = 0; hh < 4; hh++)
            sum += s->acc1[n * 64 + hh * 16 + c] / (s->denom1[n * 4 + hh] + 1e-16f);
        aarr[n * 18 + c] = 0.25f * sum + s->root1[idx];
    }
    __syncthreads();

    const int ag = s->agent;

    // ---- S5: g2 agent q and root ----
    {
        const float* ar = &aarr[ag * 18];
        for (int u = tid; u < 128; u += NT) {
            float ac = A.g2bq[u];
#pragma unroll
            for (int j = 0; j < 16; j++) ac += A.g2Wq[u * 16 + j] * ar[j];
            s->qa[u] = ac;
        }
        for (int c = tid; c < 32; c += NT) {
            float ac = A.g2bs[c];
#pragma unroll
            for (int j = 0; j < 16; j++) ac += A.g2Ws[c * 16 + j] * ar[j];
            s->roota[c] = ac;
        }
    }
    __syncthreads();

    // ---- S6: g2 edges with dst == agent ----
    {
        const int p0 = s->rowptr[ag];
        const int m = s->rowptr[ag + 1] - p0;
        for (int w = tid; w < m * 4; w += NT) {
            const int pe = w >> 2, hh = w & 3;
            const int pk = s->csr[p0 + pe];
            const int e = pk & 0xFFF, src = (pk >> 12) & 0x7F;
            const float* eap = eag + (size_t)e * 8;
            float ear[8];
#pragma unroll
            for (int j = 0; j < 8; j++) ear[j] = eap[j];
            const float* ar = &aarr[src * 18];
            float ev[32];
            float lg = 0.f;
#pragma unroll
            for (int c = 0; c < 32; c++) {
                const int u = hh * 32 + c;
                float evv = 0.f;
#pragma unroll
                for (int j = 0; j < 8; j++) evv += A.g2We[u * 8 + j] * ear[j];
                ev[c] = evv;
                float kk = A.g2bk[u];
#pragma unroll
                for (int j = 0; j < 16; j++) kk += A.g2Wk[u * 16 + j] * ar[j];
                lg += s->qa[u] * (kk + evv);
            }
            const float ex = fexp(lg * 0.17677669529663689f);
            atomicAdd(&s->denom2[hh], ex);
#pragma unroll
            for (int c = 0; c < 32; c++) {
                const int u = hh * 32 + c;
                float vv = A.g2bv[u];
#pragma unroll
                for (int j = 0; j < 16; j++) vv += A.g2Wv[u * 16 + j] * ar[j];
                atomicAdd(&s->acc2[u], ex * (vv + ev[c]));
            }
        }
    }
    __syncthreads();

    // ---- S7: output at agent node ----
    for (int c = tid; c < 32; c += NT) {
        float sum = 0.f;
#pragma unroll
        for (int hh = 0; hh < 4; hh++)
            sum += s->acc2[hh * 32 + c] / (s->denom2[hh] + 1e-16f);
        A.out[b * 32 + c] = fmaxf(0.25f * sum + s->roota[c], 0.f);
    }
}

extern "C" void kernel_launch(void* const* d_in, const int* in_sizes, int n_in,
                              void* d_out, int out_size) {
    Args A;
    A.nodes = (const float*)d_in[0];
    A.ei    = (const int*)  d_in[1];
    A.ea    = (const float*)d_in[2];
    A.agent = (const int*)  d_in[3];
    A.emb   = (const float*)d_in[4];
    A.W1 = (const float*)d_in[5];  A.b1 = (const float*)d_in[6];
    A.W2 = (const float*)d_in[7];  A.b2 = (const float*)d_in[8];
    A.W3 = (const float*)d_in[9];  A.b3 = (const float*)d_in[10];
    A.lng = (const float*)d_in[11]; A.lnb = (const float*)d_in[12];
    A.g1Wq = (const float*)d_in[13]; A.g1bq = (const float*)d_in[14];
    A.g1Wk = (const float*)d_in[15]; A.g1bk = (const float*)d_in[16];
    A.g1Wv = (const float*)d_in[17]; A.g1bv = (const float*)d_in[18];
    A.g1We = (const float*)d_in[19];
    A.g1Ws = (const float*)d_in[20]; A.g1bs = (const float*)d_in[21];
    A.g2Wq = (const float*)d_in[22]; A.g2bq = (const float*)d_in[23];
    A.g2Wk = (const float*)d_in[24]; A.g2bk = (const float*)d_in[25];
    A.g2Wv = (const float*)d_in[26]; A.g2bv = (const float*)d_in[27];
    A.g2We = (const float*)d_in[28];
    A.g2Ws = (const float*)d_in[29]; A.g2bs = (const float*)d_in[30];
    A.out = (float*)d_out;

    cudaFuncSetAttribute(gnn_kernel, cudaFuncAttributeMaxDynamicSharedMemorySize,
                         (int)sizeof(SM));
    gnn_kernel<<<BB, NT, sizeof(SM)>>>(A);
}

// round 13
// speedup vs baseline: 1.2065x; 1.0047x over previous
#include <cuda_runtime.h>

#define BB 128
#define NN 100
#define EE 3200
#define NT 768

typedef unsigned long long u64;

struct Args {
    const float* nodes;
    const int*   ei;
    const float* ea;
    const int*   agent;
    const float* emb;
    const float *W1,*b1,*W2,*b2,*W3,*b3,*lng,*lnb;
    const float *g1Wq,*g1bq,*g1Wk,*g1bk,*g1Wv,*g1bv,*g1We,*g1Ws,*g1bs;
    const float *g2Wq,*g2bq,*g2Wk,*g2bk,*g2Wv,*g2bv,*g2We,*g2Ws,*g2bs;
    float* out;
};

// block-private global scratch, indexed by CSR position p (sequential reads)
__device__ float g_hbuf [(size_t)BB * EE * 16];
__device__ float g_eabuf[(size_t)BB * EE * 8];

__device__ __forceinline__ u64 fma2(u64 a, u64 b, u64 c) {
    u64 d; asm("fma.rn.f32x2 %0,%1,%2,%3;" : "=l"(d) : "l"(a), "l"(b), "l"(c)); return d;
}
__device__ __forceinline__ u64 pk2(float lo, float hi) {
    u64 r; asm("mov.b64 %0,{%1,%2};" : "=l"(r) : "f"(lo), "f"(hi)); return r;
}
__device__ __forceinline__ float hadd2(u64 v) {
    float lo, hi; asm("mov.b64 {%0,%1},%2;" : "=f"(lo), "=f"(hi) : "l"(v)); return lo + hi;
}
__device__ __forceinline__ void unpk2(u64 v, float& lo, float& hi) {
    asm("mov.b64 {%0,%1},%2;" : "=f"(lo), "=f"(hi) : "l"(v));
}

__device__ __forceinline__ float fexp(float x) {
    float t = x * 1.4426950408889634f;
    float n = rintf(t);
    float f = t - n;
    float p = 1.3333558e-3f;
    p = p * f + 9.6181291e-3f;
    p = p * f + 5.5504109e-2f;
    p = p * f + 2.4022651e-1f;
    p = p * f + 6.9314718e-1f;
    p = p * f + 1.0f;
    int ni = (int)n;
    ni = max(-126, min(127, ni));
    return p * __int_as_float((ni + 127) << 23);
}

struct SM {
    float z[NN * 16];
    float q[NN * 66], k[NN * 66], v[NN * 66];
    float root1[NN * 16];
    float acc1[NN * 64];
    float denom1[NN * 4];
    float expl[EE * 4];        // by CSR position p; [alias] a[NN*18] after S3b
    float qwe[NN * 32];
    float4 W1v[48];  float b1[16];
    float4 W2v[64];  float b2[16];
    float4 W3v[64];  float b3[16];
    float lng[16], lnb[16], emb[20];
    float WqT[16 * 66], WkT[16 * 66], WvT[16 * 66];
    float g1bq[64], g1bk[64], g1bv[64];
    float4 Wev[128];
    float WsT[256];
    float g1bs[16];
    float qa[128], roota[32], denom2[4], acc2[128];
    int csr[EE];               // (dst<<19)|(src<<12)|e
    int rowptr[NN + 1];
    int cursor[NN], deg[NN], etype[NN];
    int agent;
};
static_assert(sizeof(SM) <= 232448, "smem over limit");

__device__ __forceinline__ void cpf(float* d, const float* s, int n, int tid) {
    for (int i = tid; i < n; i += NT) d[i] = s[i];
}

__device__ __forceinline__ void ln16(float* h, const float* g, const float* bb) {
    float m = 0.f;
#pragma unroll
    for (int i = 0; i < 16; i++) m += h[i];
    m *= (1.f / 16.f);
    float var = 0.f;
#pragma unroll
    for (int i = 0; i < 16; i++) { float d = h[i] - m; var += d * d; }
    var *= (1.f / 16.f);
    float inv = rsqrtf(var + 1e-5f);
#pragma unroll
    for (int i = 0; i < 16; i++) h[i] = (h[i] - m) * inv * g[i] + bb[i];
}

__global__ void __launch_bounds__(NT, 1) gnn_kernel(Args A) {
    extern __shared__ unsigned char smraw[];
    SM* s = reinterpret_cast<SM*>(smraw);
    const int b = blockIdx.x;
    const int tid = threadIdx.x;
    const int* ei = A.ei + b * 2 * EE;
    const float* eag = A.ea + (size_t)b * EE * 8;
    const float* wef = (const float*)s->Wev;
    float* aarr = s->expl;   // alias: a[n*18+c], valid after S3b
    float* hpos = g_hbuf + (size_t)b * EE * 16;
    float* epos = g_eabuf + (size_t)b * EE * 8;

    // ---- S0 ----
    cpf((float*)s->W1v, A.W1, 192, tid);  cpf(s->b1, A.b1, 16, tid);
    cpf((float*)s->W2v, A.W2, 256, tid);  cpf(s->b2, A.b2, 16, tid);
    cpf((float*)s->W3v, A.W3, 256, tid);  cpf(s->b3, A.b3, 16, tid);
    cpf(s->lng, A.lng, 16, tid); cpf(s->lnb, A.lnb, 16, tid);
    cpf(s->emb, A.emb, 20, tid);
    cpf((float*)s->Wev, A.g1We, 512, tid);
    cpf(s->g1bq, A.g1bq, 64, tid); cpf(s->g1bk, A.g1bk, 64, tid);
    cpf(s->g1bv, A.g1bv, 64, tid); cpf(s->g1bs, A.g1bs, 16, tid);
    for (int i = tid; i < 1024; i += NT) {
        const int u = i >> 4, j = i & 15;
        s->WqT[j * 66 + u] = A.g1Wq[i];
        s->WkT[j * 66 + u] = A.g1Wk[i];
        s->WvT[j * 66 + u] = A.g1Wv[i];
    }
    for (int i = tid; i < 256; i += NT) {
        const int o = i >> 4, j = i & 15;
        s->WsT[j * 16 + o] = A.g1Ws[i];
    }
    for (int i = tid; i < NN; i += NT) {
        s->etype[i] = (int)A.nodes[b * NN + i];
        s->deg[i] = 0;
    }
    for (int i = tid; i < 4; i += NT) s->denom2[i] = 0.f;
    for (int i = tid; i < 128; i += NT) s->acc2[i] = 0.f;
    if (tid == 0) s->agent = A.agent[b];
    __syncthreads();

    // ---- S0b: degree histogram ----
    for (int e = tid; e < EE; e += NT) atomicAdd(&s->deg[ei[EE + e]], 1);
    __syncthreads();

    // ---- S0c: warp-parallel prefix sum ----
    if (tid < 32) {
        int d0[4]; int t = 0;
#pragma unroll
        for (int u = 0; u < 4; u++) {
            const int n = tid * 4 + u;
            d0[u] = (n < NN) ? s->deg[n] : 0;
            t += d0[u];
        }
        int incl = t;
#pragma unroll
        for (int o = 1; o < 32; o <<= 1) {
            const int vv = __shfl_up_sync(0xFFFFFFFFu, incl, o);
            if (tid >= o) incl += vv;
        }
        int run = incl - t;
#pragma unroll
        for (int u = 0; u < 4; u++) {
            const int n = tid * 4 + u;
            if (n < NN) { s->rowptr[n] = run; run += d0[u]; }
        }
        if (tid == 31) s->rowptr[NN] = incl;
    }
    __syncthreads();
    for (int n = tid; n < NN; n += NT) s->cursor[n] = s->rowptr[n];
    __syncthreads();

    // ---- S1a: CSR scatter + per-edge MLP; h and ea stored BY POSITION ----
    for (int e = tid; e < EE; e += NT) {
        const int src = ei[e], dst = ei[EE + e];
        const int pos = atomicAdd(&s->cursor[dst], 1);
        s->csr[pos] = (dst << 19) | (src << 12) | e;

        const int t = s->etype[src];
        const float4 xA = *(const float4*)&s->emb[t * 4];
        const float4 xB = *(const float4*)(eag + (size_t)e * 8);
        const float4 xC = *(const float4*)(eag + (size_t)e * 8 + 4);

        // position-ordered ea mirror
        float4* ep = (float4*)&epos[(size_t)pos * 8];
        ep[0] = xB; ep[1] = xC;

        u64 xp[6];
        xp[0] = pk2(xA.x, xA.y); xp[1] = pk2(xA.z, xA.w);
        xp[2] = pk2(xB.x, xB.y); xp[3] = pk2(xB.z, xB.w);
        xp[4] = pk2(xC.x, xC.y); xp[5] = pk2(xC.z, xC.w);

        float h[16], h2[16];
#pragma unroll
        for (int o = 0; o < 16; o++) {
            const ulonglong2* wr = reinterpret_cast<const ulonglong2*>(&s->W1v[o * 3]);
            const ulonglong2 wa = wr[0], wb = wr[1], wc = wr[2];
            u64 acc = pk2(s->b1[o], 0.f);
            acc = fma2(wa.x, xp[0], acc); acc = fma2(wa.y, xp[1], acc);
            acc = fma2(wb.x, xp[2], acc); acc = fma2(wb.y, xp[3], acc);
            acc = fma2(wc.x, xp[4], acc); acc = fma2(wc.y, xp[5], acc);
            h[o] = fmaxf(hadd2(acc), 0.f);
        }
        ln16(h, s->lng, s->lnb);
        u64 hp2[8];
#pragma unroll
        for (int i = 0; i < 8; i++) hp2[i] = pk2(h[i * 2], h[i * 2 + 1]);
#pragma unroll
        for (int o = 0; o < 16; o++) {
            const ulonglong2* wr = reinterpret_cast<const ulonglong2*>(&s->W2v[o * 4]);
            const ulonglong2 w0 = wr[0], w1 = wr[1], w2 = wr[2], w3 = wr[3];
            u64 acc = pk2(s->b2[o], 0.f);
            acc = fma2(w0.x, hp2[0], acc); acc = fma2(w0.y, hp2[1], acc);
            acc = fma2(w1.x, hp2[2], acc); acc = fma2(w1.y, hp2[3], acc);
            acc = fma2(w2.x, hp2[4], acc); acc = fma2(w2.y, hp2[5], acc);
            acc = fma2(w3.x, hp2[6], acc); acc = fma2(w3.y, hp2[7], acc);
            h2[o] = fmaxf(hadd2(acc), 0.f);
        }
        ln16(h2, s->lng, s->lnb);
#pragma unroll
        for (int i = 0; i < 8; i++) hp2[i] = pk2(h2[i * 2], h2[i * 2 + 1]);
#pragma unroll
        for (int o = 0; o < 16; o++) {
            const ulonglong2* wr = reinterpret_cast<const ulonglong2*>(&s->W3v[o * 4]);
            const ulonglong2 w0 = wr[0], w1 = wr[1], w2 = wr[2], w3 = wr[3];
            u64 acc = pk2(s->b3[o], 0.f);
            acc = fma2(w0.x, hp2[0], acc); acc = fma2(w0.y, hp2[1], acc);
            acc = fma2(w1.x, hp2[2], acc); acc = fma2(w1.y, hp2[3], acc);
            acc = fma2(w2.x, hp2[4], acc); acc = fma2(w2.y, hp2[5], acc);
            acc = fma2(w3.x, hp2[6], acc); acc = fma2(w3.y, hp2[7], acc);
            h[o] = fmaxf(hadd2(acc), 0.f);
        }
        ln16(h, s->lng, s->lnb);

        float4* hp = (float4*)&hpos[(size_t)pos * 16];
        hp[0] = make_float4(h[0], h[1], h[2], h[3]);
        hp[1] = make_float4(h[4], h[5], h[6], h[7]);
        hp[2] = make_float4(h[8], h[9], h[10], h[11]);
        hp[3] = make_float4(h[12], h[13], h[14], h[15]);
    }
    __syncthreads();

    // ---- S1b: z gather — SEQUENTIAL reads by position, parity split ----
    for (int idx = tid; idx < NN * 8; idx += NT) {
        const int par = idx & 1, g = (idx >> 1) & 3, n = idx >> 3;
        const int p1 = s->rowptr[n + 1];
        float4 acc = make_float4(0.f, 0.f, 0.f, 0.f);
        for (int p = s->rowptr[n] + par; p < p1; p += 2) {
            const float4 hv = *(const float4*)&hpos[(size_t)p * 16 + g * 4];
            acc.x += hv.x; acc.y += hv.y; acc.z += hv.z; acc.w += hv.w;
        }
        acc.x += __shfl_xor_sync(0xFFFFFFFFu, acc.x, 1);
        acc.y += __shfl_xor_sync(0xFFFFFFFFu, acc.y, 1);
        acc.z += __shfl_xor_sync(0xFFFFFFFFu, acc.z, 1);
        acc.w += __shfl_xor_sync(0xFFFFFFFFu, acc.w, 1);
        if (!par) *(float4*)&s->z[n * 16 + g * 4] = acc;
    }
    __syncthreads();

    // ---- S2: q,k,v (stride 66, packed pairs); root ----
    for (int idx = tid; idx < NN * 32; idx += NT) {
        const int n = idx >> 5, up = idx & 31;
        const int u = up * 2;
        const float* zr = &s->z[n * 16];
        u64 aq = *(const u64*)&s->g1bq[u];
        u64 ak = *(const u64*)&s->g1bk[u];
        u64 av = *(const u64*)&s->g1bv[u];
#pragma unroll
        for (int j = 0; j < 16; j++) {
            const u64 zj = pk2(zr[j], zr[j]);
            aq = fma2(*(const u64*)&s->WqT[j * 66 + u], zj, aq);
            ak = fma2(*(const u64*)&s->WkT[j * 66 + u], zj, ak);
            av = fma2(*(const u64*)&s->WvT[j * 66 + u], zj, av);
        }
        *(u64*)&s->q[n * 66 + u] = aq;
        *(u64*)&s->k[n * 66 + u] = ak;
        *(u64*)&s->v[n * 66 + u] = av;
    }
    for (int idx = tid; idx < NN * 16; idx += NT) {
        const int n = idx >> 4, o = idx & 15;
        float ac = s->g1bs[o];
#pragma unroll
        for (int j = 0; j < 16; j++) ac += s->WsT[j * 16 + o] * s->z[n * 16 + j];
        s->root1[idx] = ac;
    }
    __syncthreads();

    // ---- S2b: qWe[n,h,j] ----
    for (int idx = tid; idx < NN * 32; idx += NT) {
        const int n = idx >> 5, r = idx & 31;
        const int hh = r >> 3, j = r & 7;
        const float* qr = &s->q[n * 66 + hh * 16];
        float acc = 0.f;
#pragma unroll
        for (int c = 0; c < 16; c++) acc += qr[c] * wef[(hh * 16 + c) * 8 + j];
        s->qwe[idx] = acc;
    }
    __syncthreads();

    // ---- S3a: per-position logits; ea read SEQUENTIALLY by position ----
    for (int p = tid; p < EE; p += NT) {
        const int pk = s->csr[p];
        const int dst = pk >> 19, src = (pk >> 12) & 0x7F;
        const float4 eA = *(const float4*)&epos[(size_t)p * 8];
        const float4 eB = *(const float4*)&epos[(size_t)p * 8 + 4];
        u64 eap[4];
        eap[0] = pk2(eA.x, eA.y); eap[1] = pk2(eA.z, eA.w);
        eap[2] = pk2(eB.x, eB.y); eap[3] = pk2(eB.z, eB.w);
        const u64* qd2 = (const u64*)&s->q[dst * 66];
        const u64* ks2 = (const u64*)&s->k[src * 66];
        const u64* qw2 = (const u64*)&s->qwe[dst * 32];
#pragma unroll
        for (int hh = 0; hh < 4; hh++) {
            u64 acc = 0ull;
#pragma unroll
            for (int t = 0; t < 8; t++)
                acc = fma2(qd2[hh * 8 + t], ks2[hh * 8 + t], acc);
            acc = fma2(qw2[hh * 4 + 0], eap[0], acc);
            acc = fma2(qw2[hh * 4 + 1], eap[1], acc);
            acc = fma2(qw2[hh * 4 + 2], eap[2], acc);
            acc = fma2(qw2[hh * 4 + 3], eap[3], acc);
            s->expl[p * 4 + hh] = fexp(hadd2(acc) * 0.25f);
        }
    }
    __syncthreads();

    // ---- S3b-1: wea + denominators — sequential ea, parity split ----
    for (int idx = tid; idx < NN * 16; idx += NT) {
        const int par = idx & 1, half = (idx >> 1) & 1, hh = (idx >> 2) & 3, n = idx >> 4;
        const int p1 = s->rowptr[n + 1];
        float4 acc = make_float4(0.f, 0.f, 0.f, 0.f);
        float d = 0.f;
        for (int p = s->rowptr[n] + par; p < p1; p += 2) {
            const float ex = s->expl[p * 4 + hh];
            const float4 ea4 = *(const float4*)&epos[(size_t)p * 8 + half * 4];
            acc.x += ex * ea4.x; acc.y += ex * ea4.y; acc.z += ex * ea4.z; acc.w += ex * ea4.w;
            d += ex;
        }
        acc.x += __shfl_xor_sync(0xFFFFFFFFu, acc.x, 1);
        acc.y += __shfl_xor_sync(0xFFFFFFFFu, acc.y, 1);
        acc.z += __shfl_xor_sync(0xFFFFFFFFu, acc.z, 1);
        acc.w += __shfl_xor_sync(0xFFFFFFFFu, acc.w, 1);
        d += __shfl_xor_sync(0xFFFFFFFFu, d, 1);
        if (!par) {
            *(float4*)&s->qwe[n * 32 + hh * 8 + half * 4] = acc;
            if (half == 0) s->denom1[n * 4 + hh] = d;
        }
    }
    __syncthreads();

    // ---- S3b-3: acc1 — parity split + shfl combine ----
    for (int idx = tid; idx < NN * 32; idx += NT) {
        const int par = idx & 1, g = (idx >> 1) & 15, n = idx >> 5;
        const int u0 = g * 4, hh = g >> 2;
        const int p1 = s->rowptr[n + 1];
        u64 acc01 = 0ull, acc23 = 0ull;
        for (int p = s->rowptr[n] + par; p < p1; p += 2) {
            const int pk = s->csr[p];
            const int src = (pk >> 12) & 0x7F;
            const float ex = s->expl[p * 4 + hh];
            const u64 ex2 = pk2(ex, ex);
            acc01 = fma2(*(const u64*)&s->v[src * 66 + u0], ex2, acc01);
            acc23 = fma2(*(const u64*)&s->v[src * 66 + u0 + 2], ex2, acc23);
        }
        float a0, a1, a2, a3;
        unpk2(acc01, a0, a1);
        unpk2(acc23, a2, a3);
        a0 += __shfl_xor_sync(0xFFFFFFFFu, a0, 1);
        a1 += __shfl_xor_sync(0xFFFFFFFFu, a1, 1);
        a2 += __shfl_xor_sync(0xFFFFFFFFu, a2, 1);
        a3 += __shfl_xor_sync(0xFFFFFFFFu, a3, 1);
        if (!par) {
            const float* we_n = &s->qwe[n * 32 + hh * 8];
            float add[4];
#pragma unroll
            for (int t = 0; t < 4; t++) {
                const int u = u0 + t;
                float w = 0.f;
#pragma unroll
                for (int j = 0; j < 8; j++) w += wef[u * 8 + j] * we_n[j];
                add[t] = w;
            }
            float4 outv = make_float4(a0 + add[0], a1 + add[1], a2 + add[2], a3 + add[3]);
            *(float4*)&s->acc1[n * 64 + u0] = outv;
        }
    }
    __syncthreads();

    // ---- S4: a = mean_h(acc/denom) + root (alias over expl, stride 18) ----
    for (int idx = tid; idx < NN * 16; idx += NT) {
        const int n = idx >> 4, c = idx & 15;
        float sum = 0.f;
#pragma unroll
        for (int hh = 0; hh < 4; hh++)
            sum += s->acc1[n * 64 + hh * 16 + c] / (s->denom1[n * 4 + hh] + 1e-16f);
        aarr[n * 18 + c] = 0.25f * sum + s->root1[idx];
    }
    __syncthreads();

    const int ag = s->agent;

    // ---- S5: g2 agent q and root ----
    {
        const float* ar = &aarr[ag * 18];
        for (int u = tid; u < 128; u += NT) {
            float ac = A.g2bq[u];
#pragma unroll
            for (int j = 0; j < 16; j++) ac += A.g2Wq[u * 16 + j] * ar[j];
            s->qa[u] = ac;
        }
        for (int c = tid; c < 32; c += NT) {
            float ac = A.g2bs[c];
#pragma unroll
            for (int j = 0; j < 16; j++) ac += A.g2Ws[c * 16 + j] * ar[j];
            s->roota[c] = ac;
        }
    }
    __syncthreads();

    // ---- S6: g2 edges with dst == agent (ea by position) ----
    {
        const int p0 = s->rowptr[ag];
        const int m = s->rowptr[ag + 1] - p0;
        for (int w = tid; w < m * 4; w += NT) {
            const int pe = w >> 2, hh = w & 3;
            const int pk = s->csr[p0 + pe];
            const int src = (pk >> 12) & 0x7F;
            const float* eap = &epos[(size_t)(p0 + pe) * 8];
            float ear[8];
#pragma unroll
            for (int j = 0; j < 8; j++) ear[j] = eap[j];
            const float* ar = &aarr[src * 18];
            float ev[32];
            float lg = 0.f;
#pragma unroll
            for (int c = 0; c < 32; c++) {
                const int u = hh * 32 + c;
                float evv = 0.f;
#pragma unroll
                for (int j = 0; j < 8; j++) evv += A.g2We[u * 8 + j] * ear[j];
                ev[c] = evv;
                float kk = A.g2bk[u];
#pragma unroll
                for (int j = 0; j < 16; j++) kk += A.g2Wk[u * 16 + j] * ar[j];
                lg += s->qa[u] * (kk + evv);
            }
            const float ex = fexp(lg * 0.17677669529663689f);
            atomicAdd(&s->denom2[hh], ex);
#pragma unroll
            for (int c = 0; c < 32; c++) {
                const int u = hh * 32 + c;
                float vv = A.g2bv[u];
#pragma unroll
                for (int j = 0; j < 16; j++) vv += A.g2Wv[u * 16 + j] * ar[j];
                atomicAdd(&s->acc2[u], ex * (vv + ev[c]));
            }
        }
    }
    __syncthreads();

    // ---- S7: output at agent node ----
    for (int c = tid; c < 32; c += NT) {
        float sum = 0.f;
#pragma unroll
        for (int hh = 0; hh < 4; hh++)
            sum += s->acc2[hh * 32 + c] / (s->denom2[hh] + 1e-16f);
        A.out[b * 32 + c] = fmaxf(0.25f * sum + s->roota[c], 0.f);
    }
}

extern "C" void kernel_launch(void* const* d_in, const int* in_sizes, int n_in,
                              void* d_out, int out_size) {
    Args A;
    A.nodes = (const float*)d_in[0];
    A.ei    = (const int*)  d_in[1];
    A.ea    = (const float*)d_in[2];
    A.agent = (const int*)  d_in[3];
    A.emb   = (const float*)d_in[4];
    A.W1 = (const float*)d_in[5];  A.b1 = (const float*)d_in[6];
    A.W2 = (const float*)d_in[7];  A.b2 = (const float*)d_in[8];
    A.W3 = (const float*)d_in[9];  A.b3 = (const float*)d_in[10];
    A.lng = (const float*)d_in[11]; A.lnb = (const float*)d_in[12];
    A.g1Wq = (const float*)d_in[13]; A.g1bq = (const float*)d_in[14];
    A.g1Wk = (const float*)d_in[15]; A.g1bk = (const float*)d_in[16];
    A.g1Wv = (const float*)d_in[17]; A.g1bv = (const float*)d_in[18];
    A.g1We = (const float*)d_in[19];
    A.g1Ws = (const float*)d_in[20]; A.g1bs = (const float*)d_in[21];
    A.g2Wq = (const float*)d_in[22]; A.g2bq = (const float*)d_in[23];
    A.g2Wk = (const float*)d_in[24]; A.g2bk = (const float*)d_in[25];
    A.g2Wv = (const float*)d_in[26]; A.g2bv = (const float*)d_in[27];
    A.g2We = (const float*)d_in[28];
    A.g2Ws = (const float*)d_in[29]; A.g2bs = (const float*)d_in[30];
    A.out = (float*)d_out;

    cudaFuncSetAttribute(gnn_kernel, cudaFuncAttributeMaxDynamicSharedMemorySize,
                         (int)sizeof(SM));
    gnn_kernel<<<BB, NT, sizeof(SM)>>>(A);
}

// round 14
// speedup vs baseline: 1.3236x; 1.0971x over previous
#include <cuda_runtime.h>

#define BB 128
#define NN 100
#define EE 3200
#define NT 768

typedef unsigned long long u64;

struct Args {
    const float* nodes;
    const int*   ei;
    const float* ea;
    const int*   agent;
    const float* emb;
    const float *W1,*b1,*W2,*b2,*W3,*b3,*lng,*lnb;
    const float *g1Wq,*g1bq,*g1Wk,*g1bk,*g1Wv,*g1bv,*g1We,*g1Ws,*g1bs;
    const float *g2Wq,*g2bq,*g2Wk,*g2bk,*g2Wv,*g2bv,*g2We,*g2Ws,*g2bs;
    float* out;
};

// block-private global scratch, indexed by CSR position p (sequential reads)
__device__ float g_hbuf [(size_t)BB * EE * 16];
__device__ float g_eabuf[(size_t)BB * EE * 8];

__device__ __forceinline__ u64 fma2(u64 a, u64 b, u64 c) {
    u64 d; asm("fma.rn.f32x2 %0,%1,%2,%3;" : "=l"(d) : "l"(a), "l"(b), "l"(c)); return d;
}
__device__ __forceinline__ u64 pk2(float lo, float hi) {
    u64 r; asm("mov.b64 %0,{%1,%2};" : "=l"(r) : "f"(lo), "f"(hi)); return r;
}
__device__ __forceinline__ float hadd2(u64 v) {
    float lo, hi; asm("mov.b64 {%0,%1},%2;" : "=f"(lo), "=f"(hi) : "l"(v)); return lo + hi;
}
__device__ __forceinline__ void unpk2(u64 v, float& lo, float& hi) {
    asm("mov.b64 {%0,%1},%2;" : "=f"(lo), "=f"(hi) : "l"(v));
}

__device__ __forceinline__ float fexp(float x) {
    float t = x * 1.4426950408889634f;
    float n = rintf(t);
    float f = t - n;
    float p = 1.3333558e-3f;
    p = p * f + 9.6181291e-3f;
    p = p * f + 5.5504109e-2f;
    p = p * f + 2.4022651e-1f;
    p = p * f + 6.9314718e-1f;
    p = p * f + 1.0f;
    int ni = (int)n;
    ni = max(-126, min(127, ni));
    return p * __int_as_float((ni + 127) << 23);
}

struct SM {
    float z[NN * 16];
    float q[NN * 66], k[NN * 66], v[NN * 66];
    float root1[NN * 16];
    float acc1[NN * 64];
    float denom1[NN * 4];
    float expl[EE * 4];        // by CSR position p; [alias] a[NN*18] after S3b
    float qwe[NN * 32];
    float4 W1v[48];  float b1[16];
    float4 W2v[64];  float b2[16];
    float4 W3v[64];  float b3[16];
    float lng[16], lnb[16], emb[20];
    float WqT[16 * 66], WkT[16 * 66], WvT[16 * 66];
    float g1bq[64], g1bk[64], g1bv[64];
    float4 Wev[128];
    float WsT[256];
    float g1bs[16];
    float qa[128], roota[32], denom2[4], acc2[128];
    int csr[EE];               // (dst<<19)|(src<<12)|e
    int rowptr[NN + 1];
    int cursor[NN], deg[NN], etype[NN];
    int needed[NN], slist[NN];
    int scount, agent;
};
static_assert(sizeof(SM) <= 232448, "smem over limit");

__device__ __forceinline__ void cpf(float* d, const float* s, int n, int tid) {
    for (int i = tid; i < n; i += NT) d[i] = s[i];
}

__device__ __forceinline__ void ln16(float* h, const float* g, const float* bb) {
    float m = 0.f;
#pragma unroll
    for (int i = 0; i < 16; i++) m += h[i];
    m *= (1.f / 16.f);
    float var = 0.f;
#pragma unroll
    for (int i = 0; i < 16; i++) { float d = h[i] - m; var += d * d; }
    var *= (1.f / 16.f);
    float inv = rsqrtf(var + 1e-5f);
#pragma unroll
    for (int i = 0; i < 16; i++) h[i] = (h[i] - m) * inv * g[i] + bb[i];
}

__global__ void __launch_bounds__(NT, 1) gnn_kernel(Args A) {
    extern __shared__ unsigned char smraw[];
    SM* s = reinterpret_cast<SM*>(smraw);
    const int b = blockIdx.x;
    const int tid = threadIdx.x;
    const int* ei = A.ei + b * 2 * EE;
    const float* eag = A.ea + (size_t)b * EE * 8;
    const float* wef = (const float*)s->Wev;
    float* aarr = s->expl;   // alias: a[n*18+c], valid after S3b
    float* hpos = g_hbuf + (size_t)b * EE * 16;
    float* epos = g_eabuf + (size_t)b * EE * 8;

    // ---- S0 ----
    cpf((float*)s->W1v, A.W1, 192, tid);  cpf(s->b1, A.b1, 16, tid);
    cpf((float*)s->W2v, A.W2, 256, tid);  cpf(s->b2, A.b2, 16, tid);
    cpf((float*)s->W3v, A.W3, 256, tid);  cpf(s->b3, A.b3, 16, tid);
    cpf(s->lng, A.lng, 16, tid); cpf(s->lnb, A.lnb, 16, tid);
    cpf(s->emb, A.emb, 20, tid);
    cpf((float*)s->Wev, A.g1We, 512, tid);
    cpf(s->g1bq, A.g1bq, 64, tid); cpf(s->g1bk, A.g1bk, 64, tid);
    cpf(s->g1bv, A.g1bv, 64, tid); cpf(s->g1bs, A.g1bs, 16, tid);
    for (int i = tid; i < 1024; i += NT) {
        const int u = i >> 4, j = i & 15;
        s->WqT[j * 66 + u] = A.g1Wq[i];
        s->WkT[j * 66 + u] = A.g1Wk[i];
        s->WvT[j * 66 + u] = A.g1Wv[i];
    }
    for (int i = tid; i < 256; i += NT) {
        const int o = i >> 4, j = i & 15;
        s->WsT[j * 16 + o] = A.g1Ws[i];
    }
    for (int i = tid; i < NN; i += NT) {
        s->etype[i] = (int)A.nodes[b * NN + i];
        s->deg[i] = 0;
        s->needed[i] = 0;
    }
    for (int i = tid; i < 4; i += NT) s->denom2[i] = 0.f;
    for (int i = tid; i < 128; i += NT) s->acc2[i] = 0.f;
    if (tid == 0) { s->agent = A.agent[b]; s->scount = 0; }
    __syncthreads();

    const int ag = s->agent;

    // ---- S0b: degree histogram + needed marking (after zeroing barrier) ----
    if (tid == 0) s->needed[ag] = 1;
    for (int e = tid; e < EE; e += NT) {
        const int dst = ei[EE + e];
        atomicAdd(&s->deg[dst], 1);
        if (dst == ag) s->needed[ei[e]] = 1;
    }
    __syncthreads();

    // ---- S0c: warp-parallel prefix sum + slist ----
    if (tid < 32) {
        int d0[4]; int t = 0;
#pragma unroll
        for (int u = 0; u < 4; u++) {
            const int n = tid * 4 + u;
            d0[u] = (n < NN) ? s->deg[n] : 0;
            t += d0[u];
        }
        int incl = t;
#pragma unroll
        for (int o = 1; o < 32; o <<= 1) {
            const int vv = __shfl_up_sync(0xFFFFFFFFu, incl, o);
            if (tid >= o) incl += vv;
        }
        int run = incl - t;
#pragma unroll
        for (int u = 0; u < 4; u++) {
            const int n = tid * 4 + u;
            if (n < NN) { s->rowptr[n] = run; run += d0[u]; }
        }
        if (tid == 31) s->rowptr[NN] = incl;
    }
    for (int n = tid; n < NN; n += NT)
        if (s->needed[n]) { const int si = atomicAdd(&s->scount, 1); s->slist[si] = n; }
    __syncthreads();
    for (int n = tid; n < NN; n += NT) s->cursor[n] = s->rowptr[n];
    __syncthreads();

    // ---- S1a: CSR scatter + per-edge MLP; h and ea stored BY POSITION ----
    for (int e = tid; e < EE; e += NT) {
        const int src = ei[e], dst = ei[EE + e];
        const int pos = atomicAdd(&s->cursor[dst], 1);
        s->csr[pos] = (dst << 19) | (src << 12) | e;

        const int t = s->etype[src];
        const float4 xA = *(const float4*)&s->emb[t * 4];
        const float4 xB = *(const float4*)(eag + (size_t)e * 8);
        const float4 xC = *(const float4*)(eag + (size_t)e * 8 + 4);

        float4* ep = (float4*)&epos[(size_t)pos * 8];
        ep[0] = xB; ep[1] = xC;

        u64 xp[6];
        xp[0] = pk2(xA.x, xA.y); xp[1] = pk2(xA.z, xA.w);
        xp[2] = pk2(xB.x, xB.y); xp[3] = pk2(xB.z, xB.w);
        xp[4] = pk2(xC.x, xC.y); xp[5] = pk2(xC.z, xC.w);

        float h[16], h2[16];
#pragma unroll
        for (int o = 0; o < 16; o++) {
            const ulonglong2* wr = reinterpret_cast<const ulonglong2*>(&s->W1v[o * 3]);
            const ulonglong2 wa = wr[0], wb = wr[1], wc = wr[2];
            u64 acc = pk2(s->b1[o], 0.f);
            acc = fma2(wa.x, xp[0], acc); acc = fma2(wa.y, xp[1], acc);
            acc = fma2(wb.x, xp[2], acc); acc = fma2(wb.y, xp[3], acc);
            acc = fma2(wc.x, xp[4], acc); acc = fma2(wc.y, xp[5], acc);
            h[o] = fmaxf(hadd2(acc), 0.f);
        }
        ln16(h, s->lng, s->lnb);
        u64 hp2[8];
#pragma unroll
        for (int i = 0; i < 8; i++) hp2[i] = pk2(h[i * 2], h[i * 2 + 1]);
#pragma unroll
        for (int o = 0; o < 16; o++) {
            const ulonglong2* wr = reinterpret_cast<const ulonglong2*>(&s->W2v[o * 4]);
            const ulonglong2 w0 = wr[0], w1 = wr[1], w2 = wr[2], w3 = wr[3];
            u64 acc = pk2(s->b2[o], 0.f);
            acc = fma2(w0.x, hp2[0], acc); acc = fma2(w0.y, hp2[1], acc);
            acc = fma2(w1.x, hp2[2], acc); acc = fma2(w1.y, hp2[3], acc);
            acc = fma2(w2.x, hp2[4], acc); acc = fma2(w2.y, hp2[5], acc);
            acc = fma2(w3.x, hp2[6], acc); acc = fma2(w3.y, hp2[7], acc);
            h2[o] = fmaxf(hadd2(acc), 0.f);
        }
        ln16(h2, s->lng, s->lnb);
#pragma unroll
        for (int i = 0; i < 8; i++) hp2[i] = pk2(h2[i * 2], h2[i * 2 + 1]);
#pragma unroll
        for (int o = 0; o < 16; o++) {
            const ulonglong2* wr = reinterpret_cast<const ulonglong2*>(&s->W3v[o * 4]);
            const ulonglong2 w0 = wr[0], w1 = wr[1], w2 = wr[2], w3 = wr[3];
            u64 acc = pk2(s->b3[o], 0.f);
            acc = fma2(w0.x, hp2[0], acc); acc = fma2(w0.y, hp2[1], acc);
            acc = fma2(w1.x, hp2[2], acc); acc = fma2(w1.y, hp2[3], acc);
            acc = fma2(w2.x, hp2[4], acc); acc = fma2(w2.y, hp2[5], acc);
            acc = fma2(w3.x, hp2[6], acc); acc = fma2(w3.y, hp2[7], acc);
            h[o] = fmaxf(hadd2(acc), 0.f);
        }
        ln16(h, s->lng, s->lnb);

        float4* hp = (float4*)&hpos[(size_t)pos * 16];
        hp[0] = make_float4(h[0], h[1], h[2], h[3]);
        hp[1] = make_float4(h[4], h[5], h[6], h[7]);
        hp[2] = make_float4(h[8], h[9], h[10], h[11]);
        hp[3] = make_float4(h[12], h[13], h[14], h[15]);
    }
    __syncthreads();

    // ---- S1b: z gather — sequential by position, parity split ----
    for (int idx = tid; idx < NN * 8; idx += NT) {
        const int par = idx & 1, g = (idx >> 1) & 3, n = idx >> 3;
        const int p1 = s->rowptr[n + 1];
        float4 acc = make_float4(0.f, 0.f, 0.f, 0.f);
        for (int p = s->rowptr[n] + par; p < p1; p += 2) {
            const float4 hv = *(const float4*)&hpos[(size_t)p * 16 + g * 4];
            acc.x += hv.x; acc.y += hv.y; acc.z += hv.z; acc.w += hv.w;
        }
        acc.x += __shfl_xor_sync(0xFFFFFFFFu, acc.x, 1);
        acc.y += __shfl_xor_sync(0xFFFFFFFFu, acc.y, 1);
        acc.z += __shfl_xor_sync(0xFFFFFFFFu, acc.z, 1);
        acc.w += __shfl_xor_sync(0xFFFFFFFFu, acc.w, 1);
        if (!par) *(float4*)&s->z[n * 16 + g * 4] = acc;
    }
    __syncthreads();

    // ---- S2: q,k,v (stride 66, packed pairs); root ----
    for (int idx = tid; idx < NN * 32; idx += NT) {
        const int n = idx >> 5, up = idx & 31;
        const int u = up * 2;
        const float* zr = &s->z[n * 16];
        u64 aq = *(const u64*)&s->g1bq[u];
        u64 ak = *(const u64*)&s->g1bk[u];
        u64 av = *(const u64*)&s->g1bv[u];
#pragma unroll
        for (int j = 0; j < 16; j++) {
            const u64 zj = pk2(zr[j], zr[j]);
            aq = fma2(*(const u64*)&s->WqT[j * 66 + u], zj, aq);
            ak = fma2(*(const u64*)&s->WkT[j * 66 + u], zj, ak);
            av = fma2(*(const u64*)&s->WvT[j * 66 + u], zj, av);
        }
        *(u64*)&s->q[n * 66 + u] = aq;
        *(u64*)&s->k[n * 66 + u] = ak;
        *(u64*)&s->v[n * 66 + u] = av;
    }
    for (int idx = tid; idx < NN * 16; idx += NT) {
        const int n = idx >> 4, o = idx & 15;
        float ac = s->g1bs[o];
#pragma unroll
        for (int j = 0; j < 16; j++) ac += s->WsT[j * 16 + o] * s->z[n * 16 + j];
        s->root1[idx] = ac;
    }
    __syncthreads();

    // ---- S2b: qWe[n,h,j] ----
    for (int idx = tid; idx < NN * 32; idx += NT) {
        const int n = idx >> 5, r = idx & 31;
        const int hh = r >> 3, j = r & 7;
        const float* qr = &s->q[n * 66 + hh * 16];
        float acc = 0.f;
#pragma unroll
        for (int c = 0; c < 16; c++) acc += qr[c] * wef[(hh * 16 + c) * 8 + j];
        s->qwe[idx] = acc;
    }
    __syncthreads();

    // ---- S3a: per-position logits (all edges) ----
    for (int p = tid; p < EE; p += NT) {
        const int pk = s->csr[p];
        const int dst = pk >> 19, src = (pk >> 12) & 0x7F;
        const float4 eA = *(const float4*)&epos[(size_t)p * 8];
        const float4 eB = *(const float4*)&epos[(size_t)p * 8 + 4];
        u64 eap[4];
        eap[0] = pk2(eA.x, eA.y); eap[1] = pk2(eA.z, eA.w);
        eap[2] = pk2(eB.x, eB.y); eap[3] = pk2(eB.z, eB.w);
        const u64* qd2 = (const u64*)&s->q[dst * 66];
        const u64* ks2 = (const u64*)&s->k[src * 66];
        const u64* qw2 = (const u64*)&s->qwe[dst * 32];
#pragma unroll
        for (int hh = 0; hh < 4; hh++) {
            u64 acc = 0ull;
#pragma unroll
            for (int t = 0; t < 8; t++)
                acc = fma2(qd2[hh * 8 + t], ks2[hh * 8 + t], acc);
            acc = fma2(qw2[hh * 4 + 0], eap[0], acc);
            acc = fma2(qw2[hh * 4 + 1], eap[1], acc);
            acc = fma2(qw2[hh * 4 + 2], eap[2], acc);
            acc = fma2(qw2[hh * 4 + 3], eap[3], acc);
            s->expl[p * 4 + hh] = fexp(hadd2(acc) * 0.25f);
        }
    }
    __syncthreads();

    const int sc = s->scount;

    // ---- S3b-1: wea + denominators — NEEDED NODES ONLY (padded for shfl) ----
    {
        const int bound = sc * 16;
        const int padded = (bound + 31) & ~31;
        for (int idx = tid; idx < padded; idx += NT) {
            const bool live = idx < bound;
            const int li = live ? idx : (bound - 1);
            const int par = idx & 1, half = (li >> 1) & 1, hh = (li >> 2) & 3;
            const int n = s->slist[li >> 4];
            const int p1 = s->rowptr[n + 1];
            float4 acc = make_float4(0.f, 0.f, 0.f, 0.f);
            float d = 0.f;
            if (live) {
                for (int p = s->rowptr[n] + par; p < p1; p += 2) {
                    const float ex = s->expl[p * 4 + hh];
                    const float4 ea4 = *(const float4*)&epos[(size_t)p * 8 + half * 4];
                    acc.x += ex * ea4.x; acc.y += ex * ea4.y; acc.z += ex * ea4.z; acc.w += ex * ea4.w;
                    d += ex;
                }
            }
            acc.x += __shfl_xor_sync(0xFFFFFFFFu, acc.x, 1);
            acc.y += __shfl_xor_sync(0xFFFFFFFFu, acc.y, 1);
            acc.z += __shfl_xor_sync(0xFFFFFFFFu, acc.z, 1);
            acc.w += __shfl_xor_sync(0xFFFFFFFFu, acc.w, 1);
            d += __shfl_xor_sync(0xFFFFFFFFu, d, 1);
            if (live && !par) {
                *(float4*)&s->qwe[n * 32 + hh * 8 + half * 4] = acc;
                if (half == 0) s->denom1[n * 4 + hh] = d;
            }
        }
    }
    __syncthreads();

    // ---- S3b-3: acc1 — NEEDED NODES ONLY (padded for shfl) ----
    {
        const int bound = sc * 32;
        const int padded = (bound + 31) & ~31;
        for (int idx = tid; idx < padded; idx += NT) {
            const bool live = idx < bound;
            const int li = live ? idx : (bound - 1);
            const int par = idx & 1, g = (li >> 1) & 15;
            const int n = s->slist[li >> 5];
            const int u0 = g * 4, hh = g >> 2;
            const int p1 = s->rowptr[n + 1];
            u64 acc01 = 0ull, acc23 = 0ull;
            if (live) {
                for (int p = s->rowptr[n] + par; p < p1; p += 2) {
                    const int pk = s->csr[p];
                    const int src = (pk >> 12) & 0x7F;
                    const float ex = s->expl[p * 4 + hh];
                    const u64 ex2 = pk2(ex, ex);
                    acc01 = fma2(*(const u64*)&s->v[src * 66 + u0], ex2, acc01);
                    acc23 = fma2(*(const u64*)&s->v[src * 66 + u0 + 2], ex2, acc23);
                }
            }
            float a0, a1, a2, a3;
            unpk2(acc01, a0, a1);
            unpk2(acc23, a2, a3);
            a0 += __shfl_xor_sync(0xFFFFFFFFu, a0, 1);
            a1 += __shfl_xor_sync(0xFFFFFFFFu, a1, 1);
            a2 += __shfl_xor_sync(0xFFFFFFFFu, a2, 1);
            a3 += __shfl_xor_sync(0xFFFFFFFFu, a3, 1);
            if (live && !par) {
                const float* we_n = &s->qwe[n * 32 + hh * 8];
                float add[4];
#pragma unroll
                for (int t = 0; t < 4; t++) {
                    const int u = u0 + t;
                    float w = 0.f;
#pragma unroll
                    for (int j = 0; j < 8; j++) w += wef[u * 8 + j] * we_n[j];
                    add[t] = w;
                }
                float4 outv = make_float4(a0 + add[0], a1 + add[1], a2 + add[2], a3 + add[3]);
                *(float4*)&s->acc1[n * 64 + u0] = outv;
            }
        }
    }
    __syncthreads();

    // ---- S4: a — NEEDED NODES ONLY (alias over expl, stride 18) ----
    for (int idx = tid; idx < sc * 16; idx += NT) {
        const int si = idx >> 4, c = idx & 15;
        const int n = s->slist[si];
        float sum = 0.f;
#pragma unroll
        for (int hh = 0; hh < 4; hh++)
            sum += s->acc1[n * 64 + hh * 16 + c] / (s->denom1[n * 4 + hh] + 1e-16f);
        aarr[n * 18 + c] = 0.25f * sum + s->root1[n * 16 + c];
    }
    __syncthreads();

    // ---- S5: g2 agent q and root ----
    {
        const float* ar = &aarr[ag * 18];
        for (int u = tid; u < 128; u += NT) {
            float ac = A.g2bq[u];
#pragma unroll
            for (int j = 0; j < 16; j++) ac += A.g2Wq[u * 16 + j] * ar[j];
            s->qa[u] = ac;
        }
        for (int c = tid; c < 32; c += NT) {
            float ac = A.g2bs[c];
#pragma unroll
            for (int j = 0; j < 16; j++) ac += A.g2Ws[c * 16 + j] * ar[j];
            s->roota[c] = ac;
        }
    }
    __syncthreads();

    // ---- S6: g2 edges with dst == agent (ea by position) ----
    {
        const int p0 = s->rowptr[ag];
        const int m = s->rowptr[ag + 1] - p0;
        for (int w = tid; w < m * 4; w += NT) {
            const int pe = w >> 2, hh = w & 3;
            const int pk = s->csr[p0 + pe];
            const int src = (pk >> 12) & 0x7F;
            const float* eap = &epos[(size_t)(p0 + pe) * 8];
            float ear[8];
#pragma unroll
            for (int j = 0; j < 8; j++) ear[j] = eap[j];
            const float* ar = &aarr[src * 18];
            float ev[32];
            float lg = 0.f;
#pragma unroll
            for (int c = 0; c < 32; c++) {
                const int u = hh * 32 + c;
                float evv = 0.f;
#pragma unroll
                for (int j = 0; j < 8; j++) evv += A.g2We[u * 8 + j] * ear[j];
                ev[c] = evv;
                float kk = A.g2bk[u];
#pragma unroll
                for (int j = 0; j < 16; j++) kk += A.g2Wk[u * 16 + j] * ar[j];
                lg += s->qa[u] * (kk + evv);
            }
            const float ex = fexp(lg * 0.17677669529663689f);
            atomicAdd(&s->denom2[hh], ex);
#pragma unroll
            for (int c = 0; c < 32; c++) {
                const int u = hh * 32 + c;
                float vv = A.g2bv[u];
#pragma unroll
                for (int j = 0; j < 16; j++) vv += A.g2Wv[u * 16 + j] * ar[j];
                atomicAdd(&s->acc2[u], ex * (vv + ev[c]));
            }
        }
    }
    __syncthreads();

    // ---- S7: output at agent node ----
    for (int c = tid; c < 32; c += NT) {
        float sum = 0.f;
#pragma unroll
        for (int hh = 0; hh < 4; hh++)
            sum += s->acc2[hh * 32 + c] / (s->denom2[hh] + 1e-16f);
        A.out[b * 32 + c] = fmaxf(0.25f * sum + s->roota[c], 0.f);
    }
}

extern "C" void kernel_launch(void* const* d_in, const int* in_sizes, int n_in,
                              void* d_out, int out_size) {
    Args A;
    A.nodes = (const float*)d_in[0];
    A.ei    = (const int*)  d_in[1];
    A.ea    = (const float*)d_in[2];
    A.agent = (const int*)  d_in[3];
    A.emb   = (const float*)d_in[4];
    A.W1 = (const float*)d_in[5];  A.b1 = (const float*)d_in[6];
    A.W2 = (const float*)d_in[7];  A.b2 = (const float*)d_in[8];
    A.W3 = (const float*)d_in[9];  A.b3 = (const float*)d_in[10];
    A.lng = (const float*)d_in[11]; A.lnb = (const float*)d_in[12];
    A.g1Wq = (const float*)d_in[13]; A.g1bq = (const float*)d_in[14];
    A.g1Wk = (const float*)d_in[15]; A.g1bk = (const float*)d_in[16];
    A.g1Wv = (const float*)d_in[17]; A.g1bv = (const float*)d_in[18];
    A.g1We = (const float*)d_in[19];
    A.g1Ws = (const float*)d_in[20]; A.g1bs = (const float*)d_in[21];
    A.g2Wq = (const float*)d_in[22]; A.g2bq = (const float*)d_in[23];
    A.g2Wk = (const float*)d_in[24]; A.g2bk = (const float*)d_in[25];
    A.g2Wv = (const float*)d_in[26]; A.g2bv = (const float*)d_in[27];
    A.g2We = (const float*)d_in[28];
    A.g2Ws = (const float*)d_in[29]; A.g2bs = (const float*)d_in[30];
    A.out = (float*)d_out;

    cudaFuncSetAttribute(gnn_kernel, cudaFuncAttributeMaxDynamicSharedMemorySize,
                         (int)sizeof(SM));
    gnn_kernel<<<BB, NT, sizeof(SM)>>>(A);
}

// round 15
// speedup vs baseline: 1.4965x; 1.1306x over previous
#include <cuda_runtime.h>

#define BB 128
#define NN 100
#define EE 3200
#define NT 768

typedef unsigned long long u64;

struct Args {
    const float* nodes;
    const int*   ei;
    const float* ea;
    const int*   agent;
    const float* emb;
    const float *W1,*b1,*W2,*b2,*W3,*b3,*lng,*lnb;
    const float *g1Wq,*g1bq,*g1Wk,*g1bk,*g1Wv,*g1bv,*g1We,*g1Ws,*g1bs;
    const float *g2Wq,*g2bq,*g2Wk,*g2bk,*g2Wv,*g2bv,*g2We,*g2Ws,*g2bs;
    float* out;
};

// block-private global scratch, indexed by CSR position p (sequential reads)
__device__ float g_hbuf [(size_t)BB * EE * 16];
__device__ float g_eabuf[(size_t)BB * EE * 8];

__device__ __forceinline__ u64 fma2(u64 a, u64 b, u64 c) {
    u64 d; asm("fma.rn.f32x2 %0,%1,%2,%3;" : "=l"(d) : "l"(a), "l"(b), "l"(c)); return d;
}
__device__ __forceinline__ u64 pk2(float lo, float hi) {
    u64 r; asm("mov.b64 %0,{%1,%2};" : "=l"(r) : "f"(lo), "f"(hi)); return r;
}
__device__ __forceinline__ float hadd2(u64 v) {
    float lo, hi; asm("mov.b64 {%0,%1},%2;" : "=f"(lo), "=f"(hi) : "l"(v)); return lo + hi;
}
__device__ __forceinline__ void unpk2(u64 v, float& lo, float& hi) {
    asm("mov.b64 {%0,%1},%2;" : "=f"(lo), "=f"(hi) : "l"(v));
}

__device__ __forceinline__ float fexp(float x) {
    float t = x * 1.4426950408889634f;
    float n = rintf(t);
    float f = t - n;
    float p = 1.3333558e-3f;
    p = p * f + 9.6181291e-3f;
    p = p * f + 5.5504109e-2f;
    p = p * f + 2.4022651e-1f;
    p = p * f + 6.9314718e-1f;
    p = p * f + 1.0f;
    int ni = (int)n;
    ni = max(-126, min(127, ni));
    return p * __int_as_float((ni + 127) << 23);
}

struct SM {
    float z[NN * 16];
    float q[NN * 66], k[NN * 66], v[NN * 66];
    float root1[NN * 16];
    float acc1[NN * 64];
    float denom1[NN * 4];
    float expl[EE * 4];        // by CSR position p; [alias] a[NN*18] after S3b
    float qwe[NN * 32];
    float4 W1v[48];  float b1[16];
    float4 W2v[64];  float b2[16];
    float4 W3v[64];  float b3[16];
    float lng[16], lnb[16], emb[20];
    float WqT[16 * 66], WkT[16 * 66], WvT[16 * 66];
    float g1bq[64], g1bk[64], g1bv[64];
    float4 Wev[128];
    float WsT[256];
    float g1bs[16];
    float qa[128], roota[32], denom2[4], acc2[128];
    int csr[EE];               // (dst<<19)|(src<<12)|e
    int rowptr[NN + 1];
    int cursor[NN], deg[NN], etype[NN];
    int needed[NN], slist[NN];
    int scount, agent;
};
static_assert(sizeof(SM) <= 232448, "smem over limit");

__device__ __forceinline__ void cpf(float* d, const float* s, int n, int tid) {
    for (int i = tid; i < n; i += NT) d[i] = s[i];
}

__device__ __forceinline__ void ln16(float* h, const float* g, const float* bb) {
    float m = 0.f;
#pragma unroll
    for (int i = 0; i < 16; i++) m += h[i];
    m *= (1.f / 16.f);
    float var = 0.f;
#pragma unroll
    for (int i = 0; i < 16; i++) { float d = h[i] - m; var += d * d; }
    var *= (1.f / 16.f);
    float inv = rsqrtf(var + 1e-5f);
#pragma unroll
    for (int i = 0; i < 16; i++) h[i] = (h[i] - m) * inv * g[i] + bb[i];
}

__global__ void __launch_bounds__(NT, 1) gnn_kernel(Args A) {
    extern __shared__ unsigned char smraw[];
    SM* s = reinterpret_cast<SM*>(smraw);
    const int b = blockIdx.x;
    const int tid = threadIdx.x;
    const int* ei = A.ei + b * 2 * EE;
    const float* eag = A.ea + (size_t)b * EE * 8;
    const float* wef = (const float*)s->Wev;
    float* aarr = s->expl;   // alias: a[n*18+c], valid after S3b
    float* hpos = g_hbuf + (size_t)b * EE * 16;
    float* epos = g_eabuf + (size_t)b * EE * 8;

    // ---- S0 ----
    cpf((float*)s->W1v, A.W1, 192, tid);  cpf(s->b1, A.b1, 16, tid);
    cpf((float*)s->W2v, A.W2, 256, tid);  cpf(s->b2, A.b2, 16, tid);
    cpf((float*)s->W3v, A.W3, 256, tid);  cpf(s->b3, A.b3, 16, tid);
    cpf(s->lng, A.lng, 16, tid); cpf(s->lnb, A.lnb, 16, tid);
    cpf(s->emb, A.emb, 20, tid);
    cpf((float*)s->Wev, A.g1We, 512, tid);
    cpf(s->g1bq, A.g1bq, 64, tid); cpf(s->g1bk, A.g1bk, 64, tid);
    cpf(s->g1bv, A.g1bv, 64, tid); cpf(s->g1bs, A.g1bs, 16, tid);
    for (int i = tid; i < 1024; i += NT) {
        const int u = i >> 4, j = i & 15;
        s->WqT[j * 66 + u] = A.g1Wq[i];
        s->WkT[j * 66 + u] = A.g1Wk[i];
        s->WvT[j * 66 + u] = A.g1Wv[i];
    }
    for (int i = tid; i < 256; i += NT) {
        const int o = i >> 4, j = i & 15;
        s->WsT[j * 16 + o] = A.g1Ws[i];
    }
    for (int i = tid; i < NN; i += NT) {
        s->etype[i] = (int)A.nodes[b * NN + i];
        s->deg[i] = 0;
        s->needed[i] = 0;
    }
    for (int i = tid; i < 4; i += NT) s->denom2[i] = 0.f;
    for (int i = tid; i < 128; i += NT) s->acc2[i] = 0.f;
    if (tid == 0) { s->agent = A.agent[b]; s->scount = 0; }
    __syncthreads();

    const int ag = s->agent;

    // ---- S0b: degree histogram + needed marking (after zeroing barrier) ----
    if (tid == 0) s->needed[ag] = 1;
    for (int e = tid; e < EE; e += NT) {
        const int dst = ei[EE + e];
        atomicAdd(&s->deg[dst], 1);
        if (dst == ag) s->needed[ei[e]] = 1;
    }
    __syncthreads();

    // ---- S0c: warp-parallel prefix sum + slist ----
    if (tid < 32) {
        int d0[4]; int t = 0;
#pragma unroll
        for (int u = 0; u < 4; u++) {
            const int n = tid * 4 + u;
            d0[u] = (n < NN) ? s->deg[n] : 0;
            t += d0[u];
        }
        int incl = t;
#pragma unroll
        for (int o = 1; o < 32; o <<= 1) {
            const int vv = __shfl_up_sync(0xFFFFFFFFu, incl, o);
            if (tid >= o) incl += vv;
        }
        int run = incl - t;
#pragma unroll
        for (int u = 0; u < 4; u++) {
            const int n = tid * 4 + u;
            if (n < NN) { s->rowptr[n] = run; run += d0[u]; }
        }
        if (tid == 31) s->rowptr[NN] = incl;
    }
    for (int n = tid; n < NN; n += NT)
        if (s->needed[n]) { const int si = atomicAdd(&s->scount, 1); s->slist[si] = n; }
    __syncthreads();
    for (int n = tid; n < NN; n += NT) s->cursor[n] = s->rowptr[n];
    __syncthreads();

    // ---- S1a: CSR scatter + per-edge MLP; h and ea stored BY POSITION ----
    for (int e = tid; e < EE; e += NT) {
        const int src = ei[e], dst = ei[EE + e];
        const int pos = atomicAdd(&s->cursor[dst], 1);
        s->csr[pos] = (dst << 19) | (src << 12) | e;

        const int t = s->etype[src];
        const float4 xA = *(const float4*)&s->emb[t * 4];
        const float4 xB = *(const float4*)(eag + (size_t)e * 8);
        const float4 xC = *(const float4*)(eag + (size_t)e * 8 + 4);

        float4* ep = (float4*)&epos[(size_t)pos * 8];
        ep[0] = xB; ep[1] = xC;

        u64 xp[6];
        xp[0] = pk2(xA.x, xA.y); xp[1] = pk2(xA.z, xA.w);
        xp[2] = pk2(xB.x, xB.y); xp[3] = pk2(xB.z, xB.w);
        xp[4] = pk2(xC.x, xC.y); xp[5] = pk2(xC.z, xC.w);

        float h[16], h2[16];
#pragma unroll
        for (int o = 0; o < 16; o++) {
            const ulonglong2* wr = reinterpret_cast<const ulonglong2*>(&s->W1v[o * 3]);
            const ulonglong2 wa = wr[0], wb = wr[1], wc = wr[2];
            u64 acc = pk2(s->b1[o], 0.f);
            acc = fma2(wa.x, xp[0], acc); acc = fma2(wa.y, xp[1], acc);
            acc = fma2(wb.x, xp[2], acc); acc = fma2(wb.y, xp[3], acc);
            acc = fma2(wc.x, xp[4], acc); acc = fma2(wc.y, xp[5], acc);
            h[o] = fmaxf(hadd2(acc), 0.f);
        }
        ln16(h, s->lng, s->lnb);
        u64 hp2[8];
#pragma unroll
        for (int i = 0; i < 8; i++) hp2[i] = pk2(h[i * 2], h[i * 2 + 1]);
#pragma unroll
        for (int o = 0; o < 16; o++) {
            const ulonglong2* wr = reinterpret_cast<const ulonglong2*>(&s->W2v[o * 4]);
            const ulonglong2 w0 = wr[0], w1 = wr[1], w2 = wr[2], w3 = wr[3];
            u64 acc = pk2(s->b2[o], 0.f);
            acc = fma2(w0.x, hp2[0], acc); acc = fma2(w0.y, hp2[1], acc);
            acc = fma2(w1.x, hp2[2], acc); acc = fma2(w1.y, hp2[3], acc);
            acc = fma2(w2.x, hp2[4], acc); acc = fma2(w2.y, hp2[5], acc);
            acc = fma2(w3.x, hp2[6], acc); acc = fma2(w3.y, hp2[7], acc);
            h2[o] = fmaxf(hadd2(acc), 0.f);
        }
        ln16(h2, s->lng, s->lnb);
#pragma unroll
        for (int i = 0; i < 8; i++) hp2[i] = pk2(h2[i * 2], h2[i * 2 + 1]);
#pragma unroll
        for (int o = 0; o < 16; o++) {
            const ulonglong2* wr = reinterpret_cast<const ulonglong2*>(&s->W3v[o * 4]);
            const ulonglong2 w0 = wr[0], w1 = wr[1], w2 = wr[2], w3 = wr[3];
            u64 acc = pk2(s->b3[o], 0.f);
            acc = fma2(w0.x, hp2[0], acc); acc = fma2(w0.y, hp2[1], acc);
            acc = fma2(w1.x, hp2[2], acc); acc = fma2(w1.y, hp2[3], acc);
            acc = fma2(w2.x, hp2[4], acc); acc = fma2(w2.y, hp2[5], acc);
            acc = fma2(w3.x, hp2[6], acc); acc = fma2(w3.y, hp2[7], acc);
            h[o] = fmaxf(hadd2(acc), 0.f);
        }
        ln16(h, s->lng, s->lnb);

        float4* hp = (float4*)&hpos[(size_t)pos * 16];
        hp[0] = make_float4(h[0], h[1], h[2], h[3]);
        hp[1] = make_float4(h[4], h[5], h[6], h[7]);
        hp[2] = make_float4(h[8], h[9], h[10], h[11]);
        hp[3] = make_float4(h[12], h[13], h[14], h[15]);
    }
    __syncthreads();

    // ---- S1b: z gather — sequential by position, parity split ----
    for (int idx = tid; idx < NN * 8; idx += NT) {
        const int par = idx & 1, g = (idx >> 1) & 3, n = idx >> 3;
        const int p1 = s->rowptr[n + 1];
        float4 acc = make_float4(0.f, 0.f, 0.f, 0.f);
        for (int p = s->rowptr[n] + par; p < p1; p += 2) {
            const float4 hv = *(const float4*)&hpos[(size_t)p * 16 + g * 4];
            acc.x += hv.x; acc.y += hv.y; acc.z += hv.z; acc.w += hv.w;
        }
        acc.x += __shfl_xor_sync(0xFFFFFFFFu, acc.x, 1);
        acc.y += __shfl_xor_sync(0xFFFFFFFFu, acc.y, 1);
        acc.z += __shfl_xor_sync(0xFFFFFFFFu, acc.z, 1);
        acc.w += __shfl_xor_sync(0xFFFFFFFFu, acc.w, 1);
        if (!par) *(float4*)&s->z[n * 16 + g * 4] = acc;
    }
    __syncthreads();

    const int sc = s->scount;

    // ---- S2: k,v for ALL nodes (stride 66, packed pairs) ----
    for (int idx = tid; idx < NN * 32; idx += NT) {
        const int n = idx >> 5, up = idx & 31;
        const int u = up * 2;
        const float* zr = &s->z[n * 16];
        u64 ak = *(const u64*)&s->g1bk[u];
        u64 av = *(const u64*)&s->g1bv[u];
#pragma unroll
        for (int j = 0; j < 16; j++) {
            const u64 zj = pk2(zr[j], zr[j]);
            ak = fma2(*(const u64*)&s->WkT[j * 66 + u], zj, ak);
            av = fma2(*(const u64*)&s->WvT[j * 66 + u], zj, av);
        }
        *(u64*)&s->k[n * 66 + u] = ak;
        *(u64*)&s->v[n * 66 + u] = av;
    }
    // ---- S2q: q for NEEDED nodes only ----
    for (int idx = tid; idx < sc * 32; idx += NT) {
        const int si = idx >> 5, up = idx & 31;
        const int n = s->slist[si];
        const int u = up * 2;
        const float* zr = &s->z[n * 16];
        u64 aq = *(const u64*)&s->g1bq[u];
#pragma unroll
        for (int j = 0; j < 16; j++) {
            const u64 zj = pk2(zr[j], zr[j]);
            aq = fma2(*(const u64*)&s->WqT[j * 66 + u], zj, aq);
        }
        *(u64*)&s->q[n * 66 + u] = aq;
    }
    // ---- root1 for NEEDED nodes only ----
    for (int idx = tid; idx < sc * 16; idx += NT) {
        const int si = idx >> 4, o = idx & 15;
        const int n = s->slist[si];
        float ac = s->g1bs[o];
#pragma unroll
        for (int j = 0; j < 16; j++) ac += s->WsT[j * 16 + o] * s->z[n * 16 + j];
        s->root1[n * 16 + o] = ac;
    }
    __syncthreads();

    // ---- S2b: qWe for NEEDED nodes only ----
    for (int idx = tid; idx < sc * 32; idx += NT) {
        const int si = idx >> 5, r = idx & 31;
        const int n = s->slist[si];
        const int hh = r >> 3, j = r & 7;
        const float* qr = &s->q[n * 66 + hh * 16];
        float acc = 0.f;
#pragma unroll
        for (int c = 0; c < 16; c++) acc += qr[c] * wef[(hh * 16 + c) * 8 + j];
        s->qwe[n * 32 + r] = acc;
    }
    __syncthreads();

    // ---- S3a: per-position logits — NEEDED dst only (warp-coherent skip) ----
    for (int p = tid; p < EE; p += NT) {
        const int pk = s->csr[p];
        const int dst = pk >> 19;
        if (!s->needed[dst]) continue;
        const int src = (pk >> 12) & 0x7F;
        const float4 eA = *(const float4*)&epos[(size_t)p * 8];
        const float4 eB = *(const float4*)&epos[(size_t)p * 8 + 4];
        u64 eap[4];
        eap[0] = pk2(eA.x, eA.y); eap[1] = pk2(eA.z, eA.w);
        eap[2] = pk2(eB.x, eB.y); eap[3] = pk2(eB.z, eB.w);
        const u64* qd2 = (const u64*)&s->q[dst * 66];
        const u64* ks2 = (const u64*)&s->k[src * 66];
        const u64* qw2 = (const u64*)&s->qwe[dst * 32];
#pragma unroll
        for (int hh = 0; hh < 4; hh++) {
            u64 acc = 0ull;
#pragma unroll
            for (int t = 0; t < 8; t++)
                acc = fma2(qd2[hh * 8 + t], ks2[hh * 8 + t], acc);
            acc = fma2(qw2[hh * 4 + 0], eap[0], acc);
            acc = fma2(qw2[hh * 4 + 1], eap[1], acc);
            acc = fma2(qw2[hh * 4 + 2], eap[2], acc);
            acc = fma2(qw2[hh * 4 + 3], eap[3], acc);
            s->expl[p * 4 + hh] = fexp(hadd2(acc) * 0.25f);
        }
    }
    __syncthreads();

    // ---- S3b-1: wea + denominators — NEEDED NODES ONLY (padded for shfl) ----
    {
        const int bound = sc * 16;
        const int padded = (bound + 31) & ~31;
        for (int idx = tid; idx < padded; idx += NT) {
            const bool live = idx < bound;
            const int li = live ? idx : (bound - 1);
            const int par = idx & 1, half = (li >> 1) & 1, hh = (li >> 2) & 3;
            const int n = s->slist[li >> 4];
            const int p1 = s->rowptr[n + 1];
            float4 acc = make_float4(0.f, 0.f, 0.f, 0.f);
            float d = 0.f;
            if (live) {
                for (int p = s->rowptr[n] + par; p < p1; p += 2) {
                    const float ex = s->expl[p * 4 + hh];
                    const float4 ea4 = *(const float4*)&epos[(size_t)p * 8 + half * 4];
                    acc.x += ex * ea4.x; acc.y += ex * ea4.y; acc.z += ex * ea4.z; acc.w += ex * ea4.w;
                    d += ex;
                }
            }
            acc.x += __shfl_xor_sync(0xFFFFFFFFu, acc.x, 1);
            acc.y += __shfl_xor_sync(0xFFFFFFFFu, acc.y, 1);
            acc.z += __shfl_xor_sync(0xFFFFFFFFu, acc.z, 1);
            acc.w += __shfl_xor_sync(0xFFFFFFFFu, acc.w, 1);
            d += __shfl_xor_sync(0xFFFFFFFFu, d, 1);
            if (live && !par) {
                *(float4*)&s->qwe[n * 32 + hh * 8 + half * 4] = acc;
                if (half == 0) s->denom1[n * 4 + hh] = d;
            }
        }
    }
    __syncthreads();

    // ---- S3b-3: acc1 — NEEDED NODES ONLY (padded for shfl) ----
    {
        const int bound = sc * 32;
        const int padded = (bound + 31) & ~31;
        for (int idx = tid; idx < padded; idx += NT) {
            const bool live = idx < bound;
            const int li = live ? idx : (bound - 1);
            const int par = idx & 1, g = (li >> 1) & 15;
            const int n = s->slist[li >> 5];
            const int u0 = g * 4, hh = g >> 2;
            const int p1 = s->rowptr[n + 1];
            u64 acc01 = 0ull, acc23 = 0ull;
            if (live) {
                for (int p = s->rowptr[n] + par; p < p1; p += 2) {
                    const int pk = s->csr[p];
                    const int src = (pk >> 12) & 0x7F;
                    const float ex = s->expl[p * 4 + hh];
                    const u64 ex2 = pk2(ex, ex);
                    acc01 = fma2(*(const u64*)&s->v[src * 66 + u0], ex2, acc01);
                    acc23 = fma2(*(const u64*)&s->v[src * 66 + u0 + 2], ex2, acc23);
                }
            }
            float a0, a1, a2, a3;
            unpk2(acc01, a0, a1);
            unpk2(acc23, a2, a3);
            a0 += __shfl_xor_sync(0xFFFFFFFFu, a0, 1);
            a1 += __shfl_xor_sync(0xFFFFFFFFu, a1, 1);
            a2 += __shfl_xor_sync(0xFFFFFFFFu, a2, 1);
            a3 += __shfl_xor_sync(0xFFFFFFFFu, a3, 1);
            if (live && !par) {
                const float* we_n = &s->qwe[n * 32 + hh * 8];
                float add[4];
#pragma unroll
                for (int t = 0; t < 4; t++) {
                    const int u = u0 + t;
                    float w = 0.f;
#pragma unroll
                    for (int j = 0; j < 8; j++) w += wef[u * 8 + j] * we_n[j];
                    add[t] = w;
                }
                float4 outv = make_float4(a0 + add[0], a1 + add[1], a2 + add[2], a3 + add[3]);
                *(float4*)&s->acc1[n * 64 + u0] = outv;
            }
        }
    }
    __syncthreads();

    // ---- S4: a — NEEDED NODES ONLY (alias over expl, stride 18) ----
    for (int idx = tid; idx < sc * 16; idx += NT) {
        const int si = idx >> 4, c = idx & 15;
        const int n = s->slist[si];
        float sum = 0.f;
#pragma unroll
        for (int hh = 0; hh < 4; hh++)
            sum += s->acc1[n * 64 + hh * 16 + c] / (s->denom1[n * 4 + hh] + 1e-16f);
        aarr[n * 18 + c] = 0.25f * sum + s->root1[n * 16 + c];
    }
    __syncthreads();

    // ---- S5: g2 agent q and root ----
    {
        const float* ar = &aarr[ag * 18];
        for (int u = tid; u < 128; u += NT) {
            float ac = A.g2bq[u];
#pragma unroll
            for (int j = 0; j < 16; j++) ac += A.g2Wq[u * 16 + j] * ar[j];
            s->qa[u] = ac;
        }
        for (int c = tid; c < 32; c += NT) {
            float ac = A.g2bs[c];
#pragma unroll
            for (int j = 0; j < 16; j++) ac += A.g2Ws[c * 16 + j] * ar[j];
            s->roota[c] = ac;
        }
    }
    __syncthreads();

    // ---- S6: g2 edges with dst == agent (ea by position) ----
    {
        const int p0 = s->rowptr[ag];
        const int m = s->rowptr[ag + 1] - p0;
        for (int w = tid; w < m * 4; w += NT) {
            const int pe = w >> 2, hh = w & 3;
            const int pk = s->csr[p0 + pe];
            const int src = (pk >> 12) & 0x7F;
            const float* eap = &epos[(size_t)(p0 + pe) * 8];
            float ear[8];
#pragma unroll
            for (int j = 0; j < 8; j++) ear[j] = eap[j];
            const float* ar = &aarr[src * 18];
            float ev[32];
            float lg = 0.f;
#pragma unroll
            for (int c = 0; c < 32; c++) {
                const int u = hh * 32 + c;
                float evv = 0.f;
#pragma unroll
                for (int j = 0; j < 8; j++) evv += A.g2We[u * 8 + j] * ear[j];
                ev[c] = evv;
                float kk = A.g2bk[u];
#pragma unroll
                for (int j = 0; j < 16; j++) kk += A.g2Wk[u * 16 + j] * ar[j];
                lg += s->qa[u] * (kk + evv);
            }
            const float ex = fexp(lg * 0.17677669529663689f);
            atomicAdd(&s->denom2[hh], ex);
#pragma unroll
            for (int c = 0; c < 32; c++) {
                const int u = hh * 32 + c;
                float vv = A.g2bv[u];
#pragma unroll
                for (int j = 0; j < 16; j++) vv += A.g2Wv[u * 16 + j] * ar[j];
                atomicAdd(&s->acc2[u], ex * (vv + ev[c]));
            }
        }
    }
    __syncthreads();

    // ---- S7: output at agent node ----
    for (int c = tid; c < 32; c += NT) {
        float sum = 0.f;
#pragma unroll
        for (int hh = 0; hh < 4; hh++)
            sum += s->acc2[hh * 32 + c] / (s->denom2[hh] + 1e-16f);
        A.out[b * 32 + c] = fmaxf(0.25f * sum + s->roota[c], 0.f);
    }
}

extern "C" void kernel_launch(void* const* d_in, const int* in_sizes, int n_in,
                              void* d_out, int out_size) {
    Args A;
    A.nodes = (const float*)d_in[0];
    A.ei    = (const int*)  d_in[1];
    A.ea    = (const float*)d_in[2];
    A.agent = (const int*)  d_in[3];
    A.emb   = (const float*)d_in[4];
    A.W1 = (const float*)d_in[5];  A.b1 = (const float*)d_in[6];
    A.W2 = (const float*)d_in[7];  A.b2 = (const float*)d_in[8];
    A.W3 = (const float*)d_in[9];  A.b3 = (const float*)d_in[10];
    A.lng = (const float*)d_in[11]; A.lnb = (const float*)d_in[12];
    A.g1Wq = (const float*)d_in[13]; A.g1bq = (const float*)d_in[14];
    A.g1Wk = (const float*)d_in[15]; A.g1bk = (const float*)d_in[16];
    A.g1Wv = (const float*)d_in[17]; A.g1bv = (const float*)d_in[18];
    A.g1We = (const float*)d_in[19];
    A.g1Ws = (const float*)d_in[20]; A.g1bs = (const float*)d_in[21];
    A.g2Wq = (const float*)d_in[22]; A.g2bq = (const float*)d_in[23];
    A.g2Wk = (const float*)d_in[24]; A.g2bk = (const float*)d_in[25];
    A.g2Wv = (const float*)d_in[26]; A.g2bv = (const float*)d_in[27];
    A.g2We = (const float*)d_in[28];
    A.g2Ws = (const float*)d_in[29]; A.g2bs = (const float*)d_in[30];
    A.out = (float*)d_out;

    cudaFuncSetAttribute(gnn_kernel, cudaFuncAttributeMaxDynamicSharedMemorySize,
                         (int)sizeof(SM));
    gnn_kernel<<<BB, NT, sizeof(SM)>>>(A);
}

// round 16
// speedup vs baseline: 1.5044x; 1.0053x over previous
#include <cuda_runtime.h>

#define BB 128
#define NN 100
#define EE 3200
#define NT 768

typedef unsigned long long u64;

struct Args {
    const float* nodes;
    const int*   ei;
    const float* ea;
    const int*   agent;
    const float* emb;
    const float *W1,*b1,*W2,*b2,*W3,*b3,*lng,*lnb;
    const float *g1Wq,*g1bq,*g1Wk,*g1bk,*g1Wv,*g1bv,*g1We,*g1Ws,*g1bs;
    const float *g2Wq,*g2bq,*g2Wk,*g2bk,*g2Wv,*g2bv,*g2We,*g2Ws,*g2bs;
    float* out;
};

// block-private global scratch, indexed by CSR position p (sequential reads)
__device__ float g_hbuf [(size_t)BB * EE * 16];
__device__ float g_eabuf[(size_t)BB * EE * 8];

__device__ __forceinline__ u64 fma2(u64 a, u64 b, u64 c) {
    u64 d; asm("fma.rn.f32x2 %0,%1,%2,%3;" : "=l"(d) : "l"(a), "l"(b), "l"(c)); return d;
}
__device__ __forceinline__ u64 pk2(float lo, float hi) {
    u64 r; asm("mov.b64 %0,{%1,%2};" : "=l"(r) : "f"(lo), "f"(hi)); return r;
}
__device__ __forceinline__ float hadd2(u64 v) {
    float lo, hi; asm("mov.b64 {%0,%1},%2;" : "=f"(lo), "=f"(hi) : "l"(v)); return lo + hi;
}
__device__ __forceinline__ void unpk2(u64 v, float& lo, float& hi) {
    asm("mov.b64 {%0,%1},%2;" : "=f"(lo), "=f"(hi) : "l"(v));
}

__device__ __forceinline__ float fexp(float x) {
    float t = x * 1.4426950408889634f;
    float n = rintf(t);
    float f = t - n;
    float p = 1.3333558e-3f;
    p = p * f + 9.6181291e-3f;
    p = p * f + 5.5504109e-2f;
    p = p * f + 2.4022651e-1f;
    p = p * f + 6.9314718e-1f;
    p = p * f + 1.0f;
    int ni = (int)n;
    ni = max(-126, min(127, ni));
    return p * __int_as_float((ni + 127) << 23);
}

struct SM {
    float z[NN * 16];
    float q[NN * 66], k[NN * 66], v[NN * 66];
    float root1[NN * 16];
    float abuf[NN * 18];       // g1 output a (stride 18)
    float expl[EE * 4];        // by CSR position p
    float qwe[NN * 32];        // qWe for logits (needed nodes)
    float wes[128 * 9];        // We padded stride 9 (conflict-free per-u reads)
    float Mf[512];             // M[h][j][j'] = sum_c We[hc,j]*Wq[hc,j']
    float qweb[32];            // bias term sum_c We[hc,j]*bq[hc]
    float4 W1v[48];  float b1[16];
    float4 W2v[64];  float b2[16];
    float4 W3v[64];  float b3[16];
    float lng[16], lnb[16], emb[20];
    float WqT[16 * 66], WkT[16 * 66], WvT[16 * 66];
    float g1bq[64], g1bk[64], g1bv[64];
    float4 Wev[128];
    float WsT[256];
    float g1bs[16];
    float qa[128], roota[32], denom2[4], acc2[128];
    int csr[EE];               // (dst<<19)|(src<<12)|e
    int rowptr[NN + 1];
    int cursor[NN], deg[NN], etype[NN];
    int needed[NN], slist[NN];
    int scount, agent;
};
static_assert(sizeof(SM) <= 232448, "smem over limit");

__device__ __forceinline__ void cpf(float* d, const float* s, int n, int tid) {
    for (int i = tid; i < n; i += NT) d[i] = s[i];
}

__device__ __forceinline__ void ln16(float* h, const float* g, const float* bb) {
    float m = 0.f;
#pragma unroll
    for (int i = 0; i < 16; i++) m += h[i];
    m *= (1.f / 16.f);
    float var = 0.f;
#pragma unroll
    for (int i = 0; i < 16; i++) { float d = h[i] - m; var += d * d; }
    var *= (1.f / 16.f);
    float inv = rsqrtf(var + 1e-5f);
#pragma unroll
    for (int i = 0; i < 16; i++) h[i] = (h[i] - m) * inv * g[i] + bb[i];
}

__global__ void __launch_bounds__(NT, 1) gnn_kernel(Args A) {
    extern __shared__ unsigned char smraw[];
    SM* s = reinterpret_cast<SM*>(smraw);
    const int b = blockIdx.x;
    const int tid = threadIdx.x;
    const int* ei = A.ei + b * 2 * EE;
    const float* eag = A.ea + (size_t)b * EE * 8;
    const float* wef = (const float*)s->Wev;
    float* hpos = g_hbuf + (size_t)b * EE * 16;
    float* epos = g_eabuf + (size_t)b * EE * 8;

    // ---- S0 ----
    cpf((float*)s->W1v, A.W1, 192, tid);  cpf(s->b1, A.b1, 16, tid);
    cpf((float*)s->W2v, A.W2, 256, tid);  cpf(s->b2, A.b2, 16, tid);
    cpf((float*)s->W3v, A.W3, 256, tid);  cpf(s->b3, A.b3, 16, tid);
    cpf(s->lng, A.lng, 16, tid); cpf(s->lnb, A.lnb, 16, tid);
    cpf(s->emb, A.emb, 20, tid);
    cpf((float*)s->Wev, A.g1We, 512, tid);
    cpf(s->g1bq, A.g1bq, 64, tid); cpf(s->g1bk, A.g1bk, 64, tid);
    cpf(s->g1bv, A.g1bv, 64, tid); cpf(s->g1bs, A.g1bs, 16, tid);
    for (int i = tid; i < 1024; i += NT) {
        const int u = i >> 4, j = i & 15;
        s->WqT[j * 66 + u] = A.g1Wq[i];
        s->WkT[j * 66 + u] = A.g1Wk[i];
        s->WvT[j * 66 + u] = A.g1Wv[i];
    }
    for (int i = tid; i < 1024; i += NT) {
        const int u = i >> 3, j = i & 7;
        s->wes[u * 9 + j] = A.g1We[i];
    }
    for (int i = tid; i < 256; i += NT) {
        const int o = i >> 4, j = i & 15;
        s->WsT[j * 16 + o] = A.g1Ws[i];
    }
    for (int i = tid; i < NN; i += NT) {
        s->etype[i] = (int)A.nodes[b * NN + i];
        s->deg[i] = 0;
        s->needed[i] = 0;
    }
    for (int i = tid; i < 4; i += NT) s->denom2[i] = 0.f;
    for (int i = tid; i < 128; i += NT) s->acc2[i] = 0.f;
    if (tid == 0) { s->agent = A.agent[b]; s->scount = 0; }
    __syncthreads();

    const int ag = s->agent;

    // ---- S0b: histogram + needed marking + M/qweb precompute ----
    if (tid == 0) s->needed[ag] = 1;
    for (int e = tid; e < EE; e += NT) {
        const int dst = ei[EE + e];
        atomicAdd(&s->deg[dst], 1);
        if (dst == ag) s->needed[ei[e]] = 1;
    }
    // M[h,j,j'] = sum_c We[(h16+c)8+j] * Wq[(h16+c),j']   (WqT[j'*66 + h16+c])
    for (int i = tid; i < 512; i += NT) {
        const int h = i >> 7, j = (i >> 4) & 7, jp = i & 15;
        float acc = 0.f;
#pragma unroll
        for (int c = 0; c < 16; c++)
            acc += wef[(h * 16 + c) * 8 + j] * s->WqT[jp * 66 + h * 16 + c];
        s->Mf[i] = acc;
    }
    for (int i = tid; i < 32; i += NT) {
        const int h = i >> 3, j = i & 7;
        float acc = 0.f;
#pragma unroll
        for (int c = 0; c < 16; c++)
            acc += wef[(h * 16 + c) * 8 + j] * s->g1bq[h * 16 + c];
        s->qweb[i] = acc;
    }
    __syncthreads();

    // ---- S0c: warp-parallel prefix sum + slist ----
    if (tid < 32) {
        int d0[4]; int t = 0;
#pragma unroll
        for (int u = 0; u < 4; u++) {
            const int n = tid * 4 + u;
            d0[u] = (n < NN) ? s->deg[n] : 0;
            t += d0[u];
        }
        int incl = t;
#pragma unroll
        for (int o = 1; o < 32; o <<= 1) {
            const int vv = __shfl_up_sync(0xFFFFFFFFu, incl, o);
            if (tid >= o) incl += vv;
        }
        int run = incl - t;
#pragma unroll
        for (int u = 0; u < 4; u++) {
            const int n = tid * 4 + u;
            if (n < NN) { s->rowptr[n] = run; run += d0[u]; }
        }
        if (tid == 31) s->rowptr[NN] = incl;
    }
    for (int n = tid; n < NN; n += NT)
        if (s->needed[n]) { const int si = atomicAdd(&s->scount, 1); s->slist[si] = n; }
    __syncthreads();
    for (int n = tid; n < NN; n += NT) s->cursor[n] = s->rowptr[n];
    __syncthreads();

    // ---- S1a: CSR scatter + per-edge MLP; h and ea stored BY POSITION ----
    for (int e = tid; e < EE; e += NT) {
        const int src = ei[e], dst = ei[EE + e];
        const int pos = atomicAdd(&s->cursor[dst], 1);
        s->csr[pos] = (dst << 19) | (src << 12) | e;

        const int t = s->etype[src];
        const float4 xA = *(const float4*)&s->emb[t * 4];
        const float4 xB = *(const float4*)(eag + (size_t)e * 8);
        const float4 xC = *(const float4*)(eag + (size_t)e * 8 + 4);

        float4* ep = (float4*)&epos[(size_t)pos * 8];
        ep[0] = xB; ep[1] = xC;

        u64 xp[6];
        xp[0] = pk2(xA.x, xA.y); xp[1] = pk2(xA.z, xA.w);
        xp[2] = pk2(xB.x, xB.y); xp[3] = pk2(xB.z, xB.w);
        xp[4] = pk2(xC.x, xC.y); xp[5] = pk2(xC.z, xC.w);

        float h[16], h2[16];
#pragma unroll
        for (int o = 0; o < 16; o++) {
            const ulonglong2* wr = reinterpret_cast<const ulonglong2*>(&s->W1v[o * 3]);
            const ulonglong2 wa = wr[0], wb = wr[1], wc = wr[2];
            u64 acc = pk2(s->b1[o], 0.f);
            acc = fma2(wa.x, xp[0], acc); acc = fma2(wa.y, xp[1], acc);
            acc = fma2(wb.x, xp[2], acc); acc = fma2(wb.y, xp[3], acc);
            acc = fma2(wc.x, xp[4], acc); acc = fma2(wc.y, xp[5], acc);
            h[o] = fmaxf(hadd2(acc), 0.f);
        }
        ln16(h, s->lng, s->lnb);
        u64 hp2[8];
#pragma unroll
        for (int i = 0; i < 8; i++) hp2[i] = pk2(h[i * 2], h[i * 2 + 1]);
#pragma unroll
        for (int o = 0; o < 16; o++) {
            const ulonglong2* wr = reinterpret_cast<const ulonglong2*>(&s->W2v[o * 4]);
            const ulonglong2 w0 = wr[0], w1 = wr[1], w2 = wr[2], w3 = wr[3];
            u64 acc = pk2(s->b2[o], 0.f);
            acc = fma2(w0.x, hp2[0], acc); acc = fma2(w0.y, hp2[1], acc);
            acc = fma2(w1.x, hp2[2], acc); acc = fma2(w1.y, hp2[3], acc);
            acc = fma2(w2.x, hp2[4], acc); acc = fma2(w2.y, hp2[5], acc);
            acc = fma2(w3.x, hp2[6], acc); acc = fma2(w3.y, hp2[7], acc);
            h2[o] = fmaxf(hadd2(acc), 0.f);
        }
        ln16(h2, s->lng, s->lnb);
#pragma unroll
        for (int i = 0; i < 8; i++) hp2[i] = pk2(h2[i * 2], h2[i * 2 + 1]);
#pragma unroll
        for (int o = 0; o < 16; o++) {
            const ulonglong2* wr = reinterpret_cast<const ulonglong2*>(&s->W3v[o * 4]);
            const ulonglong2 w0 = wr[0], w1 = wr[1], w2 = wr[2], w3 = wr[3];
            u64 acc = pk2(s->b3[o], 0.f);
            acc = fma2(w0.x, hp2[0], acc); acc = fma2(w0.y, hp2[1], acc);
            acc = fma2(w1.x, hp2[2], acc); acc = fma2(w1.y, hp2[3], acc);
            acc = fma2(w2.x, hp2[4], acc); acc = fma2(w2.y, hp2[5], acc);
            acc = fma2(w3.x, hp2[6], acc); acc = fma2(w3.y, hp2[7], acc);
            h[o] = fmaxf(hadd2(acc), 0.f);
        }
        ln16(h, s->lng, s->lnb);

        float4* hp = (float4*)&hpos[(size_t)pos * 16];
        hp[0] = make_float4(h[0], h[1], h[2], h[3]);
        hp[1] = make_float4(h[4], h[5], h[6], h[7]);
        hp[2] = make_float4(h[8], h[9], h[10], h[11]);
        hp[3] = make_float4(h[12], h[13], h[14], h[15]);
    }
    __syncthreads();

    // ---- S1b: z gather — sequential by position, parity split ----
    for (int idx = tid; idx < NN * 8; idx += NT) {
        const int par = idx & 1, g = (idx >> 1) & 3, n = idx >> 3;
        const int p1 = s->rowptr[n + 1];
        float4 acc = make_float4(0.f, 0.f, 0.f, 0.f);
        for (int p = s->rowptr[n] + par; p < p1; p += 2) {
            const float4 hv = *(const float4*)&hpos[(size_t)p * 16 + g * 4];
            acc.x += hv.x; acc.y += hv.y; acc.z += hv.z; acc.w += hv.w;
        }
        acc.x += __shfl_xor_sync(0xFFFFFFFFu, acc.x, 1);
        acc.y += __shfl_xor_sync(0xFFFFFFFFu, acc.y, 1);
        acc.z += __shfl_xor_sync(0xFFFFFFFFu, acc.z, 1);
        acc.w += __shfl_xor_sync(0xFFFFFFFFu, acc.w, 1);
        if (!par) *(float4*)&s->z[n * 16 + g * 4] = acc;
    }
    __syncthreads();

    const int sc = s->scount;

    // ---- S2 region: k,v all; q + root + qwe (via Mf) for needed nodes ----
    for (int idx = tid; idx < NN * 32; idx += NT) {
        const int n = idx >> 5, up = idx & 31;
        const int u = up * 2;
        const float* zr = &s->z[n * 16];
        u64 ak = *(const u64*)&s->g1bk[u];
        u64 av = *(const u64*)&s->g1bv[u];
#pragma unroll
        for (int j = 0; j < 16; j++) {
            const u64 zj = pk2(zr[j], zr[j]);
            ak = fma2(*(const u64*)&s->WkT[j * 66 + u], zj, ak);
            av = fma2(*(const u64*)&s->WvT[j * 66 + u], zj, av);
        }
        *(u64*)&s->k[n * 66 + u] = ak;
        *(u64*)&s->v[n * 66 + u] = av;
    }
    for (int idx = tid; idx < sc * 32; idx += NT) {
        const int si = idx >> 5, up = idx & 31;
        const int n = s->slist[si];
        const int u = up * 2;
        const float* zr = &s->z[n * 16];
        u64 aq = *(const u64*)&s->g1bq[u];
#pragma unroll
        for (int j = 0; j < 16; j++) {
            const u64 zj = pk2(zr[j], zr[j]);
            aq = fma2(*(const u64*)&s->WqT[j * 66 + u], zj, aq);
        }
        *(u64*)&s->q[n * 66 + u] = aq;
    }
    for (int idx = tid; idx < sc * 16; idx += NT) {
        const int si = idx >> 4, o = idx & 15;
        const int n = s->slist[si];
        float ac = s->g1bs[o];
#pragma unroll
        for (int j = 0; j < 16; j++) ac += s->WsT[j * 16 + o] * s->z[n * 16 + j];
        s->root1[n * 16 + o] = ac;
    }
    // qwe directly from z via fused M (no dependency on q)
    for (int idx = tid; idx < sc * 32; idx += NT) {
        const int si = idx >> 5, r = idx & 31;
        const int n = s->slist[si];
        const float* Mr = &s->Mf[r * 16];   // Mf[h*128 + j*16 + jp] with r = h*8+j
        const float* zr = &s->z[n * 16];
        float acc = s->qweb[r];
#pragma unroll
        for (int jp = 0; jp < 16; jp++) acc += Mr[jp] * zr[jp];
        s->qwe[n * 32 + r] = acc;
    }
    __syncthreads();

    // ---- S3a: per-position logits — NEEDED dst only (warp-coherent skip) ----
    for (int p = tid; p < EE; p += NT) {
        const int pk = s->csr[p];
        const int dst = pk >> 19;
        if (!s->needed[dst]) continue;
        const int src = (pk >> 12) & 0x7F;
        const float4 eA = *(const float4*)&epos[(size_t)p * 8];
        const float4 eB = *(const float4*)&epos[(size_t)p * 8 + 4];
        u64 eap[4];
        eap[0] = pk2(eA.x, eA.y); eap[1] = pk2(eA.z, eA.w);
        eap[2] = pk2(eB.x, eB.y); eap[3] = pk2(eB.z, eB.w);
        const u64* qd2 = (const u64*)&s->q[dst * 66];
        const u64* ks2 = (const u64*)&s->k[src * 66];
        const u64* qw2 = (const u64*)&s->qwe[dst * 32];
#pragma unroll
        for (int hh = 0; hh < 4; hh++) {
            u64 acc = 0ull;
#pragma unroll
            for (int t = 0; t < 8; t++)
                acc = fma2(qd2[hh * 8 + t], ks2[hh * 8 + t], acc);
            acc = fma2(qw2[hh * 4 + 0], eap[0], acc);
            acc = fma2(qw2[hh * 4 + 1], eap[1], acc);
            acc = fma2(qw2[hh * 4 + 2], eap[2], acc);
            acc = fma2(qw2[hh * 4 + 3], eap[3], acc);
            s->expl[p * 4 + hh] = fexp(hadd2(acc) * 0.25f);
        }
    }
    __syncthreads();

    // ---- S3f: fused wea/denom/message/finalize — warp per needed node ----
    {
        const int w = tid >> 5, l = tid & 31;
        const int hL = l >> 3, jL = l & 7;
        const int base = l & 24;
        for (int si = w; si < sc; si += NT / 32) {
            const int n = s->slist[si];
            const int p0 = s->rowptr[n], p1 = s->rowptr[n + 1];
            u64 accv = 0ull;
            float weaL = 0.f, dL = 0.f;
#pragma unroll 4
            for (int p = p0; p < p1; p++) {
                const int pk = s->csr[p];
                const int src = (pk >> 12) & 0x7F;
                const float ex = s->expl[p * 4 + hL];
                accv = fma2(*(const u64*)&s->v[src * 66 + 2 * l], pk2(ex, ex), accv);
                weaL += ex * epos[(size_t)p * 8 + jL];
                dL += ex;
            }
            float add0 = 0.f, add1 = 0.f;
#pragma unroll
            for (int j = 0; j < 8; j++) {
                const float wj = __shfl_sync(0xFFFFFFFFu, weaL, base | j);
                add0 += s->wes[(2 * l) * 9 + j] * wj;
                add1 += s->wes[(2 * l + 1) * 9 + j] * wj;
            }
            float a0, a1;
            unpk2(accv, a0, a1);
            const float inv = 1.f / (dL + 1e-16f);
            float r0 = (a0 + add0) * inv;
            float r1 = (a1 + add1) * inv;
            r0 += __shfl_xor_sync(0xFFFFFFFFu, r0, 8);
            r0 += __shfl_xor_sync(0xFFFFFFFFu, r0, 16);
            r1 += __shfl_xor_sync(0xFFFFFFFFu, r1, 8);
            r1 += __shfl_xor_sync(0xFFFFFFFFu, r1, 16);
            if (l < 8) {
                s->abuf[n * 18 + 2 * l]     = 0.25f * r0 + s->root1[n * 16 + 2 * l];
                s->abuf[n * 18 + 2 * l + 1] = 0.25f * r1 + s->root1[n * 16 + 2 * l + 1];
            }
        }
    }
    __syncthreads();

    // ---- S5: g2 agent q and root ----
    {
        const float* ar = &s->abuf[ag * 18];
        for (int u = tid; u < 128; u += NT) {
            float ac = A.g2bq[u];
#pragma unroll
            for (int j = 0; j < 16; j++) ac += A.g2Wq[u * 16 + j] * ar[j];
            s->qa[u] = ac;
        }
        for (int c = tid; c < 32; c += NT) {
            float ac = A.g2bs[c];
#pragma unroll
            for (int j = 0; j < 16; j++) ac += A.g2Ws[c * 16 + j] * ar[j];
            s->roota[c] = ac;
        }
    }
    __syncthreads();

    // ---- S6: g2 edges with dst == agent (ea by position) ----
    {
        const int p0 = s->rowptr[ag];
        const int m = s->rowptr[ag + 1] - p0;
        for (int w = tid; w < m * 4; w += NT) {
            const int pe = w >> 2, hh = w & 3;
            const int pk = s->csr[p0 + pe];
            const int src = (pk >> 12) & 0x7F;
            const float* eap = &epos[(size_t)(p0 + pe) * 8];
            float ear[8];
#pragma unroll
            for (int j = 0; j < 8; j++) ear[j] = eap[j];
            const float* ar = &s->abuf[src * 18];
            float ev[32];
            float lg = 0.f;
#pragma unroll
            for (int c = 0; c < 32; c++) {
                const int u = hh * 32 + c;
                float evv = 0.f;
#pragma unroll
                for (int j = 0; j < 8; j++) evv += A.g2We[u * 8 + j] * ear[j];
                ev[c] = evv;
                float kk = A.g2bk[u];
#pragma unroll
                for (int j = 0; j < 16; j++) kk += A.g2Wk[u * 16 + j] * ar[j];
                lg += s->qa[u] * (kk + evv);
            }
            const float ex = fexp(lg * 0.17677669529663689f);
            atomicAdd(&s->denom2[hh], ex);
#pragma unroll
            for (int c = 0; c < 32; c++) {
                const int u = hh * 32 + c;
                float vv = A.g2bv[u];
#pragma unroll
                for (int j = 0; j < 16; j++) vv += A.g2Wv[u * 16 + j] * ar[j];
                atomicAdd(&s->acc2[u], ex * (vv + ev[c]));
            }
        }
    }
    __syncthreads();

    // ---- S7: output at agent node ----
    for (int c = tid; c < 32; c += NT) {
        float sum = 0.f;
#pragma unroll
        for (int hh = 0; hh < 4; hh++)
            sum += s->acc2[hh * 32 + c] / (s->denom2[hh] + 1e-16f);
        A.out[b * 32 + c] = fmaxf(0.25f * sum + s->roota[c], 0.f);
    }
}

extern "C" void kernel_launch(void* const* d_in, const int* in_sizes, int n_in,
                              void* d_out, int out_size) {
    Args A;
    A.nodes = (const float*)d_in[0];
    A.ei    = (const int*)  d_in[1];
    A.ea    = (const float*)d_in[2];
    A.agent = (const int*)  d_in[3];
    A.emb   = (const float*)d_in[4];
    A.W1 = (const float*)d_in[5];  A.b1 = (const float*)d_in[6];
    A.W2 = (const float*)d_in[7];  A.b2 = (const float*)d_in[8];
    A.W3 = (const float*)d_in[9];  A.b3 = (const float*)d_in[10];
    A.lng = (const float*)d_in[11]; A.lnb = (const float*)d_in[12];
    A.g1Wq = (const float*)d_in[13]; A.g1bq = (const float*)d_in[14];
    A.g1Wk = (const float*)d_in[15]; A.g1bk = (const float*)d_in[16];
    A.g1Wv = (const float*)d_in[17]; A.g1bv = (const float*)d_in[18];
    A.g1We = (const float*)d_in[19];
    A.g1Ws = (const float*)d_in[20]; A.g1bs = (const float*)d_in[21];
    A.g2Wq = (const float*)d_in[22]; A.g2bq = (const float*)d_in[23];
    A.g2Wk = (const float*)d_in[24]; A.g2bk = (const float*)d_in[25];
    A.g2Wv = (const float*)d_in[26]; A.g2bv = (const float*)d_in[27];
    A.g2We = (const float*)d_in[28];
    A.g2Ws = (const float*)d_in[29]; A.g2bs = (const float*)d_in[30];
    A.out = (float*)d_out;

    cudaFuncSetAttribute(gnn_kernel, cudaFuncAttributeMaxDynamicSharedMemorySize,
                         (int)sizeof(SM));
    gnn_kernel<<<BB, NT, sizeof(SM)>>>(A);
}